// round 1
// baseline (speedup 1.0000x reference)
#include <cuda_runtime.h>
#include <math.h>

// Problem dims (fixed by the reference)
#define NB 4
#define NS 2048
#define ND 512
#define NH 8
#define NHD 64
#define NF 2048
#define NROW (NB * NS)   // 8192

// ---------------- scratch (device globals; no allocation allowed) -----------
__device__ float g_wqt[ND * ND];
__device__ float g_wkt[ND * ND];
__device__ float g_wvt[ND * ND];
__device__ float g_q[NROW * ND];
__device__ float g_k[NROW * ND];
__device__ float g_v[NROW * ND];
__device__ float g_attn[NROW * ND];
__device__ float g_res1[NROW * ND];
__device__ float g_x1[NROW * ND];
__device__ float g_h[NROW * NF];
__device__ float g_res2[NROW * ND];

// ---------------- weight packing: [H,D,HD] -> [D, H*HD] ---------------------
__global__ void pack_w_kernel(const float* __restrict__ Wq,
                              const float* __restrict__ Wk,
                              const float* __restrict__ Wv,
                              float* __restrict__ tq,
                              float* __restrict__ tk,
                              float* __restrict__ tv) {
    int idx = blockIdx.x * 256 + threadIdx.x;   // over 8*512*64 = 262144
    int e = idx & 63;
    int d = (idx >> 6) & 511;
    int h = idx >> 15;
    int dst = d * ND + h * NHD + e;
    tq[dst] = Wq[idx];
    tk[dst] = Wk[idx];
    tv[dst] = Wv[idx];
}

// ---------------- SGEMM: C[M,N] = A[M,K] * B[K,N] + bias (+epilogue) --------
#define EPI_BIAS 0
#define EPI_GELU 1
#define EPI_RES  2

__global__ __launch_bounds__(256)
void sgemm_kernel(const float* __restrict__ A, const float* __restrict__ B,
                  const float* __restrict__ bias, const float* __restrict__ resid,
                  float* __restrict__ C, int M, int N, int K, int epi) {
    __shared__ float As[8][128];   // transposed A tile: As[k][m]
    __shared__ float Bs[8][128];   // natural B tile:    Bs[k][n]

    int t = threadIdx.x;
    int brow = blockIdx.y * 128;
    int bcol = blockIdx.x * 128;

    int ar = t >> 1;            // 0..127
    int ac = (t & 1) * 4;       // 0 or 4
    int br = t >> 5;            // 0..7
    int bc = (t & 31) * 4;      // 0..124

    const float* Ap = A + (size_t)(brow + ar) * K + ac;
    const float* Bp = B + (size_t)br * N + bcol + bc;

    float acc[8][8];
#pragma unroll
    for (int i = 0; i < 8; i++)
#pragma unroll
        for (int j = 0; j < 8; j++) acc[i][j] = 0.f;

    int ty = t >> 4, tx = t & 15;

    for (int k0 = 0; k0 < K; k0 += 8) {
        float4 av = *(const float4*)(Ap + k0);
        float4 bv = *(const float4*)(Bp + (size_t)k0 * N);
        As[ac + 0][ar] = av.x;
        As[ac + 1][ar] = av.y;
        As[ac + 2][ar] = av.z;
        As[ac + 3][ar] = av.w;
        *(float4*)&Bs[br][bc] = bv;
        __syncthreads();
#pragma unroll
        for (int k = 0; k < 8; k++) {
            float af[8], bf[8];
            *(float4*)&af[0] = *(float4*)&As[k][ty * 8];
            *(float4*)&af[4] = *(float4*)&As[k][ty * 8 + 4];
            *(float4*)&bf[0] = *(float4*)&Bs[k][tx * 8];
            *(float4*)&bf[4] = *(float4*)&Bs[k][tx * 8 + 4];
#pragma unroll
            for (int i = 0; i < 8; i++)
#pragma unroll
                for (int j = 0; j < 8; j++) acc[i][j] += af[i] * bf[j];
        }
        __syncthreads();
    }

    int row0 = brow + ty * 8;
    int col0 = bcol + tx * 8;
    float bi[8];
#pragma unroll
    for (int j = 0; j < 8; j++) bi[j] = bias[col0 + j];

#pragma unroll
    for (int i = 0; i < 8; i++) {
        size_t off = (size_t)(row0 + i) * N + col0;
        float out[8];
#pragma unroll
        for (int j = 0; j < 8; j++) out[j] = acc[i][j] + bi[j];
        if (epi == EPI_GELU) {
#pragma unroll
            for (int j = 0; j < 8; j++) {
                float xv = out[j];
                out[j] = 0.5f * xv * (1.0f + erff(xv * 0.70710678118654752f));
            }
        } else if (epi == EPI_RES) {
            float4 r0 = *(const float4*)(resid + off);
            float4 r1 = *(const float4*)(resid + off + 4);
            out[0] += r0.x; out[1] += r0.y; out[2] += r0.z; out[3] += r0.w;
            out[4] += r1.x; out[5] += r1.y; out[6] += r1.z; out[7] += r1.w;
        }
        *(float4*)(C + off)     = make_float4(out[0], out[1], out[2], out[3]);
        *(float4*)(C + off + 4) = make_float4(out[4], out[5], out[6], out[7]);
    }
}

// ---------------- flash attention: per (b,h) pair, 64-query tiles -----------
// Q,K,V,O layout: [B, S, H*HD] (head -> column offset h*64), row stride 512.
__global__ __launch_bounds__(256)
void attn_kernel(const float* __restrict__ Q, const float* __restrict__ K,
                 const float* __restrict__ V, float* __restrict__ O) {
    __shared__ float qs[64 * 64];   // [r][e] natural
    __shared__ float kp[64 * 64];   // K^T [e][c], then P [r][c] (aliased)
    __shared__ float vs[64 * 64];   // [c][e] natural

    int t = threadIdx.x;
    int bh = blockIdx.y;
    int b = bh >> 3, h = bh & 7;
    size_t hb = (size_t)b * NS * ND + (size_t)h * NHD;
    const float* Qb = Q + hb + (size_t)blockIdx.x * 64 * ND;
    const float* Kb = K + hb;
    const float* Vb = V + hb;
    float* Ob = O + hb + (size_t)blockIdx.x * 64 * ND;

    int lr = t >> 2;           // 0..63
    int lc = (t & 3) << 4;     // 0,16,32,48

    // load Q tile (natural)
    {
        const float* qp = Qb + (size_t)lr * ND + lc;
#pragma unroll
        for (int i = 0; i < 4; i++)
            *(float4*)&qs[lr * 64 + lc + i * 4] = *(const float4*)(qp + i * 4);
    }

    int ty = t >> 4, tx = t & 15;
    float m[4], l[4], o[4][4];
#pragma unroll
    for (int i = 0; i < 4; i++) {
        m[i] = -1e30f;
        l[i] = 0.f;
#pragma unroll
        for (int j = 0; j < 4; j++) o[i][j] = 0.f;
    }

    for (int ct = 0; ct < NS / 64; ct++) {
        __syncthreads();   // prior-iter PV reads done; also orders first-iter qs
        // load K tile (transposed into kp) and V tile (natural)
        {
            const float* kpt = Kb + (size_t)(ct * 64 + lr) * ND + lc;
            float kv[16];
#pragma unroll
            for (int i = 0; i < 4; i++)
                *(float4*)&kv[i * 4] = *(const float4*)(kpt + i * 4);
            const float* vp = Vb + (size_t)(ct * 64 + lr) * ND + lc;
#pragma unroll
            for (int i = 0; i < 4; i++)
                *(float4*)&vs[lr * 64 + lc + i * 4] = *(const float4*)(vp + i * 4);
#pragma unroll
            for (int i = 0; i < 16; i++) kp[(lc + i) * 64 + lr] = kv[i];
        }
        __syncthreads();

        // scores: s[r][c] = sum_e q[r][e] * k[c][e]
        float s[4][4];
#pragma unroll
        for (int i = 0; i < 4; i++)
#pragma unroll
            for (int j = 0; j < 4; j++) s[i][j] = 0.f;
#pragma unroll 8
        for (int e = 0; e < 64; e++) {
            float a0 = qs[(4 * ty + 0) * 64 + e];
            float a1 = qs[(4 * ty + 1) * 64 + e];
            float a2 = qs[(4 * ty + 2) * 64 + e];
            float a3 = qs[(4 * ty + 3) * 64 + e];
            float4 bf = *(float4*)&kp[e * 64 + 4 * tx];
            s[0][0] += a0 * bf.x; s[0][1] += a0 * bf.y; s[0][2] += a0 * bf.z; s[0][3] += a0 * bf.w;
            s[1][0] += a1 * bf.x; s[1][1] += a1 * bf.y; s[1][2] += a1 * bf.z; s[1][3] += a1 * bf.w;
            s[2][0] += a2 * bf.x; s[2][1] += a2 * bf.y; s[2][2] += a2 * bf.z; s[2][3] += a2 * bf.w;
            s[3][0] += a3 * bf.x; s[3][1] += a3 * bf.y; s[3][2] += a3 * bf.z; s[3][3] += a3 * bf.w;
        }

        // online softmax update (per-row reductions across the 16 tx lanes)
        float p[4][4];
#pragma unroll
        for (int i = 0; i < 4; i++) {
            float rm = -1e30f;
#pragma unroll
            for (int j = 0; j < 4; j++) {
                s[i][j] *= 0.125f;   // 1/sqrt(64)
                rm = fmaxf(rm, s[i][j]);
            }
#pragma unroll
            for (int off = 8; off > 0; off >>= 1)
                rm = fmaxf(rm, __shfl_xor_sync(0xFFFFFFFFu, rm, off, 16));
            float mnew = fmaxf(m[i], rm);
            float corr = __expf(m[i] - mnew);
            float rs = 0.f;
#pragma unroll
            for (int j = 0; j < 4; j++) {
                p[i][j] = __expf(s[i][j] - mnew);
                rs += p[i][j];
            }
#pragma unroll
            for (int off = 8; off > 0; off >>= 1)
                rs += __shfl_xor_sync(0xFFFFFFFFu, rs, off, 16);
            l[i] = l[i] * corr + rs;
            m[i] = mnew;
#pragma unroll
            for (int j = 0; j < 4; j++) o[i][j] *= corr;
        }

        __syncthreads();   // everyone done reading kp (K^T)
        // store P naturally [r][c] into kp (float4 stores)
#pragma unroll
        for (int i = 0; i < 4; i++)
            *(float4*)&kp[(4 * ty + i) * 64 + 4 * tx] =
                make_float4(p[i][0], p[i][1], p[i][2], p[i][3]);
        __syncthreads();

        // PV: o[r][e] += sum_c P[r][c] * V[c][e]
#pragma unroll 8
        for (int c = 0; c < 64; c++) {
            float a0 = kp[(4 * ty + 0) * 64 + c];
            float a1 = kp[(4 * ty + 1) * 64 + c];
            float a2 = kp[(4 * ty + 2) * 64 + c];
            float a3 = kp[(4 * ty + 3) * 64 + c];
            float4 bv = *(float4*)&vs[c * 64 + 4 * tx];
            o[0][0] += a0 * bv.x; o[0][1] += a0 * bv.y; o[0][2] += a0 * bv.z; o[0][3] += a0 * bv.w;
            o[1][0] += a1 * bv.x; o[1][1] += a1 * bv.y; o[1][2] += a1 * bv.z; o[1][3] += a1 * bv.w;
            o[2][0] += a2 * bv.x; o[2][1] += a2 * bv.y; o[2][2] += a2 * bv.z; o[2][3] += a2 * bv.w;
            o[3][0] += a3 * bv.x; o[3][1] += a3 * bv.y; o[3][2] += a3 * bv.z; o[3][3] += a3 * bv.w;
        }
    }

    // normalize + write (concat layout falls out automatically)
#pragma unroll
    for (int i = 0; i < 4; i++) {
        float inv = 1.0f / l[i];
        *(float4*)(Ob + (size_t)(4 * ty + i) * ND + 4 * tx) =
            make_float4(o[i][0] * inv, o[i][1] * inv, o[i][2] * inv, o[i][3] * inv);
    }
}

// ---------------- layernorm over rows of 512 --------------------------------
__global__ __launch_bounds__(128)
void layernorm_kernel(const float* __restrict__ X, const float* __restrict__ g,
                      const float* __restrict__ beta, float* __restrict__ Y) {
    __shared__ float ssum[4], ssq[4];
    int row = blockIdx.x;
    int t = threadIdx.x;   // 128 threads * float4 = 512
    float4 v = ((const float4*)(X + (size_t)row * ND))[t];
    float s = v.x + v.y + v.z + v.w;
    float q = v.x * v.x + v.y * v.y + v.z * v.z + v.w * v.w;
#pragma unroll
    for (int off = 16; off > 0; off >>= 1) {
        s += __shfl_xor_sync(0xFFFFFFFFu, s, off);
        q += __shfl_xor_sync(0xFFFFFFFFu, q, off);
    }
    int w = t >> 5;
    if ((t & 31) == 0) { ssum[w] = s; ssq[w] = q; }
    __syncthreads();
    s = ssum[0] + ssum[1] + ssum[2] + ssum[3];
    q = ssq[0] + ssq[1] + ssq[2] + ssq[3];
    float mu = s * (1.0f / 512.0f);
    float var = q * (1.0f / 512.0f) - mu * mu;
    float rstd = rsqrtf(var + 1e-12f);
    float4 gv = ((const float4*)g)[t];
    float4 bv = ((const float4*)beta)[t];
    float4 y;
    y.x = (v.x - mu) * rstd * gv.x + bv.x;
    y.y = (v.y - mu) * rstd * gv.y + bv.y;
    y.z = (v.z - mu) * rstd * gv.z + bv.z;
    y.w = (v.w - mu) * rstd * gv.w + bv.w;
    ((float4*)(Y + (size_t)row * ND))[t] = y;
}

// ---------------- launch ----------------------------------------------------
extern "C" void kernel_launch(void* const* d_in, const int* in_sizes, int n_in,
                              void* d_out, int out_size) {
    const float* x    = (const float*)d_in[0];
    const float* Wq   = (const float*)d_in[1];
    const float* bq   = (const float*)d_in[2];
    const float* Wk   = (const float*)d_in[3];
    const float* bk   = (const float*)d_in[4];
    const float* Wv   = (const float*)d_in[5];
    const float* bv   = (const float*)d_in[6];
    const float* Wo   = (const float*)d_in[7];
    const float* bo   = (const float*)d_in[8];
    const float* W1   = (const float*)d_in[9];
    const float* b1   = (const float*)d_in[10];
    const float* W2   = (const float*)d_in[11];
    const float* b2   = (const float*)d_in[12];
    const float* ln1g = (const float*)d_in[13];
    const float* ln1b = (const float*)d_in[14];
    const float* ln2g = (const float*)d_in[15];
    const float* ln2b = (const float*)d_in[16];

    float *wqt, *wkt, *wvt, *qb, *kb, *vbuf, *attnb, *res1, *x1, *hb, *res2;
    cudaGetSymbolAddress((void**)&wqt,   g_wqt);
    cudaGetSymbolAddress((void**)&wkt,   g_wkt);
    cudaGetSymbolAddress((void**)&wvt,   g_wvt);
    cudaGetSymbolAddress((void**)&qb,    g_q);
    cudaGetSymbolAddress((void**)&kb,    g_k);
    cudaGetSymbolAddress((void**)&vbuf,  g_v);
    cudaGetSymbolAddress((void**)&attnb, g_attn);
    cudaGetSymbolAddress((void**)&res1,  g_res1);
    cudaGetSymbolAddress((void**)&x1,    g_x1);
    cudaGetSymbolAddress((void**)&hb,    g_h);
    cudaGetSymbolAddress((void**)&res2,  g_res2);

    // 1. pack per-head weights into [D, H*HD]
    pack_w_kernel<<<(NH * ND * NHD) / 256, 256>>>(Wq, Wk, Wv, wqt, wkt, wvt);

    dim3 g512(ND / 128, NROW / 128);   // (4, 64)
    dim3 gF(NF / 128, NROW / 128);     // (16, 64)

    // 2. QKV projections
    sgemm_kernel<<<g512, 256>>>(x, wqt, bq, nullptr, qb,   NROW, ND, ND, EPI_BIAS);
    sgemm_kernel<<<g512, 256>>>(x, wkt, bk, nullptr, kb,   NROW, ND, ND, EPI_BIAS);
    sgemm_kernel<<<g512, 256>>>(x, wvt, bv, nullptr, vbuf, NROW, ND, ND, EPI_BIAS);

    // 3. flash attention -> concat layout
    attn_kernel<<<dim3(NS / 64, NB * NH), 256>>>(qb, kb, vbuf, attnb);

    // 4. output projection + residual, then LN1
    sgemm_kernel<<<g512, 256>>>(attnb, Wo, bo, x, res1, NROW, ND, ND, EPI_RES);
    layernorm_kernel<<<NROW, 128>>>(res1, ln1g, ln1b, x1);

    // 5. FFN
    sgemm_kernel<<<gF, 256>>>(x1, W1, b1, nullptr, hb, NROW, NF, ND, EPI_GELU);
    sgemm_kernel<<<g512, 256>>>(hb, W2, b2, x1, res2, NROW, ND, NF, EPI_RES);

    // 6. LN2 -> output
    layernorm_kernel<<<NROW, 128>>>(res2, ln2g, ln2b, (float*)d_out);
}

// round 4
// speedup vs baseline: 1.6903x; 1.6903x over previous
#include <cuda_runtime.h>
#include <math.h>
#include <cstdint>

// Problem dims
#define NB 4
#define NS 2048
#define ND 512
#define NH 8
#define NHD 64
#define NF 2048
#define NROW (NB * NS)   // 8192
#define QLD 1536         // fused qkv row stride

// ---------------- scratch ----------------------------------------------------
__device__ float g_wqkvt[1536 * 512];   // [n][k] rounded
__device__ float g_bqkv[1536];
__device__ float g_wot[512 * 512];
__device__ float g_w1t[2048 * 512];
__device__ float g_w2t[512 * 2048];
__device__ float g_xr[NROW * ND];       // x rounded (GEMM A)
__device__ float g_qkv[NROW * 1536];    // rounded (epilogue)
__device__ float g_attn[NROW * ND];     // rounded
__device__ float g_res1[NROW * ND];
__device__ float g_x1[NROW * ND];
__device__ float g_x1r[NROW * ND];      // rounded
__device__ float g_h[NROW * NF];        // rounded
__device__ float g_res2[NROW * ND];

// ---------------- helpers ----------------------------------------------------
__device__ __forceinline__ float rtf32(float x) {
    uint32_t r;
    asm("cvt.rna.tf32.f32 %0, %1;" : "=r"(r) : "f"(x));
    return __uint_as_float(r);
}
__device__ __forceinline__ uint32_t smem_u32(const void* p) {
    uint32_t a;
    asm("{ .reg .u64 t; cvta.to.shared.u64 t, %1; cvt.u32.u64 %0, t; }" : "=r"(a) : "l"(p));
    return a;
}
__device__ __forceinline__ void cp_async16(uint32_t sa, const void* ga) {
    asm volatile("cp.async.cg.shared.global [%0], [%1], 16;" :: "r"(sa), "l"(ga) : "memory");
}
__device__ __forceinline__ void cp_commit() { asm volatile("cp.async.commit_group;" ::: "memory"); }
template <int N> __device__ __forceinline__ void cp_wait() {
    asm volatile("cp.async.wait_group %0;" :: "n"(N) : "memory");
}
// D += A*B  (m16n8k8 tf32)
__device__ __forceinline__ void mma8(float* c, const uint32_t* a, const uint32_t* b) {
    asm volatile("mma.sync.aligned.m16n8k8.row.col.f32.tf32.tf32.f32 "
                 "{%0,%1,%2,%3}, {%4,%5,%6,%7}, {%8,%9}, {%0,%1,%2,%3};"
                 : "+f"(c[0]), "+f"(c[1]), "+f"(c[2]), "+f"(c[3])
                 : "r"(a[0]), "r"(a[1]), "r"(a[2]), "r"(a[3]), "r"(b[0]), "r"(b[1]));
}
__device__ __forceinline__ uint32_t f2u(float x) { return __float_as_uint(x); }

// ---------------- prep kernels -----------------------------------------------
__global__ void pack_qkvw_kernel(const float* __restrict__ Wq, const float* __restrict__ Wk,
                                 const float* __restrict__ Wv, float* __restrict__ out) {
    int idx = blockIdx.x * 256 + threadIdx.x;     // 1536*512
    int k = idx & 511;
    int n = idx >> 9;
    int sel = n >> 9;
    int h = (n >> 6) & 7;
    int e = n & 63;
    const float* W = sel == 0 ? Wq : (sel == 1 ? Wk : Wv);
    out[idx] = rtf32(W[h * (512 * 64) + k * 64 + e]);
}
__global__ void pack_qkvb_kernel(const float* __restrict__ bq, const float* __restrict__ bk,
                                 const float* __restrict__ bv, float* __restrict__ out) {
    int n = blockIdx.x * 256 + threadIdx.x;
    if (n >= 1536) return;
    int sel = n >> 9, r = n & 511;
    const float* b = sel == 0 ? bq : (sel == 1 ? bk : bv);
    out[n] = b[r];
}
__global__ void transpose_round_kernel(const float* __restrict__ in, float* __restrict__ out, int K, int N) {
    int idx = blockIdx.x * 256 + threadIdx.x;
    int k = idx % K;
    int n = idx / K;
    out[idx] = rtf32(in[(size_t)k * N + n]);
}
__global__ void round4_kernel(const float* __restrict__ in, float* __restrict__ out) {
    int i = blockIdx.x * 256 + threadIdx.x;
    float4 v = ((const float4*)in)[i];
    v.x = rtf32(v.x); v.y = rtf32(v.y); v.z = rtf32(v.z); v.w = rtf32(v.w);
    ((float4*)out)[i] = v;
}

// ---------------- tf32 mma.sync GEMM (canonical 2-stage) ----------------------
// C[8192, N] = A[8192,K] * Bt[N,K]^T + bias (+epi). Tiles 128x128x32, 8 warps.
#define GSTR 36                        // smem row stride (floats)
#define GSTAGE (128 * GSTR)            // floats per tile (A or B) = 4608
#define GEMM_SMEM (2 * 2 * GSTAGE * 4) // 73728 B

#define EPI_BIAS   0
#define EPI_BIAS_R 1   // + tf32 round
#define EPI_RES    2   // + residual
#define EPI_GELU   3   // + gelu + round

__global__ __launch_bounds__(256, 1)
void gemm_tc(const float* __restrict__ A, const float* __restrict__ Bt,
             const float* __restrict__ bias, const float* __restrict__ resid,
             float* __restrict__ C, int N, int K, int epi) {
    extern __shared__ float sm[];
    int tid = threadIdx.x;
    int lane = tid & 31, w = tid >> 5;
    int wm = w & 3, wn = w >> 2;        // 4 m-warps x 2 n-warps
    int ar = lane >> 2, ac = lane & 3;
    int brow = blockIdx.y * 128, bcol = blockIdx.x * 128;

    int lrow = tid >> 1, lc = (tid & 1) * 16;
    const float* Ap = A + (size_t)(brow + lrow) * K + lc;
    const float* Bp = Bt + (size_t)(bcol + lrow) * K + lc;
    uint32_t sbase = smem_u32(sm);
    uint32_t dstoff = (uint32_t)(lrow * GSTR + lc) * 4;
    int KT = K / 32;

#define GFETCH(kt_) do { \
        uint32_t ab_ = sbase + ((kt_) & 1) * (2 * GSTAGE * 4); \
        uint32_t bb_ = ab_ + GSTAGE * 4; \
        const float* ap_ = Ap + (kt_) * 32; \
        const float* bp_ = Bp + (kt_) * 32; \
        cp_async16(ab_ + dstoff,      ap_); \
        cp_async16(ab_ + dstoff + 16, ap_ + 4); \
        cp_async16(ab_ + dstoff + 32, ap_ + 8); \
        cp_async16(ab_ + dstoff + 48, ap_ + 12); \
        cp_async16(bb_ + dstoff,      bp_); \
        cp_async16(bb_ + dstoff + 16, bp_ + 4); \
        cp_async16(bb_ + dstoff + 32, bp_ + 8); \
        cp_async16(bb_ + dstoff + 48, bp_ + 12); \
    } while (0)

    GFETCH(0); cp_commit();

    float cf[2][8][4];
#pragma unroll
    for (int mt = 0; mt < 2; mt++)
#pragma unroll
        for (int nt = 0; nt < 8; nt++)
#pragma unroll
            for (int u = 0; u < 4; u++) cf[mt][nt][u] = 0.f;

    for (int kt = 0; kt < KT; kt++) {
        if (kt + 1 < KT) {
            GFETCH(kt + 1);
            cp_commit();
            cp_wait<1>();     // tile kt (older group) complete
        } else {
            cp_wait<0>();
        }
        __syncthreads();

        const float* As = sm + (kt & 1) * 2 * GSTAGE;
        const float* Bs = As + GSTAGE;
#pragma unroll
        for (int ks = 0; ks < 4; ks++) {
            uint32_t af[2][4], bf[8][2];
            int kc = ks * 8 + ac;
#pragma unroll
            for (int mt = 0; mt < 2; mt++) {
                int r = wm * 32 + mt * 16 + ar;
                af[mt][0] = f2u(As[r * GSTR + kc]);
                af[mt][1] = f2u(As[(r + 8) * GSTR + kc]);
                af[mt][2] = f2u(As[r * GSTR + kc + 4]);
                af[mt][3] = f2u(As[(r + 8) * GSTR + kc + 4]);
            }
#pragma unroll
            for (int nt = 0; nt < 8; nt++) {
                int cc = wn * 64 + nt * 8 + ar;
                bf[nt][0] = f2u(Bs[cc * GSTR + kc]);
                bf[nt][1] = f2u(Bs[cc * GSTR + kc + 4]);
            }
#pragma unroll
            for (int mt = 0; mt < 2; mt++)
#pragma unroll
                for (int nt = 0; nt < 8; nt++)
                    mma8(cf[mt][nt], af[mt], bf[nt]);
        }
        __syncthreads();
    }

    // epilogue
#pragma unroll
    for (int nt = 0; nt < 8; nt++) {
        int col = bcol + wn * 64 + nt * 8 + 2 * ac;
        float b0 = bias[col], b1 = bias[col + 1];
#pragma unroll
        for (int mt = 0; mt < 2; mt++) {
            int r0 = brow + wm * 32 + mt * 16 + ar;
            float v00 = cf[mt][nt][0] + b0, v01 = cf[mt][nt][1] + b1;
            float v10 = cf[mt][nt][2] + b0, v11 = cf[mt][nt][3] + b1;
            size_t o0 = (size_t)r0 * N + col;
            size_t o1 = (size_t)(r0 + 8) * N + col;
            if (epi == EPI_RES) {
                float2 q0 = *(const float2*)(resid + o0);
                float2 q1 = *(const float2*)(resid + o1);
                v00 += q0.x; v01 += q0.y; v10 += q1.x; v11 += q1.y;
            } else if (epi == EPI_GELU) {
                v00 = rtf32(0.5f * v00 * (1.0f + erff(v00 * 0.70710678118654752f)));
                v01 = rtf32(0.5f * v01 * (1.0f + erff(v01 * 0.70710678118654752f)));
                v10 = rtf32(0.5f * v10 * (1.0f + erff(v10 * 0.70710678118654752f)));
                v11 = rtf32(0.5f * v11 * (1.0f + erff(v11 * 0.70710678118654752f)));
            } else if (epi == EPI_BIAS_R) {
                v00 = rtf32(v00); v01 = rtf32(v01); v10 = rtf32(v10); v11 = rtf32(v11);
            }
            *(float2*)(C + o0) = make_float2(v00, v01);
            *(float2*)(C + o1) = make_float2(v10, v11);
        }
    }
}

// ---------------- flash attention (scalar, known-good R1 version) ------------
// Reads fused qkv [row][1536]: Q at col h*64, K at 512+h*64, V at 1024+h*64.
__global__ __launch_bounds__(256)
void attn_kernel(const float* __restrict__ QKV, float* __restrict__ O) {
    __shared__ float qs[64 * 64];   // [r][e] natural
    __shared__ float kp[64 * 64];   // K^T [e][c], then P [r][c] (aliased)
    __shared__ float vs[64 * 64];   // [c][e] natural

    int t = threadIdx.x;
    int bh = blockIdx.y;
    int b = bh >> 3, h = bh & 7;
    size_t base = (size_t)b * NS * QLD + (size_t)h * NHD;
    const float* Qb = QKV + base + (size_t)blockIdx.x * 64 * QLD;
    const float* Kb = QKV + base + 512;
    const float* Vb = QKV + base + 1024;
    float* Ob = O + (size_t)b * NS * ND + (size_t)h * NHD + (size_t)blockIdx.x * 64 * ND;

    int lr = t >> 2;           // 0..63
    int lc = (t & 3) << 4;     // 0,16,32,48

    {
        const float* qp = Qb + (size_t)lr * QLD + lc;
#pragma unroll
        for (int i = 0; i < 4; i++)
            *(float4*)&qs[lr * 64 + lc + i * 4] = *(const float4*)(qp + i * 4);
    }

    int ty = t >> 4, tx = t & 15;
    float m[4], l[4], o[4][4];
#pragma unroll
    for (int i = 0; i < 4; i++) {
        m[i] = -1e30f; l[i] = 0.f;
#pragma unroll
        for (int j = 0; j < 4; j++) o[i][j] = 0.f;
    }

    for (int ct = 0; ct < NS / 64; ct++) {
        __syncthreads();
        {
            const float* kpt = Kb + (size_t)(ct * 64 + lr) * QLD + lc;
            float kv[16];
#pragma unroll
            for (int i = 0; i < 4; i++)
                *(float4*)&kv[i * 4] = *(const float4*)(kpt + i * 4);
            const float* vp = Vb + (size_t)(ct * 64 + lr) * QLD + lc;
#pragma unroll
            for (int i = 0; i < 4; i++)
                *(float4*)&vs[lr * 64 + lc + i * 4] = *(const float4*)(vp + i * 4);
#pragma unroll
            for (int i = 0; i < 16; i++) kp[(lc + i) * 64 + lr] = kv[i];
        }
        __syncthreads();

        float s[4][4];
#pragma unroll
        for (int i = 0; i < 4; i++)
#pragma unroll
            for (int j = 0; j < 4; j++) s[i][j] = 0.f;
#pragma unroll 8
        for (int e = 0; e < 64; e++) {
            float a0 = qs[(4 * ty + 0) * 64 + e];
            float a1 = qs[(4 * ty + 1) * 64 + e];
            float a2 = qs[(4 * ty + 2) * 64 + e];
            float a3 = qs[(4 * ty + 3) * 64 + e];
            float4 bf = *(float4*)&kp[e * 64 + 4 * tx];
            s[0][0] += a0 * bf.x; s[0][1] += a0 * bf.y; s[0][2] += a0 * bf.z; s[0][3] += a0 * bf.w;
            s[1][0] += a1 * bf.x; s[1][1] += a1 * bf.y; s[1][2] += a1 * bf.z; s[1][3] += a1 * bf.w;
            s[2][0] += a2 * bf.x; s[2][1] += a2 * bf.y; s[2][2] += a2 * bf.z; s[2][3] += a2 * bf.w;
            s[3][0] += a3 * bf.x; s[3][1] += a3 * bf.y; s[3][2] += a3 * bf.z; s[3][3] += a3 * bf.w;
        }

        float p[4][4];
#pragma unroll
        for (int i = 0; i < 4; i++) {
            float rm = -1e30f;
#pragma unroll
            for (int j = 0; j < 4; j++) {
                s[i][j] *= 0.125f;
                rm = fmaxf(rm, s[i][j]);
            }
#pragma unroll
            for (int off = 8; off > 0; off >>= 1)
                rm = fmaxf(rm, __shfl_xor_sync(0xFFFFFFFFu, rm, off, 16));
            float mnew = fmaxf(m[i], rm);
            float corr = __expf(m[i] - mnew);
            float rs = 0.f;
#pragma unroll
            for (int j = 0; j < 4; j++) {
                p[i][j] = __expf(s[i][j] - mnew);
                rs += p[i][j];
            }
#pragma unroll
            for (int off = 8; off > 0; off >>= 1)
                rs += __shfl_xor_sync(0xFFFFFFFFu, rs, off, 16);
            l[i] = l[i] * corr + rs;
            m[i] = mnew;
#pragma unroll
            for (int j = 0; j < 4; j++) o[i][j] *= corr;
        }

        __syncthreads();
#pragma unroll
        for (int i = 0; i < 4; i++)
            *(float4*)&kp[(4 * ty + i) * 64 + 4 * tx] =
                make_float4(p[i][0], p[i][1], p[i][2], p[i][3]);
        __syncthreads();

#pragma unroll 8
        for (int c = 0; c < 64; c++) {
            float a0 = kp[(4 * ty + 0) * 64 + c];
            float a1 = kp[(4 * ty + 1) * 64 + c];
            float a2 = kp[(4 * ty + 2) * 64 + c];
            float a3 = kp[(4 * ty + 3) * 64 + c];
            float4 bv = *(float4*)&vs[c * 64 + 4 * tx];
            o[0][0] += a0 * bv.x; o[0][1] += a0 * bv.y; o[0][2] += a0 * bv.z; o[0][3] += a0 * bv.w;
            o[1][0] += a1 * bv.x; o[1][1] += a1 * bv.y; o[1][2] += a1 * bv.z; o[1][3] += a1 * bv.w;
            o[2][0] += a2 * bv.x; o[2][1] += a2 * bv.y; o[2][2] += a2 * bv.z; o[2][3] += a2 * bv.w;
            o[3][0] += a3 * bv.x; o[3][1] += a3 * bv.y; o[3][2] += a3 * bv.z; o[3][3] += a3 * bv.w;
        }
    }

#pragma unroll
    for (int i = 0; i < 4; i++) {
        float inv = 1.0f / l[i];
        *(float4*)(Ob + (size_t)(4 * ty + i) * ND + 4 * tx) =
            make_float4(rtf32(o[i][0] * inv), rtf32(o[i][1] * inv),
                        rtf32(o[i][2] * inv), rtf32(o[i][3] * inv));
    }
}

// ---------------- layernorm --------------------------------------------------
__global__ __launch_bounds__(128)
void layernorm_kernel(const float* __restrict__ X, const float* __restrict__ g,
                      const float* __restrict__ beta, float* __restrict__ Y,
                      float* __restrict__ Yr) {
    __shared__ float ssum[4], ssq[4];
    int row = blockIdx.x;
    int t = threadIdx.x;
    float4 v = ((const float4*)(X + (size_t)row * ND))[t];
    float s = v.x + v.y + v.z + v.w;
    float q = v.x * v.x + v.y * v.y + v.z * v.z + v.w * v.w;
#pragma unroll
    for (int off = 16; off > 0; off >>= 1) {
        s += __shfl_xor_sync(0xFFFFFFFFu, s, off);
        q += __shfl_xor_sync(0xFFFFFFFFu, q, off);
    }
    int w = t >> 5;
    if ((t & 31) == 0) { ssum[w] = s; ssq[w] = q; }
    __syncthreads();
    s = ssum[0] + ssum[1] + ssum[2] + ssum[3];
    q = ssq[0] + ssq[1] + ssq[2] + ssq[3];
    float mu = s * (1.0f / 512.0f);
    float var = q * (1.0f / 512.0f) - mu * mu;
    float rstd = rsqrtf(var + 1e-12f);
    float4 gv = ((const float4*)g)[t];
    float4 bv = ((const float4*)beta)[t];
    float4 y;
    y.x = (v.x - mu) * rstd * gv.x + bv.x;
    y.y = (v.y - mu) * rstd * gv.y + bv.y;
    y.z = (v.z - mu) * rstd * gv.z + bv.z;
    y.w = (v.w - mu) * rstd * gv.w + bv.w;
    ((float4*)(Y + (size_t)row * ND))[t] = y;
    if (Yr) {
        float4 yr = make_float4(rtf32(y.x), rtf32(y.y), rtf32(y.z), rtf32(y.w));
        ((float4*)(Yr + (size_t)row * ND))[t] = yr;
    }
}

// ---------------- launch -----------------------------------------------------
extern "C" void kernel_launch(void* const* d_in, const int* in_sizes, int n_in,
                              void* d_out, int out_size) {
    const float* x    = (const float*)d_in[0];
    const float* Wq   = (const float*)d_in[1];
    const float* bq   = (const float*)d_in[2];
    const float* Wk   = (const float*)d_in[3];
    const float* bk   = (const float*)d_in[4];
    const float* Wv   = (const float*)d_in[5];
    const float* bv   = (const float*)d_in[6];
    const float* Wo   = (const float*)d_in[7];
    const float* bo   = (const float*)d_in[8];
    const float* W1   = (const float*)d_in[9];
    const float* b1   = (const float*)d_in[10];
    const float* W2   = (const float*)d_in[11];
    const float* b2   = (const float*)d_in[12];
    const float* ln1g = (const float*)d_in[13];
    const float* ln1b = (const float*)d_in[14];
    const float* ln2g = (const float*)d_in[15];
    const float* ln2b = (const float*)d_in[16];

    float *wqkvt, *bqkv, *wot, *w1t, *w2t, *xr, *qkv, *attnb, *res1, *x1, *x1r, *hb, *res2;
    cudaGetSymbolAddress((void**)&wqkvt, g_wqkvt);
    cudaGetSymbolAddress((void**)&bqkv,  g_bqkv);
    cudaGetSymbolAddress((void**)&wot,   g_wot);
    cudaGetSymbolAddress((void**)&w1t,   g_w1t);
    cudaGetSymbolAddress((void**)&w2t,   g_w2t);
    cudaGetSymbolAddress((void**)&xr,    g_xr);
    cudaGetSymbolAddress((void**)&qkv,   g_qkv);
    cudaGetSymbolAddress((void**)&attnb, g_attn);
    cudaGetSymbolAddress((void**)&res1,  g_res1);
    cudaGetSymbolAddress((void**)&x1,    g_x1);
    cudaGetSymbolAddress((void**)&x1r,   g_x1r);
    cudaGetSymbolAddress((void**)&hb,    g_h);
    cudaGetSymbolAddress((void**)&res2,  g_res2);

    cudaFuncSetAttribute(gemm_tc, cudaFuncAttributeMaxDynamicSharedMemorySize, GEMM_SMEM);

    // prep
    pack_qkvw_kernel<<<(1536 * 512) / 256, 256>>>(Wq, Wk, Wv, wqkvt);
    pack_qkvb_kernel<<<6, 256>>>(bq, bk, bv, bqkv);
    transpose_round_kernel<<<(512 * 512) / 256, 256>>>(Wo, wot, 512, 512);
    transpose_round_kernel<<<(2048 * 512) / 256, 256>>>(W1, w1t, 512, 2048);
    transpose_round_kernel<<<(512 * 2048) / 256, 256>>>(W2, w2t, 2048, 512);
    round4_kernel<<<(NROW * ND / 4) / 256, 256>>>(x, xr);

    // QKV fused projection
    gemm_tc<<<dim3(12, 64), 256, GEMM_SMEM>>>(xr, wqkvt, bqkv, nullptr, qkv, 1536, 512, EPI_BIAS_R);

    // flash attention (scalar, known-good)
    attn_kernel<<<dim3(NS / 64, NB * NH), 256>>>(qkv, attnb);

    // Wo + residual(x); LN1
    gemm_tc<<<dim3(4, 64), 256, GEMM_SMEM>>>(attnb, wot, bo, x, res1, 512, 512, EPI_RES);
    layernorm_kernel<<<NROW, 128>>>(res1, ln1g, ln1b, x1, x1r);

    // FFN
    gemm_tc<<<dim3(16, 64), 256, GEMM_SMEM>>>(x1r, w1t, b1, nullptr, hb, 2048, 512, EPI_GELU);
    gemm_tc<<<dim3(4, 64), 256, GEMM_SMEM>>>(hb, w2t, b2, x1, res2, 512, 2048, EPI_RES);

    // LN2 -> out
    layernorm_kernel<<<NROW, 128>>>(res2, ln2g, ln2b, (float*)d_out, nullptr);
}

// round 6
// speedup vs baseline: 2.6381x; 1.5608x over previous
#include <cuda_runtime.h>
#include <math.h>
#include <cstdint>

// Problem dims
#define NB 4
#define NS 2048
#define ND 512
#define NH 8
#define NHD 64
#define NF 2048
#define NROW (NB * NS)   // 8192
#define QLD 1536         // fused qkv row stride

// ---------------- scratch ----------------------------------------------------
__device__ float g_wqkvt[1536 * 512];   // [n][k] rounded
__device__ float g_bqkv[1536];
__device__ float g_wot[512 * 512];
__device__ float g_w1t[2048 * 512];
__device__ float g_w2t[512 * 2048];
__device__ float g_xr[NROW * ND];       // x rounded (GEMM A)
__device__ float g_qkv[NROW * 1536];    // rounded (epilogue)
__device__ float g_attn[NROW * ND];     // rounded
__device__ float g_res1[NROW * ND];
__device__ float g_x1[NROW * ND];
__device__ float g_x1r[NROW * ND];      // rounded
__device__ float g_h[NROW * NF];        // rounded
__device__ float g_res2[NROW * ND];

// ---------------- helpers ----------------------------------------------------
__device__ __forceinline__ float rtf32(float x) {
    uint32_t r;
    asm("cvt.rna.tf32.f32 %0, %1;" : "=r"(r) : "f"(x));
    return __uint_as_float(r);
}
__device__ __forceinline__ uint32_t smem_u32(const void* p) {
    uint32_t a;
    asm("{ .reg .u64 t; cvta.to.shared.u64 t, %1; cvt.u32.u64 %0, t; }" : "=r"(a) : "l"(p));
    return a;
}
__device__ __forceinline__ void cp_async16(uint32_t sa, const void* ga) {
    asm volatile("cp.async.cg.shared.global [%0], [%1], 16;" :: "r"(sa), "l"(ga) : "memory");
}
__device__ __forceinline__ void cp_commit() { asm volatile("cp.async.commit_group;" ::: "memory"); }
template <int N> __device__ __forceinline__ void cp_wait() {
    asm volatile("cp.async.wait_group %0;" :: "n"(N) : "memory");
}
// D += A*B  (m16n8k8 tf32)
__device__ __forceinline__ void mma8(float* c, const uint32_t* a, const uint32_t* b) {
    asm volatile("mma.sync.aligned.m16n8k8.row.col.f32.tf32.tf32.f32 "
                 "{%0,%1,%2,%3}, {%4,%5,%6,%7}, {%8,%9}, {%0,%1,%2,%3};"
                 : "+f"(c[0]), "+f"(c[1]), "+f"(c[2]), "+f"(c[3])
                 : "r"(a[0]), "r"(a[1]), "r"(a[2]), "r"(a[3]), "r"(b[0]), "r"(b[1]));
}
__device__ __forceinline__ uint32_t f2u(float x) { return __float_as_uint(x); }

// ---------------- prep kernels -----------------------------------------------
__global__ void pack_qkvw_kernel(const float* __restrict__ Wq, const float* __restrict__ Wk,
                                 const float* __restrict__ Wv, float* __restrict__ out) {
    int idx = blockIdx.x * 256 + threadIdx.x;     // 1536*512
    int k = idx & 511;
    int n = idx >> 9;
    int sel = n >> 9;
    int h = (n >> 6) & 7;
    int e = n & 63;
    const float* W = sel == 0 ? Wq : (sel == 1 ? Wk : Wv);
    out[idx] = rtf32(W[h * (512 * 64) + k * 64 + e]);
}
__global__ void pack_qkvb_kernel(const float* __restrict__ bq, const float* __restrict__ bk,
                                 const float* __restrict__ bv, float* __restrict__ out) {
    int n = blockIdx.x * 256 + threadIdx.x;
    if (n >= 1536) return;
    int sel = n >> 9, r = n & 511;
    const float* b = sel == 0 ? bq : (sel == 1 ? bk : bv);
    out[n] = b[r];
}
__global__ void transpose_round_kernel(const float* __restrict__ in, float* __restrict__ out, int K, int N) {
    int idx = blockIdx.x * 256 + threadIdx.x;
    int k = idx % K;
    int n = idx / K;
    out[idx] = rtf32(in[(size_t)k * N + n]);
}
__global__ void round4_kernel(const float* __restrict__ in, float* __restrict__ out) {
    int i = blockIdx.x * 256 + threadIdx.x;
    float4 v = ((const float4*)in)[i];
    v.x = rtf32(v.x); v.y = rtf32(v.y); v.z = rtf32(v.z); v.w = rtf32(v.w);
    ((float4*)out)[i] = v;
}

// ---------------- tf32 mma.sync GEMM (canonical 2-stage) ----------------------
// C[8192, N] = A[8192,K] * Bt[N,K]^T + bias (+epi). Tiles 128x128x32, 8 warps.
#define GSTR 36                        // smem row stride (floats)
#define GSTAGE (128 * GSTR)            // floats per tile (A or B) = 4608
#define GEMM_SMEM (2 * 2 * GSTAGE * 4) // 73728 B

#define EPI_BIAS   0
#define EPI_BIAS_R 1   // + tf32 round
#define EPI_RES    2   // + residual
#define EPI_GELU   3   // + gelu + round

__global__ __launch_bounds__(256, 1)
void gemm_tc(const float* __restrict__ A, const float* __restrict__ Bt,
             const float* __restrict__ bias, const float* __restrict__ resid,
             float* __restrict__ C, int N, int K, int epi) {
    extern __shared__ float sm[];
    int tid = threadIdx.x;
    int lane = tid & 31, w = tid >> 5;
    int wm = w & 3, wn = w >> 2;        // 4 m-warps x 2 n-warps
    int ar = lane >> 2, ac = lane & 3;
    int brow = blockIdx.y * 128, bcol = blockIdx.x * 128;

    int lrow = tid >> 1, lc = (tid & 1) * 16;
    const float* Ap = A + (size_t)(brow + lrow) * K + lc;
    const float* Bp = Bt + (size_t)(bcol + lrow) * K + lc;
    uint32_t sbase = smem_u32(sm);
    uint32_t dstoff = (uint32_t)(lrow * GSTR + lc) * 4;
    int KT = K / 32;

#define GFETCH(kt_) do { \
        uint32_t ab_ = sbase + ((kt_) & 1) * (2 * GSTAGE * 4); \
        uint32_t bb_ = ab_ + GSTAGE * 4; \
        const float* ap_ = Ap + (kt_) * 32; \
        const float* bp_ = Bp + (kt_) * 32; \
        cp_async16(ab_ + dstoff,      ap_); \
        cp_async16(ab_ + dstoff + 16, ap_ + 4); \
        cp_async16(ab_ + dstoff + 32, ap_ + 8); \
        cp_async16(ab_ + dstoff + 48, ap_ + 12); \
        cp_async16(bb_ + dstoff,      bp_); \
        cp_async16(bb_ + dstoff + 16, bp_ + 4); \
        cp_async16(bb_ + dstoff + 32, bp_ + 8); \
        cp_async16(bb_ + dstoff + 48, bp_ + 12); \
    } while (0)

    GFETCH(0); cp_commit();

    float cf[2][8][4];
#pragma unroll
    for (int mt = 0; mt < 2; mt++)
#pragma unroll
        for (int nt = 0; nt < 8; nt++)
#pragma unroll
            for (int u = 0; u < 4; u++) cf[mt][nt][u] = 0.f;

    for (int kt = 0; kt < KT; kt++) {
        if (kt + 1 < KT) {
            GFETCH(kt + 1);
            cp_commit();
            cp_wait<1>();     // tile kt (older group) complete
        } else {
            cp_wait<0>();
        }
        __syncthreads();

        const float* As = sm + (kt & 1) * 2 * GSTAGE;
        const float* Bs = As + GSTAGE;
#pragma unroll
        for (int ks = 0; ks < 4; ks++) {
            uint32_t af[2][4], bf[8][2];
            int kc = ks * 8 + ac;
#pragma unroll
            for (int mt = 0; mt < 2; mt++) {
                int r = wm * 32 + mt * 16 + ar;
                af[mt][0] = f2u(As[r * GSTR + kc]);
                af[mt][1] = f2u(As[(r + 8) * GSTR + kc]);
                af[mt][2] = f2u(As[r * GSTR + kc + 4]);
                af[mt][3] = f2u(As[(r + 8) * GSTR + kc + 4]);
            }
#pragma unroll
            for (int nt = 0; nt < 8; nt++) {
                int cc = wn * 64 + nt * 8 + ar;
                bf[nt][0] = f2u(Bs[cc * GSTR + kc]);
                bf[nt][1] = f2u(Bs[cc * GSTR + kc + 4]);
            }
#pragma unroll
            for (int mt = 0; mt < 2; mt++)
#pragma unroll
                for (int nt = 0; nt < 8; nt++)
                    mma8(cf[mt][nt], af[mt], bf[nt]);
        }
        __syncthreads();
    }

    // epilogue
#pragma unroll
    for (int nt = 0; nt < 8; nt++) {
        int col = bcol + wn * 64 + nt * 8 + 2 * ac;
        float b0 = bias[col], b1 = bias[col + 1];
#pragma unroll
        for (int mt = 0; mt < 2; mt++) {
            int r0 = brow + wm * 32 + mt * 16 + ar;
            float v00 = cf[mt][nt][0] + b0, v01 = cf[mt][nt][1] + b1;
            float v10 = cf[mt][nt][2] + b0, v11 = cf[mt][nt][3] + b1;
            size_t o0 = (size_t)r0 * N + col;
            size_t o1 = (size_t)(r0 + 8) * N + col;
            if (epi == EPI_RES) {
                float2 q0 = *(const float2*)(resid + o0);
                float2 q1 = *(const float2*)(resid + o1);
                v00 += q0.x; v01 += q0.y; v10 += q1.x; v11 += q1.y;
            } else if (epi == EPI_GELU) {
                v00 = rtf32(0.5f * v00 * (1.0f + erff(v00 * 0.70710678118654752f)));
                v01 = rtf32(0.5f * v01 * (1.0f + erff(v01 * 0.70710678118654752f)));
                v10 = rtf32(0.5f * v10 * (1.0f + erff(v10 * 0.70710678118654752f)));
                v11 = rtf32(0.5f * v11 * (1.0f + erff(v11 * 0.70710678118654752f)));
            } else if (epi == EPI_BIAS_R) {
                v00 = rtf32(v00); v01 = rtf32(v01); v10 = rtf32(v10); v11 = rtf32(v11);
            }
            *(float2*)(C + o0) = make_float2(v00, v01);
            *(float2*)(C + o1) = make_float2(v10, v11);
        }
    }
}

// ---------------- flash attention on mma.sync tf32 ---------------------------
// 64 queries x 64 keys/iter, 32 iters. 8 warps: 4m x 2n.
// FIX vs R3/R5: each 16-float row segment needs FOUR cp_async16 (not one).
#define ASTR 68     // Q/K/P row stride (floats)
#define VSTR 72     // V row stride
#define OFF_Q  0
#define OFF_K  (64 * ASTR)                 // two buffers
#define OFF_V  (OFF_K + 2 * 64 * ASTR)     // two buffers (VSTR)
#define OFF_P  (OFF_V + 2 * 64 * VSTR)
#define OFF_RM (OFF_P + 64 * ASTR)         // redM[2][64]
#define OFF_RS (OFF_RM + 128)              // redS[2][64]
#define ATTN_SMEM ((OFF_RS + 128) * 4)     // 107520 B

__global__ __launch_bounds__(256, 1)
void attn_tc(const float* __restrict__ QKV, float* __restrict__ O) {
    extern __shared__ float sm[];
    int tid = threadIdx.x;
    int lane = tid & 31, w = tid >> 5;
    int wm = w & 3, wn = w >> 2;
    int ar = lane >> 2, ac = lane & 3;

    int bh = blockIdx.y;
    int b = bh >> 3, h = bh & 7;
    int qbase = blockIdx.x * 64;
    const float* Qg = QKV + (size_t)(b * NS + qbase) * QLD + h * NHD;
    const float* Kg = QKV + (size_t)b * NS * QLD + 512 + h * NHD;
    const float* Vg = QKV + (size_t)b * NS * QLD + 1024 + h * NHD;

    uint32_t sbase = smem_u32(sm);
    int trow = tid >> 2;            // 0..63
    int tseg = (tid & 3) * 16;      // float offset (16-float segment)

    // Q + K0 + V0  (4x cp_async16 per 16-float segment)
    {
        const float* qp = Qg + (size_t)trow * QLD + tseg;
        const float* kp = Kg + (size_t)trow * QLD + tseg;
        const float* vp = Vg + (size_t)trow * QLD + tseg;
        uint32_t qd = sbase + (uint32_t)(OFF_Q + trow * ASTR + tseg) * 4;
        uint32_t kd = sbase + (uint32_t)(OFF_K + trow * ASTR + tseg) * 4;
        uint32_t vd = sbase + (uint32_t)(OFF_V + trow * VSTR + tseg) * 4;
#pragma unroll
        for (int i = 0; i < 4; i++) {
            cp_async16(qd + i * 16, qp + i * 4);
            cp_async16(kd + i * 16, kp + i * 4);
            cp_async16(vd + i * 16, vp + i * 4);
        }
    }
    cp_commit();

    float of[4][4];
#pragma unroll
    for (int nt = 0; nt < 4; nt++)
#pragma unroll
        for (int u = 0; u < 4; u++) of[nt][u] = 0.f;
    float m0 = -1e30f, m1 = -1e30f, l0 = 0.f, l1 = 0.f;

    int r0 = wm * 16 + ar, r1 = r0 + 8;
    float* Ps = sm + OFF_P;
    float* redM = sm + OFF_RM;
    float* redS = sm + OFF_RS;

    for (int ct = 0; ct < NS / 64; ct++) {
        cp_wait<0>();
        __syncthreads();
        if (ct + 1 < NS / 64) {
            int nb = (ct + 1) & 1;
            const float* kn = Kg + (size_t)((ct + 1) * 64 + trow) * QLD + tseg;
            const float* vn = Vg + (size_t)((ct + 1) * 64 + trow) * QLD + tseg;
            uint32_t kd = sbase + (uint32_t)(OFF_K + nb * 64 * ASTR + trow * ASTR + tseg) * 4;
            uint32_t vd = sbase + (uint32_t)(OFF_V + nb * 64 * VSTR + trow * VSTR + tseg) * 4;
#pragma unroll
            for (int i = 0; i < 4; i++) {
                cp_async16(kd + i * 16, kn + i * 4);
                cp_async16(vd + i * 16, vn + i * 4);
            }
            cp_commit();
        }

        const float* Qs = sm + OFF_Q;
        const float* Ks = sm + OFF_K + (ct & 1) * 64 * ASTR;
        const float* Vs = sm + OFF_V + (ct & 1) * 64 * VSTR;

        // S = Q K^T  (warp: rows wm*16..+16, cols wn*32..+32)
        float sf[4][4];
#pragma unroll
        for (int nt = 0; nt < 4; nt++)
#pragma unroll
            for (int u = 0; u < 4; u++) sf[nt][u] = 0.f;
#pragma unroll
        for (int ks = 0; ks < 8; ks++) {
            int kc = ks * 8 + ac;
            uint32_t af[4], bf[4][2];
            af[0] = f2u(Qs[r0 * ASTR + kc]);
            af[1] = f2u(Qs[r1 * ASTR + kc]);
            af[2] = f2u(Qs[r0 * ASTR + kc + 4]);
            af[3] = f2u(Qs[r1 * ASTR + kc + 4]);
#pragma unroll
            for (int nt = 0; nt < 4; nt++) {
                int cc = wn * 32 + nt * 8 + ar;
                bf[nt][0] = f2u(Ks[cc * ASTR + kc]);
                bf[nt][1] = f2u(Ks[cc * ASTR + kc + 4]);
            }
#pragma unroll
            for (int nt = 0; nt < 4; nt++) mma8(sf[nt], af, bf[nt]);
        }

        // scale + row max (reduce over ac lanes, then the 2 wn warps via smem)
        float mx0 = -1e30f, mx1 = -1e30f;
#pragma unroll
        for (int nt = 0; nt < 4; nt++) {
#pragma unroll
            for (int u = 0; u < 4; u++) sf[nt][u] *= 0.125f;
            mx0 = fmaxf(mx0, fmaxf(sf[nt][0], sf[nt][1]));
            mx1 = fmaxf(mx1, fmaxf(sf[nt][2], sf[nt][3]));
        }
        mx0 = fmaxf(mx0, __shfl_xor_sync(0xFFFFFFFFu, mx0, 1));
        mx0 = fmaxf(mx0, __shfl_xor_sync(0xFFFFFFFFu, mx0, 2));
        mx1 = fmaxf(mx1, __shfl_xor_sync(0xFFFFFFFFu, mx1, 1));
        mx1 = fmaxf(mx1, __shfl_xor_sync(0xFFFFFFFFu, mx1, 2));
        if (ac == 0) { redM[wn * 64 + r0] = mx0; redM[wn * 64 + r1] = mx1; }
        __syncthreads();
        float mn0 = fmaxf(m0, fmaxf(redM[r0], redM[64 + r0]));
        float mn1 = fmaxf(m1, fmaxf(redM[r1], redM[64 + r1]));
        float cr0 = __expf(m0 - mn0), cr1 = __expf(m1 - mn1);
        m0 = mn0; m1 = mn1;
#pragma unroll
        for (int nt = 0; nt < 4; nt++) {
            of[nt][0] *= cr0; of[nt][1] *= cr0;
            of[nt][2] *= cr1; of[nt][3] *= cr1;
        }

        // exp + P store (tf32-rounded) + row sum
        float s0 = 0.f, s1 = 0.f;
#pragma unroll
        for (int nt = 0; nt < 4; nt++) {
            float p00 = __expf(sf[nt][0] - mn0), p01 = __expf(sf[nt][1] - mn0);
            float p10 = __expf(sf[nt][2] - mn1), p11 = __expf(sf[nt][3] - mn1);
            s0 += p00 + p01; s1 += p10 + p11;
            int cc = wn * 32 + nt * 8 + 2 * ac;
            *(float2*)&Ps[r0 * ASTR + cc] = make_float2(rtf32(p00), rtf32(p01));
            *(float2*)&Ps[r1 * ASTR + cc] = make_float2(rtf32(p10), rtf32(p11));
        }
        s0 += __shfl_xor_sync(0xFFFFFFFFu, s0, 1);
        s0 += __shfl_xor_sync(0xFFFFFFFFu, s0, 2);
        s1 += __shfl_xor_sync(0xFFFFFFFFu, s1, 1);
        s1 += __shfl_xor_sync(0xFFFFFFFFu, s1, 2);
        if (ac == 0) { redS[wn * 64 + r0] = s0; redS[wn * 64 + r1] = s1; }
        __syncthreads();    // P + redS visible to all
        l0 = l0 * cr0 + redS[r0] + redS[64 + r0];
        l1 = l1 * cr1 + redS[r1] + redS[64 + r1];

        // O += P V  (A = P rows, B = V[k=key][n=feat])
#pragma unroll
        for (int ks = 0; ks < 8; ks++) {
            int kc = ks * 8 + ac;
            uint32_t af[4], bf[4][2];
            af[0] = f2u(Ps[r0 * ASTR + kc]);
            af[1] = f2u(Ps[r1 * ASTR + kc]);
            af[2] = f2u(Ps[r0 * ASTR + kc + 4]);
            af[3] = f2u(Ps[r1 * ASTR + kc + 4]);
#pragma unroll
            for (int nt = 0; nt < 4; nt++) {
                int cc = wn * 32 + nt * 8 + ar;
                bf[nt][0] = f2u(Vs[(kc) * VSTR + cc]);
                bf[nt][1] = f2u(Vs[(kc + 4) * VSTR + cc]);
            }
#pragma unroll
            for (int nt = 0; nt < 4; nt++) mma8(of[nt], af, bf[nt]);
        }
    }

    float i0 = 1.0f / l0, i1 = 1.0f / l1;
#pragma unroll
    for (int nt = 0; nt < 4; nt++) {
        int col = h * NHD + wn * 32 + nt * 8 + 2 * ac;
        size_t o0 = (size_t)(b * NS + qbase + r0) * ND + col;
        size_t o1 = (size_t)(b * NS + qbase + r1) * ND + col;
        *(float2*)(O + o0) = make_float2(rtf32(of[nt][0] * i0), rtf32(of[nt][1] * i0));
        *(float2*)(O + o1) = make_float2(rtf32(of[nt][2] * i1), rtf32(of[nt][3] * i1));
    }
}

// ---------------- layernorm --------------------------------------------------
__global__ __launch_bounds__(128)
void layernorm_kernel(const float* __restrict__ X, const float* __restrict__ g,
                      const float* __restrict__ beta, float* __restrict__ Y,
                      float* __restrict__ Yr) {
    __shared__ float ssum[4], ssq[4];
    int row = blockIdx.x;
    int t = threadIdx.x;
    float4 v = ((const float4*)(X + (size_t)row * ND))[t];
    float s = v.x + v.y + v.z + v.w;
    float q = v.x * v.x + v.y * v.y + v.z * v.z + v.w * v.w;
#pragma unroll
    for (int off = 16; off > 0; off >>= 1) {
        s += __shfl_xor_sync(0xFFFFFFFFu, s, off);
        q += __shfl_xor_sync(0xFFFFFFFFu, q, off);
    }
    int w = t >> 5;
    if ((t & 31) == 0) { ssum[w] = s; ssq[w] = q; }
    __syncthreads();
    s = ssum[0] + ssum[1] + ssum[2] + ssum[3];
    q = ssq[0] + ssq[1] + ssq[2] + ssq[3];
    float mu = s * (1.0f / 512.0f);
    float var = q * (1.0f / 512.0f) - mu * mu;
    float rstd = rsqrtf(var + 1e-12f);
    float4 gv = ((const float4*)g)[t];
    float4 bv = ((const float4*)beta)[t];
    float4 y;
    y.x = (v.x - mu) * rstd * gv.x + bv.x;
    y.y = (v.y - mu) * rstd * gv.y + bv.y;
    y.z = (v.z - mu) * rstd * gv.z + bv.z;
    y.w = (v.w - mu) * rstd * gv.w + bv.w;
    ((float4*)(Y + (size_t)row * ND))[t] = y;
    if (Yr) {
        float4 yr = make_float4(rtf32(y.x), rtf32(y.y), rtf32(y.z), rtf32(y.w));
        ((float4*)(Yr + (size_t)row * ND))[t] = yr;
    }
}

// ---------------- launch -----------------------------------------------------
extern "C" void kernel_launch(void* const* d_in, const int* in_sizes, int n_in,
                              void* d_out, int out_size) {
    const float* x    = (const float*)d_in[0];
    const float* Wq   = (const float*)d_in[1];
    const float* bq   = (const float*)d_in[2];
    const float* Wk   = (const float*)d_in[3];
    const float* bk   = (const float*)d_in[4];
    const float* Wv   = (const float*)d_in[5];
    const float* bv   = (const float*)d_in[6];
    const float* Wo   = (const float*)d_in[7];
    const float* bo   = (const float*)d_in[8];
    const float* W1   = (const float*)d_in[9];
    const float* b1   = (const float*)d_in[10];
    const float* W2   = (const float*)d_in[11];
    const float* b2   = (const float*)d_in[12];
    const float* ln1g = (const float*)d_in[13];
    const float* ln1b = (const float*)d_in[14];
    const float* ln2g = (const float*)d_in[15];
    const float* ln2b = (const float*)d_in[16];

    float *wqkvt, *bqkv, *wot, *w1t, *w2t, *xr, *qkv, *attnb, *res1, *x1, *x1r, *hb, *res2;
    cudaGetSymbolAddress((void**)&wqkvt, g_wqkvt);
    cudaGetSymbolAddress((void**)&bqkv,  g_bqkv);
    cudaGetSymbolAddress((void**)&wot,   g_wot);
    cudaGetSymbolAddress((void**)&w1t,   g_w1t);
    cudaGetSymbolAddress((void**)&w2t,   g_w2t);
    cudaGetSymbolAddress((void**)&xr,    g_xr);
    cudaGetSymbolAddress((void**)&qkv,   g_qkv);
    cudaGetSymbolAddress((void**)&attnb, g_attn);
    cudaGetSymbolAddress((void**)&res1,  g_res1);
    cudaGetSymbolAddress((void**)&x1,    g_x1);
    cudaGetSymbolAddress((void**)&x1r,   g_x1r);
    cudaGetSymbolAddress((void**)&hb,    g_h);
    cudaGetSymbolAddress((void**)&res2,  g_res2);

    cudaFuncSetAttribute(gemm_tc, cudaFuncAttributeMaxDynamicSharedMemorySize, GEMM_SMEM);
    cudaFuncSetAttribute(attn_tc, cudaFuncAttributeMaxDynamicSharedMemorySize, ATTN_SMEM);

    // prep
    pack_qkvw_kernel<<<(1536 * 512) / 256, 256>>>(Wq, Wk, Wv, wqkvt);
    pack_qkvb_kernel<<<6, 256>>>(bq, bk, bv, bqkv);
    transpose_round_kernel<<<(512 * 512) / 256, 256>>>(Wo, wot, 512, 512);
    transpose_round_kernel<<<(2048 * 512) / 256, 256>>>(W1, w1t, 512, 2048);
    transpose_round_kernel<<<(512 * 2048) / 256, 256>>>(W2, w2t, 2048, 512);
    round4_kernel<<<(NROW * ND / 4) / 256, 256>>>(x, xr);

    // QKV fused projection
    gemm_tc<<<dim3(12, 64), 256, GEMM_SMEM>>>(xr, wqkvt, bqkv, nullptr, qkv, 1536, 512, EPI_BIAS_R);

    // flash attention (tensor cores)
    attn_tc<<<dim3(NS / 64, NB * NH), 256, ATTN_SMEM>>>(qkv, attnb);

    // Wo + residual(x); LN1
    gemm_tc<<<dim3(4, 64), 256, GEMM_SMEM>>>(attnb, wot, bo, x, res1, 512, 512, EPI_RES);
    layernorm_kernel<<<NROW, 128>>>(res1, ln1g, ln1b, x1, x1r);

    // FFN
    gemm_tc<<<dim3(16, 64), 256, GEMM_SMEM>>>(x1r, w1t, b1, nullptr, hb, 2048, 512, EPI_GELU);
    gemm_tc<<<dim3(4, 64), 256, GEMM_SMEM>>>(hb, w2t, b2, x1, res2, 512, 2048, EPI_RES);

    // LN2 -> out
    layernorm_kernel<<<NROW, 128>>>(res2, ln2g, ln2b, (float*)d_out, nullptr);
}

// round 7
// speedup vs baseline: 2.8954x; 1.0975x over previous
#include <cuda_runtime.h>
#include <math.h>
#include <cstdint>

// Problem dims
#define NB 4
#define NS 2048
#define ND 512
#define NH 8
#define NHD 64
#define NF 2048
#define NROW (NB * NS)   // 8192
#define QLD 1536         // fused qkv row stride

// ---------------- scratch ----------------------------------------------------
__device__ float g_wqkvt[1536 * 512];   // [n][k] rounded
__device__ float g_bqkv[1536];
__device__ float g_wot[512 * 512];
__device__ float g_w1t[2048 * 512];
__device__ float g_w2t[512 * 2048];
__device__ float g_xr[NROW * ND];       // x rounded (GEMM A)
__device__ float g_qkv[NROW * 1536];    // rounded (epilogue)
__device__ float g_attn[NROW * ND];     // rounded
__device__ float g_res1[NROW * ND];
__device__ float g_x1[NROW * ND];
__device__ float g_x1r[NROW * ND];      // rounded
__device__ float g_h[NROW * NF];        // rounded
__device__ float g_res2[NROW * ND];

// ---------------- helpers ----------------------------------------------------
__device__ __forceinline__ float rtf32(float x) {
    uint32_t r;
    asm("cvt.rna.tf32.f32 %0, %1;" : "=r"(r) : "f"(x));
    return __uint_as_float(r);
}
__device__ __forceinline__ uint32_t smem_u32(const void* p) {
    uint32_t a;
    asm("{ .reg .u64 t; cvta.to.shared.u64 t, %1; cvt.u32.u64 %0, t; }" : "=r"(a) : "l"(p));
    return a;
}
__device__ __forceinline__ void cp_async16(uint32_t sa, const void* ga) {
    asm volatile("cp.async.cg.shared.global [%0], [%1], 16;" :: "r"(sa), "l"(ga) : "memory");
}
__device__ __forceinline__ void cp_commit() { asm volatile("cp.async.commit_group;" ::: "memory"); }
template <int N> __device__ __forceinline__ void cp_wait() {
    asm volatile("cp.async.wait_group %0;" :: "n"(N) : "memory");
}
// D += A*B  (m16n8k8 tf32)
__device__ __forceinline__ void mma8(float* c, const uint32_t* a, const uint32_t* b) {
    asm volatile("mma.sync.aligned.m16n8k8.row.col.f32.tf32.tf32.f32 "
                 "{%0,%1,%2,%3}, {%4,%5,%6,%7}, {%8,%9}, {%0,%1,%2,%3};"
                 : "+f"(c[0]), "+f"(c[1]), "+f"(c[2]), "+f"(c[3])
                 : "r"(a[0]), "r"(a[1]), "r"(a[2]), "r"(a[3]), "r"(b[0]), "r"(b[1]));
}
__device__ __forceinline__ uint32_t f2u(float x) { return __float_as_uint(x); }

// ---------------- prep kernels -----------------------------------------------
__global__ void pack_qkvw_kernel(const float* __restrict__ Wq, const float* __restrict__ Wk,
                                 const float* __restrict__ Wv, float* __restrict__ out) {
    int idx = blockIdx.x * 256 + threadIdx.x;     // 1536*512
    int k = idx & 511;
    int n = idx >> 9;
    int sel = n >> 9;
    int h = (n >> 6) & 7;
    int e = n & 63;
    const float* W = sel == 0 ? Wq : (sel == 1 ? Wk : Wv);
    out[idx] = rtf32(W[h * (512 * 64) + k * 64 + e]);
}
__global__ void pack_qkvb_kernel(const float* __restrict__ bq, const float* __restrict__ bk,
                                 const float* __restrict__ bv, float* __restrict__ out) {
    int n = blockIdx.x * 256 + threadIdx.x;
    if (n >= 1536) return;
    int sel = n >> 9, r = n & 511;
    const float* b = sel == 0 ? bq : (sel == 1 ? bk : bv);
    out[n] = b[r];
}
__global__ void transpose_round_kernel(const float* __restrict__ in, float* __restrict__ out, int K, int N) {
    int idx = blockIdx.x * 256 + threadIdx.x;
    int k = idx % K;
    int n = idx / K;
    out[idx] = rtf32(in[(size_t)k * N + n]);
}
__global__ void round4_kernel(const float* __restrict__ in, float* __restrict__ out) {
    int i = blockIdx.x * 256 + threadIdx.x;
    float4 v = ((const float4*)in)[i];
    v.x = rtf32(v.x); v.y = rtf32(v.y); v.z = rtf32(v.z); v.w = rtf32(v.w);
    ((float4*)out)[i] = v;
}

// ---------------- tf32 mma.sync GEMM (4-stage pipeline) -----------------------
// C[8192, N] = A[8192,K] * Bt[N,K]^T + bias (+epi). Tiles 128x128x32, 8 warps.
#define GSTR 36                        // smem row stride (floats)
#define GSTAGE (128 * GSTR)            // floats per tile (A or B) = 4608
#define NSTG 4
#define GEMM_SMEM (NSTG * 2 * GSTAGE * 4)   // 147456 B

#define EPI_BIAS   0
#define EPI_BIAS_R 1   // + tf32 round
#define EPI_RES    2   // + residual
#define EPI_GELU   3   // + gelu + round

__global__ __launch_bounds__(256, 1)
void gemm_tc(const float* __restrict__ A, const float* __restrict__ Bt,
             const float* __restrict__ bias, const float* __restrict__ resid,
             float* __restrict__ C, int N, int K, int epi) {
    extern __shared__ float sm[];
    int tid = threadIdx.x;
    int lane = tid & 31, w = tid >> 5;
    int wm = w & 3, wn = w >> 2;        // 4 m-warps x 2 n-warps
    int ar = lane >> 2, ac = lane & 3;
    int brow = blockIdx.y * 128, bcol = blockIdx.x * 128;

    int lrow = tid >> 1, lc = (tid & 1) * 16;
    const float* Ap = A + (size_t)(brow + lrow) * K + lc;
    const float* Bp = Bt + (size_t)(bcol + lrow) * K + lc;
    uint32_t sbase = smem_u32(sm);
    uint32_t dstoff = (uint32_t)(lrow * GSTR + lc) * 4;
    int KT = K / 32;

#define GFETCH(kt_) do { \
        uint32_t ab_ = sbase + ((kt_) & 3) * (2 * GSTAGE * 4); \
        uint32_t bb_ = ab_ + GSTAGE * 4; \
        const float* ap_ = Ap + (kt_) * 32; \
        const float* bp_ = Bp + (kt_) * 32; \
        cp_async16(ab_ + dstoff,      ap_); \
        cp_async16(ab_ + dstoff + 16, ap_ + 4); \
        cp_async16(ab_ + dstoff + 32, ap_ + 8); \
        cp_async16(ab_ + dstoff + 48, ap_ + 12); \
        cp_async16(bb_ + dstoff,      bp_); \
        cp_async16(bb_ + dstoff + 16, bp_ + 4); \
        cp_async16(bb_ + dstoff + 32, bp_ + 8); \
        cp_async16(bb_ + dstoff + 48, bp_ + 12); \
        cp_commit(); \
    } while (0)

    GFETCH(0); GFETCH(1); GFETCH(2);

    float cf[2][8][4];
#pragma unroll
    for (int mt = 0; mt < 2; mt++)
#pragma unroll
        for (int nt = 0; nt < 8; nt++)
#pragma unroll
            for (int u = 0; u < 4; u++) cf[mt][nt][u] = 0.f;

    for (int kt = 0; kt < KT; kt++) {
        // pending groups at this point = min(3, KT - kt); need fetch kt done.
        int pend = KT - kt;
        if (pend >= 3) cp_wait<2>();
        else if (pend == 2) cp_wait<1>();
        else cp_wait<0>();
        __syncthreads();

        const float* As = sm + (kt & 3) * 2 * GSTAGE;
        const float* Bs = As + GSTAGE;
#pragma unroll
        for (int ks = 0; ks < 4; ks++) {
            uint32_t af[2][4], bf[8][2];
            int kc = ks * 8 + ac;
#pragma unroll
            for (int mt = 0; mt < 2; mt++) {
                int r = wm * 32 + mt * 16 + ar;
                af[mt][0] = f2u(As[r * GSTR + kc]);
                af[mt][1] = f2u(As[(r + 8) * GSTR + kc]);
                af[mt][2] = f2u(As[r * GSTR + kc + 4]);
                af[mt][3] = f2u(As[(r + 8) * GSTR + kc + 4]);
            }
#pragma unroll
            for (int nt = 0; nt < 8; nt++) {
                int cc = wn * 64 + nt * 8 + ar;
                bf[nt][0] = f2u(Bs[cc * GSTR + kc]);
                bf[nt][1] = f2u(Bs[cc * GSTR + kc + 4]);
            }
#pragma unroll
            for (int mt = 0; mt < 2; mt++)
#pragma unroll
                for (int nt = 0; nt < 8; nt++)
                    mma8(cf[mt][nt], af[mt], bf[nt]);
        }
        // fetch kt+3 into slot (kt+3)&3 == (kt-1)&3 — consumed at iter kt-1,
        // and all warps passed this iter's __syncthreads after computing kt-1.
        if (kt + 3 < KT) GFETCH(kt + 3);
    }

    // epilogue
#pragma unroll
    for (int nt = 0; nt < 8; nt++) {
        int col = bcol + wn * 64 + nt * 8 + 2 * ac;
        float b0 = bias[col], b1 = bias[col + 1];
#pragma unroll
        for (int mt = 0; mt < 2; mt++) {
            int r0 = brow + wm * 32 + mt * 16 + ar;
            float v00 = cf[mt][nt][0] + b0, v01 = cf[mt][nt][1] + b1;
            float v10 = cf[mt][nt][2] + b0, v11 = cf[mt][nt][3] + b1;
            size_t o0 = (size_t)r0 * N + col;
            size_t o1 = (size_t)(r0 + 8) * N + col;
            if (epi == EPI_RES) {
                float2 q0 = *(const float2*)(resid + o0);
                float2 q1 = *(const float2*)(resid + o1);
                v00 += q0.x; v01 += q0.y; v10 += q1.x; v11 += q1.y;
            } else if (epi == EPI_GELU) {
                v00 = rtf32(0.5f * v00 * (1.0f + erff(v00 * 0.70710678118654752f)));
                v01 = rtf32(0.5f * v01 * (1.0f + erff(v01 * 0.70710678118654752f)));
                v10 = rtf32(0.5f * v10 * (1.0f + erff(v10 * 0.70710678118654752f)));
                v11 = rtf32(0.5f * v11 * (1.0f + erff(v11 * 0.70710678118654752f)));
            } else if (epi == EPI_BIAS_R) {
                v00 = rtf32(v00); v01 = rtf32(v01); v10 = rtf32(v10); v11 = rtf32(v11);
            }
            *(float2*)(C + o0) = make_float2(v00, v01);
            *(float2*)(C + o1) = make_float2(v10, v11);
        }
    }
}

// ---------------- flash attention on mma.sync tf32, 128-query tiles ----------
// 128 queries x 64 keys/iter, 32 iters. 8 warps: 4m (32 rows each) x 2n (32 cols).
#define ASTR 68     // Q/K/P row stride (floats)
#define VSTR 72     // V row stride
#define OFF_Q  0                           // 128*68 = 8704 floats
#define OFF_K  (128 * ASTR)                // 2 buf x 64*68
#define OFF_V  (OFF_K + 2 * 64 * ASTR)     // 2 buf x 64*72
#define OFF_P  (OFF_V + 2 * 64 * VSTR)     // 128*68
#define OFF_RM (OFF_P + 128 * ASTR)        // redM[2][128]
#define OFF_RS (OFF_RM + 256)              // redS[2][128]
#define ATTN_SMEM ((OFF_RS + 256) * 4)     // 143360 B

__global__ __launch_bounds__(256, 1)
void attn_tc(const float* __restrict__ QKV, float* __restrict__ O) {
    extern __shared__ float sm[];
    int tid = threadIdx.x;
    int lane = tid & 31, w = tid >> 5;
    int wm = w & 3, wn = w >> 2;
    int ar = lane >> 2, ac = lane & 3;

    int bh = blockIdx.y;
    int b = bh >> 3, h = bh & 7;
    int qbase = blockIdx.x * 128;
    const float* Qg = QKV + (size_t)(b * NS + qbase) * QLD + h * NHD;
    const float* Kg = QKV + (size_t)b * NS * QLD + 512 + h * NHD;
    const float* Vg = QKV + (size_t)b * NS * QLD + 1024 + h * NHD;

    uint32_t sbase = smem_u32(sm);
    int trow = tid >> 2;            // 0..63
    int tseg = (tid & 3) * 16;      // 16-float segment

    // Q (128 rows: trow and trow+64) + K0 + V0
    {
#pragma unroll
        for (int rr = 0; rr < 2; rr++) {
            int r = trow + rr * 64;
            const float* qp = Qg + (size_t)r * QLD + tseg;
            uint32_t qd = sbase + (uint32_t)(OFF_Q + r * ASTR + tseg) * 4;
#pragma unroll
            for (int i = 0; i < 4; i++) cp_async16(qd + i * 16, qp + i * 4);
        }
        const float* kp = Kg + (size_t)trow * QLD + tseg;
        const float* vp = Vg + (size_t)trow * QLD + tseg;
        uint32_t kd = sbase + (uint32_t)(OFF_K + trow * ASTR + tseg) * 4;
        uint32_t vd = sbase + (uint32_t)(OFF_V + trow * VSTR + tseg) * 4;
#pragma unroll
        for (int i = 0; i < 4; i++) {
            cp_async16(kd + i * 16, kp + i * 4);
            cp_async16(vd + i * 16, vp + i * 4);
        }
    }
    cp_commit();

    float of[2][4][4];
#pragma unroll
    for (int mt = 0; mt < 2; mt++)
#pragma unroll
        for (int nt = 0; nt < 4; nt++)
#pragma unroll
            for (int u = 0; u < 4; u++) of[mt][nt][u] = 0.f;
    float mm[2][2], ll[2][2];
#pragma unroll
    for (int mt = 0; mt < 2; mt++) { mm[mt][0] = mm[mt][1] = -1e30f; ll[mt][0] = ll[mt][1] = 0.f; }

    int rb[2];
    rb[0] = wm * 32 + ar;          // rows rb, rb+8 (mt=0)
    rb[1] = wm * 32 + 16 + ar;     // rows rb, rb+8 (mt=1)
    float* Ps = sm + OFF_P;
    float* redM = sm + OFF_RM;
    float* redS = sm + OFF_RS;

    for (int ct = 0; ct < NS / 64; ct++) {
        cp_wait<0>();
        __syncthreads();
        if (ct + 1 < NS / 64) {
            int nb = (ct + 1) & 1;
            const float* kn = Kg + (size_t)((ct + 1) * 64 + trow) * QLD + tseg;
            const float* vn = Vg + (size_t)((ct + 1) * 64 + trow) * QLD + tseg;
            uint32_t kd = sbase + (uint32_t)(OFF_K + nb * 64 * ASTR + trow * ASTR + tseg) * 4;
            uint32_t vd = sbase + (uint32_t)(OFF_V + nb * 64 * VSTR + trow * VSTR + tseg) * 4;
#pragma unroll
            for (int i = 0; i < 4; i++) {
                cp_async16(kd + i * 16, kn + i * 4);
                cp_async16(vd + i * 16, vn + i * 4);
            }
            cp_commit();
        }

        const float* Qs = sm + OFF_Q;
        const float* Ks = sm + OFF_K + (ct & 1) * 64 * ASTR;
        const float* Vs = sm + OFF_V + (ct & 1) * 64 * VSTR;

        // S = Q K^T   (warp: rows wm*32..+32 via 2 mt, cols wn*32..+32)
        float sf[2][4][4];
#pragma unroll
        for (int mt = 0; mt < 2; mt++)
#pragma unroll
            for (int nt = 0; nt < 4; nt++)
#pragma unroll
                for (int u = 0; u < 4; u++) sf[mt][nt][u] = 0.f;
#pragma unroll
        for (int ks = 0; ks < 8; ks++) {
            int kc = ks * 8 + ac;
            uint32_t af[2][4], bf[4][2];
#pragma unroll
            for (int mt = 0; mt < 2; mt++) {
                af[mt][0] = f2u(Qs[rb[mt] * ASTR + kc]);
                af[mt][1] = f2u(Qs[(rb[mt] + 8) * ASTR + kc]);
                af[mt][2] = f2u(Qs[rb[mt] * ASTR + kc + 4]);
                af[mt][3] = f2u(Qs[(rb[mt] + 8) * ASTR + kc + 4]);
            }
#pragma unroll
            for (int nt = 0; nt < 4; nt++) {
                int cc = wn * 32 + nt * 8 + ar;
                bf[nt][0] = f2u(Ks[cc * ASTR + kc]);
                bf[nt][1] = f2u(Ks[cc * ASTR + kc + 4]);
            }
#pragma unroll
            for (int mt = 0; mt < 2; mt++)
#pragma unroll
                for (int nt = 0; nt < 4; nt++) mma8(sf[mt][nt], af[mt], bf[nt]);
        }

        // scale + row max; reduce across ac lanes then the 2 wn warps via smem
#pragma unroll
        for (int mt = 0; mt < 2; mt++) {
            float mx0 = -1e30f, mx1 = -1e30f;
#pragma unroll
            for (int nt = 0; nt < 4; nt++) {
#pragma unroll
                for (int u = 0; u < 4; u++) sf[mt][nt][u] *= 0.125f;
                mx0 = fmaxf(mx0, fmaxf(sf[mt][nt][0], sf[mt][nt][1]));
                mx1 = fmaxf(mx1, fmaxf(sf[mt][nt][2], sf[mt][nt][3]));
            }
            mx0 = fmaxf(mx0, __shfl_xor_sync(0xFFFFFFFFu, mx0, 1));
            mx0 = fmaxf(mx0, __shfl_xor_sync(0xFFFFFFFFu, mx0, 2));
            mx1 = fmaxf(mx1, __shfl_xor_sync(0xFFFFFFFFu, mx1, 1));
            mx1 = fmaxf(mx1, __shfl_xor_sync(0xFFFFFFFFu, mx1, 2));
            if (ac == 0) {
                redM[wn * 128 + rb[mt]] = mx0;
                redM[wn * 128 + rb[mt] + 8] = mx1;
            }
        }
        __syncthreads();

        float cr[2][2];
#pragma unroll
        for (int mt = 0; mt < 2; mt++) {
            float mn0 = fmaxf(mm[mt][0], fmaxf(redM[rb[mt]], redM[128 + rb[mt]]));
            float mn1 = fmaxf(mm[mt][1], fmaxf(redM[rb[mt] + 8], redM[128 + rb[mt] + 8]));
            cr[mt][0] = __expf(mm[mt][0] - mn0);
            cr[mt][1] = __expf(mm[mt][1] - mn1);
            mm[mt][0] = mn0; mm[mt][1] = mn1;
#pragma unroll
            for (int nt = 0; nt < 4; nt++) {
                of[mt][nt][0] *= cr[mt][0]; of[mt][nt][1] *= cr[mt][0];
                of[mt][nt][2] *= cr[mt][1]; of[mt][nt][3] *= cr[mt][1];
            }
        }

        // exp + P store (tf32-rounded) + row sum
#pragma unroll
        for (int mt = 0; mt < 2; mt++) {
            float s0 = 0.f, s1 = 0.f;
#pragma unroll
            for (int nt = 0; nt < 4; nt++) {
                float p00 = __expf(sf[mt][nt][0] - mm[mt][0]);
                float p01 = __expf(sf[mt][nt][1] - mm[mt][0]);
                float p10 = __expf(sf[mt][nt][2] - mm[mt][1]);
                float p11 = __expf(sf[mt][nt][3] - mm[mt][1]);
                s0 += p00 + p01; s1 += p10 + p11;
                int cc = wn * 32 + nt * 8 + 2 * ac;
                *(float2*)&Ps[rb[mt] * ASTR + cc] = make_float2(rtf32(p00), rtf32(p01));
                *(float2*)&Ps[(rb[mt] + 8) * ASTR + cc] = make_float2(rtf32(p10), rtf32(p11));
            }
            s0 += __shfl_xor_sync(0xFFFFFFFFu, s0, 1);
            s0 += __shfl_xor_sync(0xFFFFFFFFu, s0, 2);
            s1 += __shfl_xor_sync(0xFFFFFFFFu, s1, 1);
            s1 += __shfl_xor_sync(0xFFFFFFFFu, s1, 2);
            if (ac == 0) {
                redS[wn * 128 + rb[mt]] = s0;
                redS[wn * 128 + rb[mt] + 8] = s1;
            }
        }
        __syncthreads();    // P + redS visible to all
#pragma unroll
        for (int mt = 0; mt < 2; mt++) {
            ll[mt][0] = ll[mt][0] * cr[mt][0] + redS[rb[mt]] + redS[128 + rb[mt]];
            ll[mt][1] = ll[mt][1] * cr[mt][1] + redS[rb[mt] + 8] + redS[128 + rb[mt] + 8];
        }

        // O += P V
#pragma unroll
        for (int ks = 0; ks < 8; ks++) {
            int kc = ks * 8 + ac;
            uint32_t af[2][4], bf[4][2];
#pragma unroll
            for (int mt = 0; mt < 2; mt++) {
                af[mt][0] = f2u(Ps[rb[mt] * ASTR + kc]);
                af[mt][1] = f2u(Ps[(rb[mt] + 8) * ASTR + kc]);
                af[mt][2] = f2u(Ps[rb[mt] * ASTR + kc + 4]);
                af[mt][3] = f2u(Ps[(rb[mt] + 8) * ASTR + kc + 4]);
            }
#pragma unroll
            for (int nt = 0; nt < 4; nt++) {
                int cc = wn * 32 + nt * 8 + ar;
                bf[nt][0] = f2u(Vs[(kc) * VSTR + cc]);
                bf[nt][1] = f2u(Vs[(kc + 4) * VSTR + cc]);
            }
#pragma unroll
            for (int mt = 0; mt < 2; mt++)
#pragma unroll
                for (int nt = 0; nt < 4; nt++) mma8(of[mt][nt], af[mt], bf[nt]);
        }
    }

#pragma unroll
    for (int mt = 0; mt < 2; mt++) {
        float i0 = 1.0f / ll[mt][0], i1 = 1.0f / ll[mt][1];
#pragma unroll
        for (int nt = 0; nt < 4; nt++) {
            int col = h * NHD + wn * 32 + nt * 8 + 2 * ac;
            size_t o0 = (size_t)(b * NS + qbase + rb[mt]) * ND + col;
            size_t o1 = (size_t)(b * NS + qbase + rb[mt] + 8) * ND + col;
            *(float2*)(O + o0) = make_float2(rtf32(of[mt][nt][0] * i0), rtf32(of[mt][nt][1] * i0));
            *(float2*)(O + o1) = make_float2(rtf32(of[mt][nt][2] * i1), rtf32(of[mt][nt][3] * i1));
        }
    }
}

// ---------------- layernorm --------------------------------------------------
__global__ __launch_bounds__(128)
void layernorm_kernel(const float* __restrict__ X, const float* __restrict__ g,
                      const float* __restrict__ beta, float* __restrict__ Y,
                      float* __restrict__ Yr) {
    __shared__ float ssum[4], ssq[4];
    int row = blockIdx.x;
    int t = threadIdx.x;
    float4 v = ((const float4*)(X + (size_t)row * ND))[t];
    float s = v.x + v.y + v.z + v.w;
    float q = v.x * v.x + v.y * v.y + v.z * v.z + v.w * v.w;
#pragma unroll
    for (int off = 16; off > 0; off >>= 1) {
        s += __shfl_xor_sync(0xFFFFFFFFu, s, off);
        q += __shfl_xor_sync(0xFFFFFFFFu, q, off);
    }
    int w = t >> 5;
    if ((t & 31) == 0) { ssum[w] = s; ssq[w] = q; }
    __syncthreads();
    s = ssum[0] + ssum[1] + ssum[2] + ssum[3];
    q = ssq[0] + ssq[1] + ssq[2] + ssq[3];
    float mu = s * (1.0f / 512.0f);
    float var = q * (1.0f / 512.0f) - mu * mu;
    float rstd = rsqrtf(var + 1e-12f);
    float4 gv = ((const float4*)g)[t];
    float4 bv = ((const float4*)beta)[t];
    float4 y;
    y.x = (v.x - mu) * rstd * gv.x + bv.x;
    y.y = (v.y - mu) * rstd * gv.y + bv.y;
    y.z = (v.z - mu) * rstd * gv.z + bv.z;
    y.w = (v.w - mu) * rstd * gv.w + bv.w;
    ((float4*)(Y + (size_t)row * ND))[t] = y;
    if (Yr) {
        float4 yr = make_float4(rtf32(y.x), rtf32(y.y), rtf32(y.z), rtf32(y.w));
        ((float4*)(Yr + (size_t)row * ND))[t] = yr;
    }
}

// ---------------- launch -----------------------------------------------------
extern "C" void kernel_launch(void* const* d_in, const int* in_sizes, int n_in,
                              void* d_out, int out_size) {
    const float* x    = (const float*)d_in[0];
    const float* Wq   = (const float*)d_in[1];
    const float* bq   = (const float*)d_in[2];
    const float* Wk   = (const float*)d_in[3];
    const float* bk   = (const float*)d_in[4];
    const float* Wv   = (const float*)d_in[5];
    const float* bv   = (const float*)d_in[6];
    const float* Wo   = (const float*)d_in[7];
    const float* bo   = (const float*)d_in[8];
    const float* W1   = (const float*)d_in[9];
    const float* b1   = (const float*)d_in[10];
    const float* W2   = (const float*)d_in[11];
    const float* b2   = (const float*)d_in[12];
    const float* ln1g = (const float*)d_in[13];
    const float* ln1b = (const float*)d_in[14];
    const float* ln2g = (const float*)d_in[15];
    const float* ln2b = (const float*)d_in[16];

    float *wqkvt, *bqkv, *wot, *w1t, *w2t, *xr, *qkv, *attnb, *res1, *x1, *x1r, *hb, *res2;
    cudaGetSymbolAddress((void**)&wqkvt, g_wqkvt);
    cudaGetSymbolAddress((void**)&bqkv,  g_bqkv);
    cudaGetSymbolAddress((void**)&wot,   g_wot);
    cudaGetSymbolAddress((void**)&w1t,   g_w1t);
    cudaGetSymbolAddress((void**)&w2t,   g_w2t);
    cudaGetSymbolAddress((void**)&xr,    g_xr);
    cudaGetSymbolAddress((void**)&qkv,   g_qkv);
    cudaGetSymbolAddress((void**)&attnb, g_attn);
    cudaGetSymbolAddress((void**)&res1,  g_res1);
    cudaGetSymbolAddress((void**)&x1,    g_x1);
    cudaGetSymbolAddress((void**)&x1r,   g_x1r);
    cudaGetSymbolAddress((void**)&hb,    g_h);
    cudaGetSymbolAddress((void**)&res2,  g_res2);

    cudaFuncSetAttribute(gemm_tc, cudaFuncAttributeMaxDynamicSharedMemorySize, GEMM_SMEM);
    cudaFuncSetAttribute(attn_tc, cudaFuncAttributeMaxDynamicSharedMemorySize, ATTN_SMEM);

    // prep
    pack_qkvw_kernel<<<(1536 * 512) / 256, 256>>>(Wq, Wk, Wv, wqkvt);
    pack_qkvb_kernel<<<6, 256>>>(bq, bk, bv, bqkv);
    transpose_round_kernel<<<(512 * 512) / 256, 256>>>(Wo, wot, 512, 512);
    transpose_round_kernel<<<(2048 * 512) / 256, 256>>>(W1, w1t, 512, 2048);
    transpose_round_kernel<<<(512 * 2048) / 256, 256>>>(W2, w2t, 2048, 512);
    round4_kernel<<<(NROW * ND / 4) / 256, 256>>>(x, xr);

    // QKV fused projection
    gemm_tc<<<dim3(12, 64), 256, GEMM_SMEM>>>(xr, wqkvt, bqkv, nullptr, qkv, 1536, 512, EPI_BIAS_R);

    // flash attention (tensor cores, 128-query tiles)
    attn_tc<<<dim3(NS / 128, NB * NH), 256, ATTN_SMEM>>>(qkv, attnb);

    // Wo + residual(x); LN1
    gemm_tc<<<dim3(4, 64), 256, GEMM_SMEM>>>(attnb, wot, bo, x, res1, 512, 512, EPI_RES);
    layernorm_kernel<<<NROW, 128>>>(res1, ln1g, ln1b, x1, x1r);

    // FFN
    gemm_tc<<<dim3(16, 64), 256, GEMM_SMEM>>>(x1r, w1t, b1, nullptr, hb, 2048, 512, EPI_GELU);
    gemm_tc<<<dim3(4, 64), 256, GEMM_SMEM>>>(hb, w2t, b2, x1, res2, 512, 2048, EPI_RES);

    // LN2 -> out
    layernorm_kernel<<<NROW, 128>>>(res2, ln2g, ln2b, (float*)d_out, nullptr);
}

// round 8
// speedup vs baseline: 3.0919x; 1.0679x over previous
#include <cuda_runtime.h>
#include <math.h>
#include <cstdint>

// Problem dims
#define NB 4
#define NS 2048
#define ND 512
#define NH 8
#define NHD 64
#define NF 2048
#define NROW (NB * NS)   // 8192
#define QLD 1536         // fused qkv row stride

// ---------------- scratch ----------------------------------------------------
__device__ float g_wqkvt[1536 * 512];   // [n][k] rounded
__device__ float g_bqkv[1536];
__device__ float g_wot[512 * 512];
__device__ float g_w1t[2048 * 512];
__device__ float g_w2t[512 * 2048];
__device__ float g_xr[NROW * ND];       // x rounded (GEMM A)
__device__ float g_qkv[NROW * 1536];    // rounded (epilogue)
__device__ float g_attn[NROW * ND];     // rounded
__device__ float g_res1[NROW * ND];
__device__ float g_x1[NROW * ND];
__device__ float g_x1r[NROW * ND];      // rounded
__device__ float g_h[NROW * NF];        // rounded
__device__ float g_res2[NROW * ND];

// ---------------- helpers ----------------------------------------------------
__device__ __forceinline__ float rtf32(float x) {
    uint32_t r;
    asm("cvt.rna.tf32.f32 %0, %1;" : "=r"(r) : "f"(x));
    return __uint_as_float(r);
}
__device__ __forceinline__ uint32_t smem_u32(const void* p) {
    uint32_t a;
    asm("{ .reg .u64 t; cvta.to.shared.u64 t, %1; cvt.u32.u64 %0, t; }" : "=r"(a) : "l"(p));
    return a;
}
__device__ __forceinline__ void cp_async16(uint32_t sa, const void* ga) {
    asm volatile("cp.async.cg.shared.global [%0], [%1], 16;" :: "r"(sa), "l"(ga) : "memory");
}
__device__ __forceinline__ void cp_commit() { asm volatile("cp.async.commit_group;" ::: "memory"); }
template <int N> __device__ __forceinline__ void cp_wait() {
    asm volatile("cp.async.wait_group %0;" :: "n"(N) : "memory");
}
// D += A*B  (m16n8k8 tf32)
__device__ __forceinline__ void mma8(float* c, const uint32_t* a, const uint32_t* b) {
    asm volatile("mma.sync.aligned.m16n8k8.row.col.f32.tf32.tf32.f32 "
                 "{%0,%1,%2,%3}, {%4,%5,%6,%7}, {%8,%9}, {%0,%1,%2,%3};"
                 : "+f"(c[0]), "+f"(c[1]), "+f"(c[2]), "+f"(c[3])
                 : "r"(a[0]), "r"(a[1]), "r"(a[2]), "r"(a[3]), "r"(b[0]), "r"(b[1]));
}
__device__ __forceinline__ uint32_t f2u(float x) { return __float_as_uint(x); }

// ---------------- prep kernels -----------------------------------------------
__global__ void pack_qkvw_kernel(const float* __restrict__ Wq, const float* __restrict__ Wk,
                                 const float* __restrict__ Wv, float* __restrict__ out) {
    int idx = blockIdx.x * 256 + threadIdx.x;     // 1536*512
    int k = idx & 511;
    int n = idx >> 9;
    int sel = n >> 9;
    int h = (n >> 6) & 7;
    int e = n & 63;
    const float* W = sel == 0 ? Wq : (sel == 1 ? Wk : Wv);
    out[idx] = rtf32(W[h * (512 * 64) + k * 64 + e]);
}
__global__ void pack_qkvb_kernel(const float* __restrict__ bq, const float* __restrict__ bk,
                                 const float* __restrict__ bv, float* __restrict__ out) {
    int n = blockIdx.x * 256 + threadIdx.x;
    if (n >= 1536) return;
    int sel = n >> 9, r = n & 511;
    const float* b = sel == 0 ? bq : (sel == 1 ? bk : bv);
    out[n] = b[r];
}
__global__ void transpose_round_kernel(const float* __restrict__ in, float* __restrict__ out, int K, int N) {
    int idx = blockIdx.x * 256 + threadIdx.x;
    int k = idx % K;
    int n = idx / K;
    out[idx] = rtf32(in[(size_t)k * N + n]);
}
__global__ void round4_kernel(const float* __restrict__ in, float* __restrict__ out) {
    int i = blockIdx.x * 256 + threadIdx.x;
    float4 v = ((const float4*)in)[i];
    v.x = rtf32(v.x); v.y = rtf32(v.y); v.z = rtf32(v.z); v.w = rtf32(v.w);
    ((float4*)out)[i] = v;
}

// ---------------- tf32 mma.sync GEMM (3-stage, occ 2) -------------------------
// C[8192, N] = A[8192,K] * Bt[N,K]^T + bias (+epi). Tiles 128x128x32, 8 warps.
#define GSTR 36                        // smem row stride (floats)
#define GSTAGE (128 * GSTR)            // floats per tile (A or B) = 4608
#define NSTG 3
#define GEMM_SMEM (NSTG * 2 * GSTAGE * 4)   // 110592 B -> 2 CTAs/SM

#define EPI_BIAS   0
#define EPI_BIAS_R 1   // + tf32 round
#define EPI_RES    2   // + residual
#define EPI_GELU   3   // + gelu + round

__global__ __launch_bounds__(256, 2)
void gemm_tc(const float* __restrict__ A, const float* __restrict__ Bt,
             const float* __restrict__ bias, const float* __restrict__ resid,
             float* __restrict__ C, int N, int K, int epi) {
    extern __shared__ float sm[];
    int tid = threadIdx.x;
    int lane = tid & 31, w = tid >> 5;
    int wm = w & 3, wn = w >> 2;        // 4 m-warps x 2 n-warps
    int ar = lane >> 2, ac = lane & 3;
    int brow = blockIdx.y * 128, bcol = blockIdx.x * 128;

    int lrow = tid >> 1, lc = (tid & 1) * 16;
    const float* Ap = A + (size_t)(brow + lrow) * K + lc;
    const float* Bp = Bt + (size_t)(bcol + lrow) * K + lc;
    uint32_t sbase = smem_u32(sm);
    uint32_t dstoff = (uint32_t)(lrow * GSTR + lc) * 4;
    int KT = K / 32;

#define GFETCH(kt_) do { \
        uint32_t ab_ = sbase + ((kt_) % 3) * (2 * GSTAGE * 4); \
        uint32_t bb_ = ab_ + GSTAGE * 4; \
        const float* ap_ = Ap + (kt_) * 32; \
        const float* bp_ = Bp + (kt_) * 32; \
        cp_async16(ab_ + dstoff,      ap_); \
        cp_async16(ab_ + dstoff + 16, ap_ + 4); \
        cp_async16(ab_ + dstoff + 32, ap_ + 8); \
        cp_async16(ab_ + dstoff + 48, ap_ + 12); \
        cp_async16(bb_ + dstoff,      bp_); \
        cp_async16(bb_ + dstoff + 16, bp_ + 4); \
        cp_async16(bb_ + dstoff + 32, bp_ + 8); \
        cp_async16(bb_ + dstoff + 48, bp_ + 12); \
        cp_commit(); \
    } while (0)

    GFETCH(0); GFETCH(1);

    float cf[2][8][4];
#pragma unroll
    for (int mt = 0; mt < 2; mt++)
#pragma unroll
        for (int nt = 0; nt < 8; nt++)
#pragma unroll
            for (int u = 0; u < 4; u++) cf[mt][nt][u] = 0.f;

    for (int kt = 0; kt < KT; kt++) {
        // groups issued so far: up to index min(kt+1, KT-1). Need group kt done.
        if (kt + 1 < KT) cp_wait<1>();
        else cp_wait<0>();
        __syncthreads();

        const float* As = sm + (kt % 3) * 2 * GSTAGE;
        const float* Bs = As + GSTAGE;
#pragma unroll
        for (int ks = 0; ks < 4; ks++) {
            uint32_t af[2][4], bf[8][2];
            int kc = ks * 8 + ac;
#pragma unroll
            for (int mt = 0; mt < 2; mt++) {
                int r = wm * 32 + mt * 16 + ar;
                af[mt][0] = f2u(As[r * GSTR + kc]);
                af[mt][1] = f2u(As[(r + 8) * GSTR + kc]);
                af[mt][2] = f2u(As[r * GSTR + kc + 4]);
                af[mt][3] = f2u(As[(r + 8) * GSTR + kc + 4]);
            }
#pragma unroll
            for (int nt = 0; nt < 8; nt++) {
                int cc = wn * 64 + nt * 8 + ar;
                bf[nt][0] = f2u(Bs[cc * GSTR + kc]);
                bf[nt][1] = f2u(Bs[cc * GSTR + kc + 4]);
            }
#pragma unroll
            for (int mt = 0; mt < 2; mt++)
#pragma unroll
                for (int nt = 0; nt < 8; nt++)
                    mma8(cf[mt][nt], af[mt], bf[nt]);
        }
        // fetch kt+2 into slot (kt+2)%3 == (kt-1)%3: consumed at iter kt-1,
        // all warps passed this iter's __syncthreads since then.
        if (kt + 2 < KT) GFETCH(kt + 2);
    }

    // epilogue
#pragma unroll
    for (int nt = 0; nt < 8; nt++) {
        int col = bcol + wn * 64 + nt * 8 + 2 * ac;
        float b0 = bias[col], b1 = bias[col + 1];
#pragma unroll
        for (int mt = 0; mt < 2; mt++) {
            int r0 = brow + wm * 32 + mt * 16 + ar;
            float v00 = cf[mt][nt][0] + b0, v01 = cf[mt][nt][1] + b1;
            float v10 = cf[mt][nt][2] + b0, v11 = cf[mt][nt][3] + b1;
            size_t o0 = (size_t)r0 * N + col;
            size_t o1 = (size_t)(r0 + 8) * N + col;
            if (epi == EPI_RES) {
                float2 q0 = *(const float2*)(resid + o0);
                float2 q1 = *(const float2*)(resid + o1);
                v00 += q0.x; v01 += q0.y; v10 += q1.x; v11 += q1.y;
            } else if (epi == EPI_GELU) {
                v00 = rtf32(0.5f * v00 * (1.0f + erff(v00 * 0.70710678118654752f)));
                v01 = rtf32(0.5f * v01 * (1.0f + erff(v01 * 0.70710678118654752f)));
                v10 = rtf32(0.5f * v10 * (1.0f + erff(v10 * 0.70710678118654752f)));
                v11 = rtf32(0.5f * v11 * (1.0f + erff(v11 * 0.70710678118654752f)));
            } else if (epi == EPI_BIAS_R) {
                v00 = rtf32(v00); v01 = rtf32(v01); v10 = rtf32(v10); v11 = rtf32(v11);
            }
            *(float2*)(C + o0) = make_float2(v00, v01);
            *(float2*)(C + o1) = make_float2(v10, v11);
        }
    }
}

// ---------------- flash attention, 128-q tiles, single-buffer K/V, occ 2 -----
#define ASTR 68     // Q/K/P row stride (floats)
#define VSTR 72     // V row stride
#define OFF_Q  0                           // 128*68
#define OFF_K  (128 * ASTR)                // 64*68 (single buffer)
#define OFF_V  (OFF_K + 64 * ASTR)         // 64*72 (single buffer)
#define OFF_P  (OFF_V + 64 * VSTR)         // 128*68
#define OFF_RM (OFF_P + 128 * ASTR)        // redM[2][128]
#define OFF_RS (OFF_RM + 256)              // redS[2][128]
#define ATTN_SMEM ((OFF_RS + 256) * 4)     // 107520 B -> 2 CTAs/SM

__global__ __launch_bounds__(256, 2)
void attn_tc(const float* __restrict__ QKV, float* __restrict__ O) {
    extern __shared__ float sm[];
    int tid = threadIdx.x;
    int lane = tid & 31, w = tid >> 5;
    int wm = w & 3, wn = w >> 2;
    int ar = lane >> 2, ac = lane & 3;

    int bh = blockIdx.y;
    int b = bh >> 3, h = bh & 7;
    int qbase = blockIdx.x * 128;
    const float* Qg = QKV + (size_t)(b * NS + qbase) * QLD + h * NHD;
    const float* Kg = QKV + (size_t)b * NS * QLD + 512 + h * NHD;
    const float* Vg = QKV + (size_t)b * NS * QLD + 1024 + h * NHD;

    uint32_t sbase = smem_u32(sm);
    int trow = tid >> 2;            // 0..63
    int tseg = (tid & 3) * 16;      // 16-float segment

    // Q (128 rows) + K0 + V0
    {
#pragma unroll
        for (int rr = 0; rr < 2; rr++) {
            int r = trow + rr * 64;
            const float* qp = Qg + (size_t)r * QLD + tseg;
            uint32_t qd = sbase + (uint32_t)(OFF_Q + r * ASTR + tseg) * 4;
#pragma unroll
            for (int i = 0; i < 4; i++) cp_async16(qd + i * 16, qp + i * 4);
        }
        const float* kp = Kg + (size_t)trow * QLD + tseg;
        const float* vp = Vg + (size_t)trow * QLD + tseg;
        uint32_t kd = sbase + (uint32_t)(OFF_K + trow * ASTR + tseg) * 4;
        uint32_t vd = sbase + (uint32_t)(OFF_V + trow * VSTR + tseg) * 4;
#pragma unroll
        for (int i = 0; i < 4; i++) {
            cp_async16(kd + i * 16, kp + i * 4);
            cp_async16(vd + i * 16, vp + i * 4);
        }
    }
    cp_commit();

    float of[2][4][4];
#pragma unroll
    for (int mt = 0; mt < 2; mt++)
#pragma unroll
        for (int nt = 0; nt < 4; nt++)
#pragma unroll
            for (int u = 0; u < 4; u++) of[mt][nt][u] = 0.f;
    float mm[2][2], ll[2][2];
#pragma unroll
    for (int mt = 0; mt < 2; mt++) { mm[mt][0] = mm[mt][1] = -1e30f; ll[mt][0] = ll[mt][1] = 0.f; }

    int rb[2];
    rb[0] = wm * 32 + ar;
    rb[1] = wm * 32 + 16 + ar;
    float* Ps = sm + OFF_P;
    float* redM = sm + OFF_RM;
    float* redS = sm + OFF_RS;

    for (int ct = 0; ct < NS / 64; ct++) {
        cp_wait<0>();
        __syncthreads();   // K/V (and first-iter Q) visible to all warps

        const float* Qs = sm + OFF_Q;
        const float* Ks = sm + OFF_K;
        const float* Vs = sm + OFF_V;

        // S = Q K^T
        float sf[2][4][4];
#pragma unroll
        for (int mt = 0; mt < 2; mt++)
#pragma unroll
            for (int nt = 0; nt < 4; nt++)
#pragma unroll
                for (int u = 0; u < 4; u++) sf[mt][nt][u] = 0.f;
#pragma unroll
        for (int ks = 0; ks < 8; ks++) {
            int kc = ks * 8 + ac;
            uint32_t af[2][4], bf[4][2];
#pragma unroll
            for (int mt = 0; mt < 2; mt++) {
                af[mt][0] = f2u(Qs[rb[mt] * ASTR + kc]);
                af[mt][1] = f2u(Qs[(rb[mt] + 8) * ASTR + kc]);
                af[mt][2] = f2u(Qs[rb[mt] * ASTR + kc + 4]);
                af[mt][3] = f2u(Qs[(rb[mt] + 8) * ASTR + kc + 4]);
            }
#pragma unroll
            for (int nt = 0; nt < 4; nt++) {
                int cc = wn * 32 + nt * 8 + ar;
                bf[nt][0] = f2u(Ks[cc * ASTR + kc]);
                bf[nt][1] = f2u(Ks[cc * ASTR + kc + 4]);
            }
#pragma unroll
            for (int mt = 0; mt < 2; mt++)
#pragma unroll
                for (int nt = 0; nt < 4; nt++) mma8(sf[mt][nt], af[mt], bf[nt]);
        }

        // scale + row max
#pragma unroll
        for (int mt = 0; mt < 2; mt++) {
            float mx0 = -1e30f, mx1 = -1e30f;
#pragma unroll
            for (int nt = 0; nt < 4; nt++) {
#pragma unroll
                for (int u = 0; u < 4; u++) sf[mt][nt][u] *= 0.125f;
                mx0 = fmaxf(mx0, fmaxf(sf[mt][nt][0], sf[mt][nt][1]));
                mx1 = fmaxf(mx1, fmaxf(sf[mt][nt][2], sf[mt][nt][3]));
            }
            mx0 = fmaxf(mx0, __shfl_xor_sync(0xFFFFFFFFu, mx0, 1));
            mx0 = fmaxf(mx0, __shfl_xor_sync(0xFFFFFFFFu, mx0, 2));
            mx1 = fmaxf(mx1, __shfl_xor_sync(0xFFFFFFFFu, mx1, 1));
            mx1 = fmaxf(mx1, __shfl_xor_sync(0xFFFFFFFFu, mx1, 2));
            if (ac == 0) {
                redM[wn * 128 + rb[mt]] = mx0;
                redM[wn * 128 + rb[mt] + 8] = mx1;
            }
        }
        __syncthreads();

        float cr[2][2];
#pragma unroll
        for (int mt = 0; mt < 2; mt++) {
            float mn0 = fmaxf(mm[mt][0], fmaxf(redM[rb[mt]], redM[128 + rb[mt]]));
            float mn1 = fmaxf(mm[mt][1], fmaxf(redM[rb[mt] + 8], redM[128 + rb[mt] + 8]));
            cr[mt][0] = __expf(mm[mt][0] - mn0);
            cr[mt][1] = __expf(mm[mt][1] - mn1);
            mm[mt][0] = mn0; mm[mt][1] = mn1;
#pragma unroll
            for (int nt = 0; nt < 4; nt++) {
                of[mt][nt][0] *= cr[mt][0]; of[mt][nt][1] *= cr[mt][0];
                of[mt][nt][2] *= cr[mt][1]; of[mt][nt][3] *= cr[mt][1];
            }
        }

        // exp + P store + row sum
#pragma unroll
        for (int mt = 0; mt < 2; mt++) {
            float s0 = 0.f, s1 = 0.f;
#pragma unroll
            for (int nt = 0; nt < 4; nt++) {
                float p00 = __expf(sf[mt][nt][0] - mm[mt][0]);
                float p01 = __expf(sf[mt][nt][1] - mm[mt][0]);
                float p10 = __expf(sf[mt][nt][2] - mm[mt][1]);
                float p11 = __expf(sf[mt][nt][3] - mm[mt][1]);
                s0 += p00 + p01; s1 += p10 + p11;
                int cc = wn * 32 + nt * 8 + 2 * ac;
                *(float2*)&Ps[rb[mt] * ASTR + cc] = make_float2(rtf32(p00), rtf32(p01));
                *(float2*)&Ps[(rb[mt] + 8) * ASTR + cc] = make_float2(rtf32(p10), rtf32(p11));
            }
            s0 += __shfl_xor_sync(0xFFFFFFFFu, s0, 1);
            s0 += __shfl_xor_sync(0xFFFFFFFFu, s0, 2);
            s1 += __shfl_xor_sync(0xFFFFFFFFu, s1, 1);
            s1 += __shfl_xor_sync(0xFFFFFFFFu, s1, 2);
            if (ac == 0) {
                redS[wn * 128 + rb[mt]] = s0;
                redS[wn * 128 + rb[mt] + 8] = s1;
            }
        }
        __syncthreads();    // P + redS visible
#pragma unroll
        for (int mt = 0; mt < 2; mt++) {
            ll[mt][0] = ll[mt][0] * cr[mt][0] + redS[rb[mt]] + redS[128 + rb[mt]];
            ll[mt][1] = ll[mt][1] * cr[mt][1] + redS[rb[mt] + 8] + redS[128 + rb[mt] + 8];
        }

        // O += P V
#pragma unroll
        for (int ks = 0; ks < 8; ks++) {
            int kc = ks * 8 + ac;
            uint32_t af[2][4], bf[4][2];
#pragma unroll
            for (int mt = 0; mt < 2; mt++) {
                af[mt][0] = f2u(Ps[rb[mt] * ASTR + kc]);
                af[mt][1] = f2u(Ps[(rb[mt] + 8) * ASTR + kc]);
                af[mt][2] = f2u(Ps[rb[mt] * ASTR + kc + 4]);
                af[mt][3] = f2u(Ps[(rb[mt] + 8) * ASTR + kc + 4]);
            }
#pragma unroll
            for (int nt = 0; nt < 4; nt++) {
                int cc = wn * 32 + nt * 8 + ar;
                bf[nt][0] = f2u(Vs[(kc) * VSTR + cc]);
                bf[nt][1] = f2u(Vs[(kc + 4) * VSTR + cc]);
            }
#pragma unroll
            for (int mt = 0; mt < 2; mt++)
#pragma unroll
                for (int nt = 0; nt < 4; nt++) mma8(of[mt][nt], af[mt], bf[nt]);
        }

        // all warps done reading K/V -> safe to overwrite single buffer
        __syncthreads();
        if (ct + 1 < NS / 64) {
            const float* kn = Kg + (size_t)((ct + 1) * 64 + trow) * QLD + tseg;
            const float* vn = Vg + (size_t)((ct + 1) * 64 + trow) * QLD + tseg;
            uint32_t kd = sbase + (uint32_t)(OFF_K + trow * ASTR + tseg) * 4;
            uint32_t vd = sbase + (uint32_t)(OFF_V + trow * VSTR + tseg) * 4;
#pragma unroll
            for (int i = 0; i < 4; i++) {
                cp_async16(kd + i * 16, kn + i * 4);
                cp_async16(vd + i * 16, vn + i * 4);
            }
            cp_commit();
        }
    }

#pragma unroll
    for (int mt = 0; mt < 2; mt++) {
        float i0 = 1.0f / ll[mt][0], i1 = 1.0f / ll[mt][1];
#pragma unroll
        for (int nt = 0; nt < 4; nt++) {
            int col = h * NHD + wn * 32 + nt * 8 + 2 * ac;
            size_t o0 = (size_t)(b * NS + qbase + rb[mt]) * ND + col;
            size_t o1 = (size_t)(b * NS + qbase + rb[mt] + 8) * ND + col;
            *(float2*)(O + o0) = make_float2(rtf32(of[mt][nt][0] * i0), rtf32(of[mt][nt][1] * i0));
            *(float2*)(O + o1) = make_float2(rtf32(of[mt][nt][2] * i1), rtf32(of[mt][nt][3] * i1));
        }
    }
}

// ---------------- layernorm --------------------------------------------------
__global__ __launch_bounds__(128)
void layernorm_kernel(const float* __restrict__ X, const float* __restrict__ g,
                      const float* __restrict__ beta, float* __restrict__ Y,
                      float* __restrict__ Yr) {
    __shared__ float ssum[4], ssq[4];
    int row = blockIdx.x;
    int t = threadIdx.x;
    float4 v = ((const float4*)(X + (size_t)row * ND))[t];
    float s = v.x + v.y + v.z + v.w;
    float q = v.x * v.x + v.y * v.y + v.z * v.z + v.w * v.w;
#pragma unroll
    for (int off = 16; off > 0; off >>= 1) {
        s += __shfl_xor_sync(0xFFFFFFFFu, s, off);
        q += __shfl_xor_sync(0xFFFFFFFFu, q, off);
    }
    int w = t >> 5;
    if ((t & 31) == 0) { ssum[w] = s; ssq[w] = q; }
    __syncthreads();
    s = ssum[0] + ssum[1] + ssum[2] + ssum[3];
    q = ssq[0] + ssq[1] + ssq[2] + ssq[3];
    float mu = s * (1.0f / 512.0f);
    float var = q * (1.0f / 512.0f) - mu * mu;
    float rstd = rsqrtf(var + 1e-12f);
    float4 gv = ((const float4*)g)[t];
    float4 bv = ((const float4*)beta)[t];
    float4 y;
    y.x = (v.x - mu) * rstd * gv.x + bv.x;
    y.y = (v.y - mu) * rstd * gv.y + bv.y;
    y.z = (v.z - mu) * rstd * gv.z + bv.z;
    y.w = (v.w - mu) * rstd * gv.w + bv.w;
    ((float4*)(Y + (size_t)row * ND))[t] = y;
    if (Yr) {
        float4 yr = make_float4(rtf32(y.x), rtf32(y.y), rtf32(y.z), rtf32(y.w));
        ((float4*)(Yr + (size_t)row * ND))[t] = yr;
    }
}

// ---------------- launch -----------------------------------------------------
extern "C" void kernel_launch(void* const* d_in, const int* in_sizes, int n_in,
                              void* d_out, int out_size) {
    const float* x    = (const float*)d_in[0];
    const float* Wq   = (const float*)d_in[1];
    const float* bq   = (const float*)d_in[2];
    const float* Wk   = (const float*)d_in[3];
    const float* bk   = (const float*)d_in[4];
    const float* Wv   = (const float*)d_in[5];
    const float* bv   = (const float*)d_in[6];
    const float* Wo   = (const float*)d_in[7];
    const float* bo   = (const float*)d_in[8];
    const float* W1   = (const float*)d_in[9];
    const float* b1   = (const float*)d_in[10];
    const float* W2   = (const float*)d_in[11];
    const float* b2   = (const float*)d_in[12];
    const float* ln1g = (const float*)d_in[13];
    const float* ln1b = (const float*)d_in[14];
    const float* ln2g = (const float*)d_in[15];
    const float* ln2b = (const float*)d_in[16];

    float *wqkvt, *bqkv, *wot, *w1t, *w2t, *xr, *qkv, *attnb, *res1, *x1, *x1r, *hb, *res2;
    cudaGetSymbolAddress((void**)&wqkvt, g_wqkvt);
    cudaGetSymbolAddress((void**)&bqkv,  g_bqkv);
    cudaGetSymbolAddress((void**)&wot,   g_wot);
    cudaGetSymbolAddress((void**)&w1t,   g_w1t);
    cudaGetSymbolAddress((void**)&w2t,   g_w2t);
    cudaGetSymbolAddress((void**)&xr,    g_xr);
    cudaGetSymbolAddress((void**)&qkv,   g_qkv);
    cudaGetSymbolAddress((void**)&attnb, g_attn);
    cudaGetSymbolAddress((void**)&res1,  g_res1);
    cudaGetSymbolAddress((void**)&x1,    g_x1);
    cudaGetSymbolAddress((void**)&x1r,   g_x1r);
    cudaGetSymbolAddress((void**)&hb,    g_h);
    cudaGetSymbolAddress((void**)&res2,  g_res2);

    cudaFuncSetAttribute(gemm_tc, cudaFuncAttributeMaxDynamicSharedMemorySize, GEMM_SMEM);
    cudaFuncSetAttribute(attn_tc, cudaFuncAttributeMaxDynamicSharedMemorySize, ATTN_SMEM);

    // prep
    pack_qkvw_kernel<<<(1536 * 512) / 256, 256>>>(Wq, Wk, Wv, wqkvt);
    pack_qkvb_kernel<<<6, 256>>>(bq, bk, bv, bqkv);
    transpose_round_kernel<<<(512 * 512) / 256, 256>>>(Wo, wot, 512, 512);
    transpose_round_kernel<<<(2048 * 512) / 256, 256>>>(W1, w1t, 512, 2048);
    transpose_round_kernel<<<(512 * 2048) / 256, 256>>>(W2, w2t, 2048, 512);
    round4_kernel<<<(NROW * ND / 4) / 256, 256>>>(x, xr);

    // QKV fused projection
    gemm_tc<<<dim3(12, 64), 256, GEMM_SMEM>>>(xr, wqkvt, bqkv, nullptr, qkv, 1536, 512, EPI_BIAS_R);

    // flash attention (tensor cores, 128-query tiles)
    attn_tc<<<dim3(NS / 128, NB * NH), 256, ATTN_SMEM>>>(qkv, attnb);

    // Wo + residual(x); LN1
    gemm_tc<<<dim3(4, 64), 256, GEMM_SMEM>>>(attnb, wot, bo, x, res1, 512, 512, EPI_RES);
    layernorm_kernel<<<NROW, 128>>>(res1, ln1g, ln1b, x1, x1r);

    // FFN
    gemm_tc<<<dim3(16, 64), 256, GEMM_SMEM>>>(x1r, w1t, b1, nullptr, hb, 2048, 512, EPI_GELU);
    gemm_tc<<<dim3(4, 64), 256, GEMM_SMEM>>>(hb, w2t, b2, x1, res2, 512, 2048, EPI_RES);

    // LN2 -> out
    layernorm_kernel<<<NROW, 128>>>(res2, ln2g, ln2b, (float*)d_out, nullptr);
}

// round 9
// speedup vs baseline: 5.7304x; 1.8533x over previous
#include <cuda_runtime.h>
#include <cuda_fp16.h>
#include <math.h>
#include <cstdint>

// Problem dims
#define NB 4
#define NS 2048
#define ND 512
#define NH 8
#define NHD 64
#define NF 2048
#define NROW (NB * NS)   // 8192
#define QLD 1536         // fused qkv row stride (halves)

// ---------------- scratch ----------------------------------------------------
__device__ __half g_wqkvth[1536 * 512];
__device__ float  g_bqkv[1536];
__device__ __half g_woth[512 * 512];
__device__ __half g_w1th[2048 * 512];
__device__ __half g_w2th[512 * 2048];
__device__ __half g_xh[NROW * ND];
__device__ __half g_qkvh[NROW * 1536];
__device__ __half g_attnh[NROW * ND];
__device__ float  g_res1[NROW * ND];
__device__ float  g_x1[NROW * ND];
__device__ __half g_x1h[NROW * ND];
__device__ __half g_hh[NROW * NF];
__device__ float  g_res2[NROW * ND];

// ---------------- helpers ----------------------------------------------------
__device__ __forceinline__ uint32_t smem_u32(const void* p) {
    uint32_t a;
    asm("{ .reg .u64 t; cvta.to.shared.u64 t, %1; cvt.u32.u64 %0, t; }" : "=r"(a) : "l"(p));
    return a;
}
__device__ __forceinline__ void cp_async16(uint32_t sa, const void* ga) {
    asm volatile("cp.async.cg.shared.global [%0], [%1], 16;" :: "r"(sa), "l"(ga) : "memory");
}
__device__ __forceinline__ void cp_commit() { asm volatile("cp.async.commit_group;" ::: "memory"); }
template <int N> __device__ __forceinline__ void cp_wait() {
    asm volatile("cp.async.wait_group %0;" :: "n"(N) : "memory");
}
// D += A*B  (m16n8k16 fp16 in, fp32 accum)
__device__ __forceinline__ void mma16(float* c, const uint32_t* a, const uint32_t* b) {
    asm volatile("mma.sync.aligned.m16n8k16.row.col.f32.f16.f16.f32 "
                 "{%0,%1,%2,%3}, {%4,%5,%6,%7}, {%8,%9}, {%0,%1,%2,%3};"
                 : "+f"(c[0]), "+f"(c[1]), "+f"(c[2]), "+f"(c[3])
                 : "r"(a[0]), "r"(a[1]), "r"(a[2]), "r"(a[3]), "r"(b[0]), "r"(b[1]));
}
__device__ __forceinline__ uint32_t ldh2(const __half* p) { return *(const uint32_t*)p; }
__device__ __forceinline__ uint32_t pkh(__half lo, __half hi) {
    __half2 t = __halves2half2(lo, hi);
    return *(uint32_t*)&t;
}
__device__ __forceinline__ uint32_t f22u(float a, float b) {
    __half2 t = __floats2half2_rn(a, b);
    return *(uint32_t*)&t;
}

// ---------------- prep kernels -----------------------------------------------
__global__ void pack_qkvw_kernel(const float* __restrict__ Wq, const float* __restrict__ Wk,
                                 const float* __restrict__ Wv, __half* __restrict__ out) {
    int idx = blockIdx.x * 256 + threadIdx.x;     // 1536*512
    int k = idx & 511;
    int n = idx >> 9;
    int sel = n >> 9;
    int h = (n >> 6) & 7;
    int e = n & 63;
    const float* W = sel == 0 ? Wq : (sel == 1 ? Wk : Wv);
    out[idx] = __float2half_rn(W[h * (512 * 64) + k * 64 + e]);
}
__global__ void pack_qkvb_kernel(const float* __restrict__ bq, const float* __restrict__ bk,
                                 const float* __restrict__ bv, float* __restrict__ out) {
    int n = blockIdx.x * 256 + threadIdx.x;
    if (n >= 1536) return;
    int sel = n >> 9, r = n & 511;
    const float* b = sel == 0 ? bq : (sel == 1 ? bk : bv);
    out[n] = b[r];
}
// out[n*K + k] = half(in[k*N + n])   in: [K, N] fp32
__global__ void transpose_half_kernel(const float* __restrict__ in, __half* __restrict__ out, int K, int N) {
    int idx = blockIdx.x * 256 + threadIdx.x;
    int k = idx % K;
    int n = idx / K;
    out[idx] = __float2half_rn(in[(size_t)k * N + n]);
}
__global__ void cvt_half_kernel(const float* __restrict__ in, __half* __restrict__ out) {
    int i = blockIdx.x * 256 + threadIdx.x;   // per 4 floats
    float4 v = ((const float4*)in)[i];
    uint2 u;
    u.x = f22u(v.x, v.y);
    u.y = f22u(v.z, v.w);
    ((uint2*)out)[i] = u;
}

// ---------------- fp16 mma.sync GEMM (4-stage, occ 2) -------------------------
// C[8192, N] = A[8192,K] * Bt[N,K]^T + bias (+epi). Tiles 128x128x32, 8 warps.
#define SH 40                          // smem row stride (halves)
#define HSTAGE (128 * SH)              // halves per tile = 5120
#define GEMM_SMEM (4 * 2 * HSTAGE * 2) // 81920 B -> 2 CTAs/SM

#define EPI_BIAS_H 0   // bias, half out
#define EPI_RES    1   // bias + residual(f32), f32 out
#define EPI_GELU   2   // bias + gelu, half out

__global__ __launch_bounds__(256, 2)
void gemm_tc(const __half* __restrict__ A, const __half* __restrict__ Bt,
             const float* __restrict__ bias, const float* __restrict__ resid,
             float* __restrict__ Cf, __half* __restrict__ Ch, int N, int K, int epi) {
    extern __shared__ __half smh[];
    int tid = threadIdx.x;
    int lane = tid & 31, w = tid >> 5;
    int wm = w & 3, wn = w >> 2;        // 4 m-warps x 2 n-warps
    int ar = lane >> 2, ac = lane & 3;
    int brow = blockIdx.y * 128, bcol = blockIdx.x * 128;

    int lrow = tid >> 1, lh = (tid & 1) * 16;   // 16-half segment
    const __half* Ap = A + (size_t)(brow + lrow) * K + lh;
    const __half* Bp = Bt + (size_t)(bcol + lrow) * K + lh;
    uint32_t sbase = smem_u32(smh);
    uint32_t dstoff = (uint32_t)(lrow * SH + lh) * 2;
    int KT = K / 32;

#define GFETCH(kt_) do { \
        uint32_t ab_ = sbase + ((kt_) & 3) * (2 * HSTAGE * 2); \
        uint32_t bb_ = ab_ + HSTAGE * 2; \
        const __half* ap_ = Ap + (kt_) * 32; \
        const __half* bp_ = Bp + (kt_) * 32; \
        cp_async16(ab_ + dstoff,      ap_); \
        cp_async16(ab_ + dstoff + 16, ap_ + 8); \
        cp_async16(bb_ + dstoff,      bp_); \
        cp_async16(bb_ + dstoff + 16, bp_ + 8); \
        cp_commit(); \
    } while (0)

    GFETCH(0); GFETCH(1); GFETCH(2);

    float cf[2][8][4];
#pragma unroll
    for (int mt = 0; mt < 2; mt++)
#pragma unroll
        for (int nt = 0; nt < 8; nt++)
#pragma unroll
            for (int u = 0; u < 4; u++) cf[mt][nt][u] = 0.f;

    for (int kt = 0; kt < KT; kt++) {
        int pend = KT - kt;
        if (pend >= 3) cp_wait<2>();
        else if (pend == 2) cp_wait<1>();
        else cp_wait<0>();
        __syncthreads();

        const __half* As = smh + (kt & 3) * 2 * HSTAGE;
        const __half* Bs = As + HSTAGE;
#pragma unroll
        for (int ks = 0; ks < 2; ks++) {
            int kc = ks * 16 + ac * 2;
            uint32_t af[2][4], bf[8][2];
#pragma unroll
            for (int mt = 0; mt < 2; mt++) {
                int r = wm * 32 + mt * 16 + ar;
                af[mt][0] = ldh2(&As[r * SH + kc]);
                af[mt][1] = ldh2(&As[(r + 8) * SH + kc]);
                af[mt][2] = ldh2(&As[r * SH + kc + 8]);
                af[mt][3] = ldh2(&As[(r + 8) * SH + kc + 8]);
            }
#pragma unroll
            for (int nt = 0; nt < 8; nt++) {
                int cc = wn * 64 + nt * 8 + ar;
                bf[nt][0] = ldh2(&Bs[cc * SH + kc]);
                bf[nt][1] = ldh2(&Bs[cc * SH + kc + 8]);
            }
#pragma unroll
            for (int mt = 0; mt < 2; mt++)
#pragma unroll
                for (int nt = 0; nt < 8; nt++)
                    mma16(cf[mt][nt], af[mt], bf[nt]);
        }
        if (kt + 3 < KT) GFETCH(kt + 3);
    }

    // epilogue
#pragma unroll
    for (int nt = 0; nt < 8; nt++) {
        int col = bcol + wn * 64 + nt * 8 + 2 * ac;
        float b0 = bias[col], b1 = bias[col + 1];
#pragma unroll
        for (int mt = 0; mt < 2; mt++) {
            int r0 = brow + wm * 32 + mt * 16 + ar;
            float v00 = cf[mt][nt][0] + b0, v01 = cf[mt][nt][1] + b1;
            float v10 = cf[mt][nt][2] + b0, v11 = cf[mt][nt][3] + b1;
            size_t o0 = (size_t)r0 * N + col;
            size_t o1 = (size_t)(r0 + 8) * N + col;
            if (epi == EPI_RES) {
                float2 q0 = *(const float2*)(resid + o0);
                float2 q1 = *(const float2*)(resid + o1);
                v00 += q0.x; v01 += q0.y; v10 += q1.x; v11 += q1.y;
                *(float2*)(Cf + o0) = make_float2(v00, v01);
                *(float2*)(Cf + o1) = make_float2(v10, v11);
            } else {
                if (epi == EPI_GELU) {
                    v00 = 0.5f * v00 * (1.0f + erff(v00 * 0.70710678118654752f));
                    v01 = 0.5f * v01 * (1.0f + erff(v01 * 0.70710678118654752f));
                    v10 = 0.5f * v10 * (1.0f + erff(v10 * 0.70710678118654752f));
                    v11 = 0.5f * v11 * (1.0f + erff(v11 * 0.70710678118654752f));
                }
                *(uint32_t*)(Ch + o0) = f22u(v00, v01);
                *(uint32_t*)(Ch + o1) = f22u(v10, v11);
            }
        }
    }
}

// ---------------- flash attention fp16, 128-q tiles, double-buffer, occ 2 ----
#define AH 72                                 // row stride (halves)
#define OFF_Q  0                              // 128*72
#define OFF_K  (128 * AH)                     // 2 buf x 64*72
#define OFF_V  (OFF_K + 2 * 64 * AH)          // 2 buf x 64*72
#define OFF_P  (OFF_V + 2 * 64 * AH)          // 128*72
#define HTOT   (OFF_P + 128 * AH)             // 36864 halves = 73728 B
#define ATTN_SMEM (HTOT * 2 + 2048)           // + redM/redS (2x256 floats) = 75776 B

__global__ __launch_bounds__(256, 2)
void attn_tc(const __half* __restrict__ QKV, __half* __restrict__ O) {
    extern __shared__ __half smh[];
    float* redM = (float*)(smh + HTOT);
    float* redS = redM + 256;
    int tid = threadIdx.x;
    int lane = tid & 31, w = tid >> 5;
    int wm = w & 3, wn = w >> 2;
    int ar = lane >> 2, ac = lane & 3;

    int bh = blockIdx.y;
    int b = bh >> 3, h = bh & 7;
    int qbase = blockIdx.x * 128;
    const __half* Qg = QKV + (size_t)(b * NS + qbase) * QLD + h * NHD;
    const __half* Kg = QKV + (size_t)b * NS * QLD + 512 + h * NHD;
    const __half* Vg = QKV + (size_t)b * NS * QLD + 1024 + h * NHD;

    uint32_t sbase = smem_u32(smh);
    int trow = tid >> 2;            // 0..63
    int tseg = (tid & 3) * 16;      // 16-half segment

    // Q (128 rows) + K0 + V0
    {
#pragma unroll
        for (int rr = 0; rr < 2; rr++) {
            int r = trow + rr * 64;
            const __half* qp = Qg + (size_t)r * QLD + tseg;
            uint32_t qd = sbase + (uint32_t)(OFF_Q + r * AH + tseg) * 2;
            cp_async16(qd, qp);
            cp_async16(qd + 16, qp + 8);
        }
        const __half* kp = Kg + (size_t)trow * QLD + tseg;
        const __half* vp = Vg + (size_t)trow * QLD + tseg;
        uint32_t kd = sbase + (uint32_t)(OFF_K + trow * AH + tseg) * 2;
        uint32_t vd = sbase + (uint32_t)(OFF_V + trow * AH + tseg) * 2;
        cp_async16(kd, kp); cp_async16(kd + 16, kp + 8);
        cp_async16(vd, vp); cp_async16(vd + 16, vp + 8);
    }
    cp_commit();

    float of[2][4][4];
#pragma unroll
    for (int mt = 0; mt < 2; mt++)
#pragma unroll
        for (int nt = 0; nt < 4; nt++)
#pragma unroll
            for (int u = 0; u < 4; u++) of[mt][nt][u] = 0.f;
    float mm[2][2], ll[2][2];
#pragma unroll
    for (int mt = 0; mt < 2; mt++) { mm[mt][0] = mm[mt][1] = -1e30f; ll[mt][0] = ll[mt][1] = 0.f; }

    int rb[2];
    rb[0] = wm * 32 + ar;
    rb[1] = wm * 32 + 16 + ar;
    __half* Ps = smh + OFF_P;

    for (int ct = 0; ct < NS / 64; ct++) {
        cp_wait<0>();
        __syncthreads();
        if (ct + 1 < NS / 64) {
            int nb = (ct + 1) & 1;
            const __half* kn = Kg + (size_t)((ct + 1) * 64 + trow) * QLD + tseg;
            const __half* vn = Vg + (size_t)((ct + 1) * 64 + trow) * QLD + tseg;
            uint32_t kd = sbase + (uint32_t)(OFF_K + nb * 64 * AH + trow * AH + tseg) * 2;
            uint32_t vd = sbase + (uint32_t)(OFF_V + nb * 64 * AH + trow * AH + tseg) * 2;
            cp_async16(kd, kn); cp_async16(kd + 16, kn + 8);
            cp_async16(vd, vn); cp_async16(vd + 16, vn + 8);
            cp_commit();
        }

        const __half* Qs = smh + OFF_Q;
        const __half* Ks = smh + OFF_K + (ct & 1) * 64 * AH;
        const __half* Vs = smh + OFF_V + (ct & 1) * 64 * AH;

        // S = Q K^T  (k = 64 feats, 4 ks iters of k16)
        float sf[2][4][4];
#pragma unroll
        for (int mt = 0; mt < 2; mt++)
#pragma unroll
            for (int nt = 0; nt < 4; nt++)
#pragma unroll
                for (int u = 0; u < 4; u++) sf[mt][nt][u] = 0.f;
#pragma unroll
        for (int ks = 0; ks < 4; ks++) {
            int kc = ks * 16 + ac * 2;
            uint32_t af[2][4], bf[4][2];
#pragma unroll
            for (int mt = 0; mt < 2; mt++) {
                af[mt][0] = ldh2(&Qs[rb[mt] * AH + kc]);
                af[mt][1] = ldh2(&Qs[(rb[mt] + 8) * AH + kc]);
                af[mt][2] = ldh2(&Qs[rb[mt] * AH + kc + 8]);
                af[mt][3] = ldh2(&Qs[(rb[mt] + 8) * AH + kc + 8]);
            }
#pragma unroll
            for (int nt = 0; nt < 4; nt++) {
                int cc = wn * 32 + nt * 8 + ar;
                bf[nt][0] = ldh2(&Ks[cc * AH + kc]);
                bf[nt][1] = ldh2(&Ks[cc * AH + kc + 8]);
            }
#pragma unroll
            for (int mt = 0; mt < 2; mt++)
#pragma unroll
                for (int nt = 0; nt < 4; nt++) mma16(sf[mt][nt], af[mt], bf[nt]);
        }

        // scale + row max
#pragma unroll
        for (int mt = 0; mt < 2; mt++) {
            float mx0 = -1e30f, mx1 = -1e30f;
#pragma unroll
            for (int nt = 0; nt < 4; nt++) {
#pragma unroll
                for (int u = 0; u < 4; u++) sf[mt][nt][u] *= 0.125f;
                mx0 = fmaxf(mx0, fmaxf(sf[mt][nt][0], sf[mt][nt][1]));
                mx1 = fmaxf(mx1, fmaxf(sf[mt][nt][2], sf[mt][nt][3]));
            }
            mx0 = fmaxf(mx0, __shfl_xor_sync(0xFFFFFFFFu, mx0, 1));
            mx0 = fmaxf(mx0, __shfl_xor_sync(0xFFFFFFFFu, mx0, 2));
            mx1 = fmaxf(mx1, __shfl_xor_sync(0xFFFFFFFFu, mx1, 1));
            mx1 = fmaxf(mx1, __shfl_xor_sync(0xFFFFFFFFu, mx1, 2));
            if (ac == 0) {
                redM[wn * 128 + rb[mt]] = mx0;
                redM[wn * 128 + rb[mt] + 8] = mx1;
            }
        }
        __syncthreads();

        float cr[2][2];
#pragma unroll
        for (int mt = 0; mt < 2; mt++) {
            float mn0 = fmaxf(mm[mt][0], fmaxf(redM[rb[mt]], redM[128 + rb[mt]]));
            float mn1 = fmaxf(mm[mt][1], fmaxf(redM[rb[mt] + 8], redM[128 + rb[mt] + 8]));
            cr[mt][0] = __expf(mm[mt][0] - mn0);
            cr[mt][1] = __expf(mm[mt][1] - mn1);
            mm[mt][0] = mn0; mm[mt][1] = mn1;
#pragma unroll
            for (int nt = 0; nt < 4; nt++) {
                of[mt][nt][0] *= cr[mt][0]; of[mt][nt][1] *= cr[mt][0];
                of[mt][nt][2] *= cr[mt][1]; of[mt][nt][3] *= cr[mt][1];
            }
        }

        // exp + P store (half) + row sum
#pragma unroll
        for (int mt = 0; mt < 2; mt++) {
            float s0 = 0.f, s1 = 0.f;
#pragma unroll
            for (int nt = 0; nt < 4; nt++) {
                float p00 = __expf(sf[mt][nt][0] - mm[mt][0]);
                float p01 = __expf(sf[mt][nt][1] - mm[mt][0]);
                float p10 = __expf(sf[mt][nt][2] - mm[mt][1]);
                float p11 = __expf(sf[mt][nt][3] - mm[mt][1]);
                s0 += p00 + p01; s1 += p10 + p11;
                int cc = wn * 32 + nt * 8 + 2 * ac;
                *(uint32_t*)&Ps[rb[mt] * AH + cc] = f22u(p00, p01);
                *(uint32_t*)&Ps[(rb[mt] + 8) * AH + cc] = f22u(p10, p11);
            }
            s0 += __shfl_xor_sync(0xFFFFFFFFu, s0, 1);
            s0 += __shfl_xor_sync(0xFFFFFFFFu, s0, 2);
            s1 += __shfl_xor_sync(0xFFFFFFFFu, s1, 1);
            s1 += __shfl_xor_sync(0xFFFFFFFFu, s1, 2);
            if (ac == 0) {
                redS[wn * 128 + rb[mt]] = s0;
                redS[wn * 128 + rb[mt] + 8] = s1;
            }
        }
        __syncthreads();    // P + redS visible
#pragma unroll
        for (int mt = 0; mt < 2; mt++) {
            ll[mt][0] = ll[mt][0] * cr[mt][0] + redS[rb[mt]] + redS[128 + rb[mt]];
            ll[mt][1] = ll[mt][1] * cr[mt][1] + redS[rb[mt] + 8] + redS[128 + rb[mt] + 8];
        }

        // O += P V   (A = P rows (pairs along key, contiguous); B = V[key][feat],
        //             k-pairs strided -> pack from 2x u16 loads)
#pragma unroll
        for (int ks = 0; ks < 4; ks++) {
            int kc = ks * 16 + ac * 2;
            uint32_t af[2][4], bf[4][2];
#pragma unroll
            for (int mt = 0; mt < 2; mt++) {
                af[mt][0] = ldh2(&Ps[rb[mt] * AH + kc]);
                af[mt][1] = ldh2(&Ps[(rb[mt] + 8) * AH + kc]);
                af[mt][2] = ldh2(&Ps[rb[mt] * AH + kc + 8]);
                af[mt][3] = ldh2(&Ps[(rb[mt] + 8) * AH + kc + 8]);
            }
#pragma unroll
            for (int nt = 0; nt < 4; nt++) {
                int cc = wn * 32 + nt * 8 + ar;
                bf[nt][0] = pkh(Vs[kc * AH + cc],       Vs[(kc + 1) * AH + cc]);
                bf[nt][1] = pkh(Vs[(kc + 8) * AH + cc], Vs[(kc + 9) * AH + cc]);
            }
#pragma unroll
            for (int mt = 0; mt < 2; mt++)
#pragma unroll
                for (int nt = 0; nt < 4; nt++) mma16(of[mt][nt], af[mt], bf[nt]);
        }
    }

#pragma unroll
    for (int mt = 0; mt < 2; mt++) {
        float i0 = 1.0f / ll[mt][0], i1 = 1.0f / ll[mt][1];
#pragma unroll
        for (int nt = 0; nt < 4; nt++) {
            int col = h * NHD + wn * 32 + nt * 8 + 2 * ac;
            size_t o0 = (size_t)(b * NS + qbase + rb[mt]) * ND + col;
            size_t o1 = (size_t)(b * NS + qbase + rb[mt] + 8) * ND + col;
            *(uint32_t*)(O + o0) = f22u(of[mt][nt][0] * i0, of[mt][nt][1] * i0);
            *(uint32_t*)(O + o1) = f22u(of[mt][nt][2] * i1, of[mt][nt][3] * i1);
        }
    }
}

// ---------------- layernorm --------------------------------------------------
__global__ __launch_bounds__(128)
void layernorm_kernel(const float* __restrict__ X, const float* __restrict__ g,
                      const float* __restrict__ beta, float* __restrict__ Y,
                      __half* __restrict__ Yh) {
    __shared__ float ssum[4], ssq[4];
    int row = blockIdx.x;
    int t = threadIdx.x;
    float4 v = ((const float4*)(X + (size_t)row * ND))[t];
    float s = v.x + v.y + v.z + v.w;
    float q = v.x * v.x + v.y * v.y + v.z * v.z + v.w * v.w;
#pragma unroll
    for (int off = 16; off > 0; off >>= 1) {
        s += __shfl_xor_sync(0xFFFFFFFFu, s, off);
        q += __shfl_xor_sync(0xFFFFFFFFu, q, off);
    }
    int w = t >> 5;
    if ((t & 31) == 0) { ssum[w] = s; ssq[w] = q; }
    __syncthreads();
    s = ssum[0] + ssum[1] + ssum[2] + ssum[3];
    q = ssq[0] + ssq[1] + ssq[2] + ssq[3];
    float mu = s * (1.0f / 512.0f);
    float var = q * (1.0f / 512.0f) - mu * mu;
    float rstd = rsqrtf(var + 1e-12f);
    float4 gv = ((const float4*)g)[t];
    float4 bv = ((const float4*)beta)[t];
    float4 y;
    y.x = (v.x - mu) * rstd * gv.x + bv.x;
    y.y = (v.y - mu) * rstd * gv.y + bv.y;
    y.z = (v.z - mu) * rstd * gv.z + bv.z;
    y.w = (v.w - mu) * rstd * gv.w + bv.w;
    ((float4*)(Y + (size_t)row * ND))[t] = y;
    if (Yh) {
        uint2 u;
        u.x = f22u(y.x, y.y);
        u.y = f22u(y.z, y.w);
        ((uint2*)(Yh + (size_t)row * ND))[t] = u;
    }
}

// ---------------- launch -----------------------------------------------------
extern "C" void kernel_launch(void* const* d_in, const int* in_sizes, int n_in,
                              void* d_out, int out_size) {
    const float* x    = (const float*)d_in[0];
    const float* Wq   = (const float*)d_in[1];
    const float* bq   = (const float*)d_in[2];
    const float* Wk   = (const float*)d_in[3];
    const float* bk   = (const float*)d_in[4];
    const float* Wv   = (const float*)d_in[5];
    const float* bv   = (const float*)d_in[6];
    const float* Wo   = (const float*)d_in[7];
    const float* bo   = (const float*)d_in[8];
    const float* W1   = (const float*)d_in[9];
    const float* b1   = (const float*)d_in[10];
    const float* W2   = (const float*)d_in[11];
    const float* b2   = (const float*)d_in[12];
    const float* ln1g = (const float*)d_in[13];
    const float* ln1b = (const float*)d_in[14];
    const float* ln2g = (const float*)d_in[15];
    const float* ln2b = (const float*)d_in[16];

    __half *wqkvth, *woth, *w1th, *w2th, *xh, *qkvh, *attnh, *x1h, *hh;
    float *bqkv, *res1, *x1, *res2;
    cudaGetSymbolAddress((void**)&wqkvth, g_wqkvth);
    cudaGetSymbolAddress((void**)&bqkv,   g_bqkv);
    cudaGetSymbolAddress((void**)&woth,   g_woth);
    cudaGetSymbolAddress((void**)&w1th,   g_w1th);
    cudaGetSymbolAddress((void**)&w2th,   g_w2th);
    cudaGetSymbolAddress((void**)&xh,     g_xh);
    cudaGetSymbolAddress((void**)&qkvh,   g_qkvh);
    cudaGetSymbolAddress((void**)&attnh,  g_attnh);
    cudaGetSymbolAddress((void**)&res1,   g_res1);
    cudaGetSymbolAddress((void**)&x1,     g_x1);
    cudaGetSymbolAddress((void**)&x1h,    g_x1h);
    cudaGetSymbolAddress((void**)&hh,     g_hh);
    cudaGetSymbolAddress((void**)&res2,   g_res2);

    cudaFuncSetAttribute(gemm_tc, cudaFuncAttributeMaxDynamicSharedMemorySize, GEMM_SMEM);
    cudaFuncSetAttribute(attn_tc, cudaFuncAttributeMaxDynamicSharedMemorySize, ATTN_SMEM);

    // prep: weights -> half [n][k], x -> half
    pack_qkvw_kernel<<<(1536 * 512) / 256, 256>>>(Wq, Wk, Wv, wqkvth);
    pack_qkvb_kernel<<<6, 256>>>(bq, bk, bv, bqkv);
    transpose_half_kernel<<<(512 * 512) / 256, 256>>>(Wo, woth, 512, 512);
    transpose_half_kernel<<<(2048 * 512) / 256, 256>>>(W1, w1th, 512, 2048);
    transpose_half_kernel<<<(512 * 2048) / 256, 256>>>(W2, w2th, 2048, 512);
    cvt_half_kernel<<<(NROW * ND / 4) / 256, 256>>>(x, xh);

    // QKV fused projection (half out)
    gemm_tc<<<dim3(12, 64), 256, GEMM_SMEM>>>(xh, wqkvth, bqkv, nullptr, nullptr, qkvh, 1536, 512, EPI_BIAS_H);

    // flash attention (fp16 tensor cores, 128-query tiles, double-buffered)
    attn_tc<<<dim3(NS / 128, NB * NH), 256, ATTN_SMEM>>>(qkvh, attnh);

    // Wo + residual(x) -> f32; LN1 -> x1 (f32) + x1h (half)
    gemm_tc<<<dim3(4, 64), 256, GEMM_SMEM>>>(attnh, woth, bo, x, res1, nullptr, 512, 512, EPI_RES);
    layernorm_kernel<<<NROW, 128>>>(res1, ln1g, ln1b, x1, x1h);

    // FFN
    gemm_tc<<<dim3(16, 64), 256, GEMM_SMEM>>>(x1h, w1th, b1, nullptr, nullptr, hh, 2048, 512, EPI_GELU);
    gemm_tc<<<dim3(4, 64), 256, GEMM_SMEM>>>(hh, w2th, b2, x1, res2, nullptr, 512, 2048, EPI_RES);

    // LN2 -> out
    layernorm_kernel<<<NROW, 128>>>(res2, ln2g, ln2b, (float*)d_out, nullptr);
}

// round 10
// speedup vs baseline: 6.5598x; 1.1447x over previous
#include <cuda_runtime.h>
#include <cuda_fp16.h>
#include <math.h>
#include <cstdint>

// Problem dims
#define NB 4
#define NS 2048
#define ND 512
#define NH 8
#define NHD 64
#define NF 2048
#define NROW (NB * NS)   // 8192
#define QLD 1536         // fused qkv row stride (halves)

// ---------------- scratch ----------------------------------------------------
__device__ __half g_wqkvth[1536 * 512];
__device__ float  g_bqkv[1536];
__device__ __half g_woth[512 * 512];
__device__ __half g_w1th[2048 * 512];
__device__ __half g_w2th[512 * 2048];
__device__ __half g_xh[NROW * ND];
__device__ __half g_qkvh[NROW * 1536];
__device__ __half g_attnh[NROW * ND];
__device__ float  g_res1[NROW * ND];
__device__ float  g_x1[NROW * ND];
__device__ __half g_x1h[NROW * ND];
__device__ __half g_hh[NROW * NF];
__device__ float  g_res2[NROW * ND];

// ---------------- helpers ----------------------------------------------------
__device__ __forceinline__ uint32_t smem_u32(const void* p) {
    uint32_t a;
    asm("{ .reg .u64 t; cvta.to.shared.u64 t, %1; cvt.u32.u64 %0, t; }" : "=r"(a) : "l"(p));
    return a;
}
__device__ __forceinline__ void cp_async16(uint32_t sa, const void* ga) {
    asm volatile("cp.async.cg.shared.global [%0], [%1], 16;" :: "r"(sa), "l"(ga) : "memory");
}
__device__ __forceinline__ void cp_commit() { asm volatile("cp.async.commit_group;" ::: "memory"); }
template <int N> __device__ __forceinline__ void cp_wait() {
    asm volatile("cp.async.wait_group %0;" :: "n"(N) : "memory");
}
// D += A*B  (m16n8k16 fp16 in, fp32 accum)
__device__ __forceinline__ void mma16(float* c, const uint32_t* a, const uint32_t* b) {
    asm volatile("mma.sync.aligned.m16n8k16.row.col.f32.f16.f16.f32 "
                 "{%0,%1,%2,%3}, {%4,%5,%6,%7}, {%8,%9}, {%0,%1,%2,%3};"
                 : "+f"(c[0]), "+f"(c[1]), "+f"(c[2]), "+f"(c[3])
                 : "r"(a[0]), "r"(a[1]), "r"(a[2]), "r"(a[3]), "r"(b[0]), "r"(b[1]));
}
__device__ __forceinline__ void ldsm4(uint32_t* r, uint32_t addr) {
    asm volatile("ldmatrix.sync.aligned.m8n8.x4.shared.b16 {%0,%1,%2,%3}, [%4];"
                 : "=r"(r[0]), "=r"(r[1]), "=r"(r[2]), "=r"(r[3]) : "r"(addr));
}
__device__ __forceinline__ void ldsm4t(uint32_t* r, uint32_t addr) {
    asm volatile("ldmatrix.sync.aligned.m8n8.x4.trans.shared.b16 {%0,%1,%2,%3}, [%4];"
                 : "=r"(r[0]), "=r"(r[1]), "=r"(r[2]), "=r"(r[3]) : "r"(addr));
}
__device__ __forceinline__ uint32_t f22u(float a, float b) {
    __half2 t = __floats2half2_rn(a, b);
    return *(uint32_t*)&t;
}

// ---------------- prep kernels (coalesced smem-tiled transposes) -------------
// QKV pack: per (sel,h) slice, transpose W[h] [512,64] -> out rows sel*512+h*64+e
__global__ void pack_qkvw_t(const float* __restrict__ Wq, const float* __restrict__ Wk,
                            const float* __restrict__ Wv, __half* __restrict__ out) {
    __shared__ float tile[32][33];
    int slice = blockIdx.z;          // sel*8 + h
    int sel = slice >> 3, h = slice & 7;
    const float* W = sel == 0 ? Wq : (sel == 1 ? Wk : Wv);
    const float* in = W + (size_t)h * (512 * 64);   // [512][64]
    int k0 = blockIdx.x * 32, e0 = blockIdx.y * 32;
    int tx = threadIdx.x & 31, ty = threadIdx.x >> 5;
#pragma unroll
    for (int i = 0; i < 4; i++)
        tile[ty + i * 8][tx] = in[(size_t)(k0 + ty + i * 8) * 64 + e0 + tx];
    __syncthreads();
    size_t nb = (size_t)sel * 512 + h * 64 + e0;
#pragma unroll
    for (int i = 0; i < 4; i++)
        out[(nb + ty + i * 8) * 512 + k0 + tx] = __float2half_rn(tile[tx][ty + i * 8]);
}
__global__ void pack_qkvb_kernel(const float* __restrict__ bq, const float* __restrict__ bk,
                                 const float* __restrict__ bv, float* __restrict__ out) {
    int n = blockIdx.x * 256 + threadIdx.x;
    if (n >= 1536) return;
    int sel = n >> 9, r = n & 511;
    const float* b = sel == 0 ? bq : (sel == 1 ? bk : bv);
    out[n] = b[r];
}
// in [K][N] f32 -> out [N][K] half, 32x32 smem tiles
__global__ void transpose_half_t(const float* __restrict__ in, __half* __restrict__ out, int K, int N) {
    __shared__ float tile[32][33];
    int n0 = blockIdx.x * 32, k0 = blockIdx.y * 32;
    int tx = threadIdx.x & 31, ty = threadIdx.x >> 5;
#pragma unroll
    for (int i = 0; i < 4; i++)
        tile[ty + i * 8][tx] = in[(size_t)(k0 + ty + i * 8) * N + n0 + tx];
    __syncthreads();
#pragma unroll
    for (int i = 0; i < 4; i++)
        out[(size_t)(n0 + ty + i * 8) * K + k0 + tx] = __float2half_rn(tile[tx][ty + i * 8]);
}
__global__ void cvt_half_kernel(const float* __restrict__ in, __half* __restrict__ out) {
    int i = blockIdx.x * 256 + threadIdx.x;   // per 4 floats
    float4 v = ((const float4*)in)[i];
    uint2 u;
    u.x = f22u(v.x, v.y);
    u.y = f22u(v.z, v.w);
    ((uint2*)out)[i] = u;
}

// ---------------- fp16 mma.sync GEMM (4-stage, occ 2, ldmatrix) ---------------
// C[8192, N] = A[8192,K] * Bt[N,K]^T + bias (+epi). Tiles 128x128x32, 8 warps.
#define SH 40                          // smem row stride (halves)
#define HSTAGE (128 * SH)              // halves per tile = 5120
#define GEMM_SMEM (4 * 2 * HSTAGE * 2) // 81920 B -> 2 CTAs/SM

#define EPI_BIAS_H 0   // bias, half out
#define EPI_RES    1   // bias + residual(f32), f32 out
#define EPI_GELU   2   // bias + gelu, half out

__global__ __launch_bounds__(256, 2)
void gemm_tc(const __half* __restrict__ A, const __half* __restrict__ Bt,
             const float* __restrict__ bias, const float* __restrict__ resid,
             float* __restrict__ Cf, __half* __restrict__ Ch, int N, int K, int epi) {
    extern __shared__ __half smh[];
    int tid = threadIdx.x;
    int lane = tid & 31, w = tid >> 5;
    int wm = w & 3, wn = w >> 2;        // 4 m-warps x 2 n-warps
    int ar = lane >> 2, ac = lane & 3;
    int quad = lane >> 3, wi = lane & 7;
    int brow = blockIdx.y * 128, bcol = blockIdx.x * 128;

    int lrow = tid >> 1, lh = (tid & 1) * 16;   // 16-half segment
    const __half* Ap = A + (size_t)(brow + lrow) * K + lh;
    const __half* Bp = Bt + (size_t)(bcol + lrow) * K + lh;
    uint32_t sbase = smem_u32(smh);
    uint32_t dstoff = (uint32_t)(lrow * SH + lh) * 2;
    int KT = K / 32;

    // ldmatrix per-lane half-offsets (A-style and B-style)
    uint32_t aoff = (uint32_t)((wm * 32 + wi + (quad & 1) * 8) * SH + (quad >> 1) * 8);
    uint32_t boff = (uint32_t)((wn * 64 + wi + (quad >> 1) * 8) * SH + (quad & 1) * 8);

#define GFETCH(kt_) do { \
        uint32_t ab_ = sbase + ((kt_) & 3) * (2 * HSTAGE * 2); \
        uint32_t bb_ = ab_ + HSTAGE * 2; \
        const __half* ap_ = Ap + (kt_) * 32; \
        const __half* bp_ = Bp + (kt_) * 32; \
        cp_async16(ab_ + dstoff,      ap_); \
        cp_async16(ab_ + dstoff + 16, ap_ + 8); \
        cp_async16(bb_ + dstoff,      bp_); \
        cp_async16(bb_ + dstoff + 16, bp_ + 8); \
        cp_commit(); \
    } while (0)

    GFETCH(0); GFETCH(1); GFETCH(2);

    float cf[2][8][4];
#pragma unroll
    for (int mt = 0; mt < 2; mt++)
#pragma unroll
        for (int nt = 0; nt < 8; nt++)
#pragma unroll
            for (int u = 0; u < 4; u++) cf[mt][nt][u] = 0.f;

    for (int kt = 0; kt < KT; kt++) {
        int pend = KT - kt;
        if (pend >= 3) cp_wait<2>();
        else if (pend == 2) cp_wait<1>();
        else cp_wait<0>();
        __syncthreads();

        uint32_t abase = sbase + (kt & 3) * (2 * HSTAGE * 2);
        uint32_t bbase = abase + HSTAGE * 2;
#pragma unroll
        for (int ks = 0; ks < 2; ks++) {
            uint32_t af[2][4], bf[8][2];
#pragma unroll
            for (int mt = 0; mt < 2; mt++)
                ldsm4(af[mt], abase + (aoff + mt * 16 * SH + ks * 16) * 2);
#pragma unroll
            for (int i = 0; i < 4; i++) {
                uint32_t r[4];
                ldsm4(r, bbase + (boff + i * 16 * SH + ks * 16) * 2);
                bf[2 * i][0] = r[0]; bf[2 * i][1] = r[1];
                bf[2 * i + 1][0] = r[2]; bf[2 * i + 1][1] = r[3];
            }
#pragma unroll
            for (int mt = 0; mt < 2; mt++)
#pragma unroll
                for (int nt = 0; nt < 8; nt++)
                    mma16(cf[mt][nt], af[mt], bf[nt]);
        }
        if (kt + 3 < KT) GFETCH(kt + 3);
    }

    // epilogue
#pragma unroll
    for (int nt = 0; nt < 8; nt++) {
        int col = bcol + wn * 64 + nt * 8 + 2 * ac;
        float b0 = bias[col], b1 = bias[col + 1];
#pragma unroll
        for (int mt = 0; mt < 2; mt++) {
            int r0 = brow + wm * 32 + mt * 16 + ar;
            float v00 = cf[mt][nt][0] + b0, v01 = cf[mt][nt][1] + b1;
            float v10 = cf[mt][nt][2] + b0, v11 = cf[mt][nt][3] + b1;
            size_t o0 = (size_t)r0 * N + col;
            size_t o1 = (size_t)(r0 + 8) * N + col;
            if (epi == EPI_RES) {
                float2 q0 = *(const float2*)(resid + o0);
                float2 q1 = *(const float2*)(resid + o1);
                v00 += q0.x; v01 += q0.y; v10 += q1.x; v11 += q1.y;
                *(float2*)(Cf + o0) = make_float2(v00, v01);
                *(float2*)(Cf + o1) = make_float2(v10, v11);
            } else {
                if (epi == EPI_GELU) {
                    v00 = 0.5f * v00 * (1.0f + erff(v00 * 0.70710678118654752f));
                    v01 = 0.5f * v01 * (1.0f + erff(v01 * 0.70710678118654752f));
                    v10 = 0.5f * v10 * (1.0f + erff(v10 * 0.70710678118654752f));
                    v11 = 0.5f * v11 * (1.0f + erff(v11 * 0.70710678118654752f));
                }
                *(uint32_t*)(Ch + o0) = f22u(v00, v01);
                *(uint32_t*)(Ch + o1) = f22u(v10, v11);
            }
        }
    }
}

// ---------------- flash attention fp16, 128-q tiles, double-buffer, occ 2 ----
#define AH 72                                 // row stride (halves)
#define OFF_Q  0                              // 128*72
#define OFF_K  (128 * AH)                     // 2 buf x 64*72
#define OFF_V  (OFF_K + 2 * 64 * AH)          // 2 buf x 64*72
#define OFF_P  (OFF_V + 2 * 64 * AH)          // 128*72
#define HTOT   (OFF_P + 128 * AH)             // 36864 halves = 73728 B
#define ATTN_SMEM (HTOT * 2 + 2048)           // + redM/redS = 75776 B

__global__ __launch_bounds__(256, 2)
void attn_tc(const __half* __restrict__ QKV, __half* __restrict__ O) {
    extern __shared__ __half smh[];
    float* redM = (float*)(smh + HTOT);
    float* redS = redM + 256;
    int tid = threadIdx.x;
    int lane = tid & 31, w = tid >> 5;
    int wm = w & 3, wn = w >> 2;
    int ar = lane >> 2, ac = lane & 3;
    int quad = lane >> 3, wi = lane & 7;

    int bh = blockIdx.y;
    int b = bh >> 3, h = bh & 7;
    int qbase = blockIdx.x * 128;
    const __half* Qg = QKV + (size_t)(b * NS + qbase) * QLD + h * NHD;
    const __half* Kg = QKV + (size_t)b * NS * QLD + 512 + h * NHD;
    const __half* Vg = QKV + (size_t)b * NS * QLD + 1024 + h * NHD;

    uint32_t sbase = smem_u32(smh);
    int trow = tid >> 2;            // 0..63
    int tseg = (tid & 3) * 16;      // 16-half segment

    // ldmatrix per-lane half-offsets
    uint32_t qoff = (uint32_t)((wm * 32 + wi + (quad & 1) * 8) * AH + (quad >> 1) * 8);  // A-style (Q,P)
    uint32_t koff = (uint32_t)((wn * 32 + wi + (quad >> 1) * 8) * AH + (quad & 1) * 8);  // B-style (K)
    uint32_t voff = (uint32_t)((wi + (quad & 1) * 8) * AH + wn * 32 + (quad >> 1) * 8);  // trans (V)

    // Q (128 rows) + K0 + V0
    {
#pragma unroll
        for (int rr = 0; rr < 2; rr++) {
            int r = trow + rr * 64;
            const __half* qp = Qg + (size_t)r * QLD + tseg;
            uint32_t qd = sbase + (uint32_t)(OFF_Q + r * AH + tseg) * 2;
            cp_async16(qd, qp);
            cp_async16(qd + 16, qp + 8);
        }
        const __half* kp = Kg + (size_t)trow * QLD + tseg;
        const __half* vp = Vg + (size_t)trow * QLD + tseg;
        uint32_t kd = sbase + (uint32_t)(OFF_K + trow * AH + tseg) * 2;
        uint32_t vd = sbase + (uint32_t)(OFF_V + trow * AH + tseg) * 2;
        cp_async16(kd, kp); cp_async16(kd + 16, kp + 8);
        cp_async16(vd, vp); cp_async16(vd + 16, vp + 8);
    }
    cp_commit();

    float of[2][4][4];
#pragma unroll
    for (int mt = 0; mt < 2; mt++)
#pragma unroll
        for (int nt = 0; nt < 4; nt++)
#pragma unroll
            for (int u = 0; u < 4; u++) of[mt][nt][u] = 0.f;
    float mm[2][2], ll[2][2];
#pragma unroll
    for (int mt = 0; mt < 2; mt++) { mm[mt][0] = mm[mt][1] = -1e30f; ll[mt][0] = ll[mt][1] = 0.f; }

    int rb[2];
    rb[0] = wm * 32 + ar;
    rb[1] = wm * 32 + 16 + ar;
    __half* Ps = smh + OFF_P;
    uint32_t pbase = sbase + OFF_P * 2;
    uint32_t qsb = sbase + OFF_Q * 2;

    for (int ct = 0; ct < NS / 64; ct++) {
        cp_wait<0>();
        __syncthreads();
        if (ct + 1 < NS / 64) {
            int nb = (ct + 1) & 1;
            const __half* kn = Kg + (size_t)((ct + 1) * 64 + trow) * QLD + tseg;
            const __half* vn = Vg + (size_t)((ct + 1) * 64 + trow) * QLD + tseg;
            uint32_t kd = sbase + (uint32_t)(OFF_K + nb * 64 * AH + trow * AH + tseg) * 2;
            uint32_t vd = sbase + (uint32_t)(OFF_V + nb * 64 * AH + trow * AH + tseg) * 2;
            cp_async16(kd, kn); cp_async16(kd + 16, kn + 8);
            cp_async16(vd, vn); cp_async16(vd + 16, vn + 8);
            cp_commit();
        }

        uint32_t ksb = sbase + (OFF_K + (ct & 1) * 64 * AH) * 2;
        uint32_t vsb = sbase + (OFF_V + (ct & 1) * 64 * AH) * 2;

        // S = Q K^T
        float sf[2][4][4];
#pragma unroll
        for (int mt = 0; mt < 2; mt++)
#pragma unroll
            for (int nt = 0; nt < 4; nt++)
#pragma unroll
                for (int u = 0; u < 4; u++) sf[mt][nt][u] = 0.f;
#pragma unroll
        for (int ks = 0; ks < 4; ks++) {
            uint32_t af[2][4], bf[4][2];
#pragma unroll
            for (int mt = 0; mt < 2; mt++)
                ldsm4(af[mt], qsb + (qoff + mt * 16 * AH + ks * 16) * 2);
#pragma unroll
            for (int i = 0; i < 2; i++) {
                uint32_t r[4];
                ldsm4(r, ksb + (koff + i * 16 * AH + ks * 16) * 2);
                bf[2 * i][0] = r[0]; bf[2 * i][1] = r[1];
                bf[2 * i + 1][0] = r[2]; bf[2 * i + 1][1] = r[3];
            }
#pragma unroll
            for (int mt = 0; mt < 2; mt++)
#pragma unroll
                for (int nt = 0; nt < 4; nt++) mma16(sf[mt][nt], af[mt], bf[nt]);
        }

        // scale + row max
#pragma unroll
        for (int mt = 0; mt < 2; mt++) {
            float mx0 = -1e30f, mx1 = -1e30f;
#pragma unroll
            for (int nt = 0; nt < 4; nt++) {
#pragma unroll
                for (int u = 0; u < 4; u++) sf[mt][nt][u] *= 0.125f;
                mx0 = fmaxf(mx0, fmaxf(sf[mt][nt][0], sf[mt][nt][1]));
                mx1 = fmaxf(mx1, fmaxf(sf[mt][nt][2], sf[mt][nt][3]));
            }
            mx0 = fmaxf(mx0, __shfl_xor_sync(0xFFFFFFFFu, mx0, 1));
            mx0 = fmaxf(mx0, __shfl_xor_sync(0xFFFFFFFFu, mx0, 2));
            mx1 = fmaxf(mx1, __shfl_xor_sync(0xFFFFFFFFu, mx1, 1));
            mx1 = fmaxf(mx1, __shfl_xor_sync(0xFFFFFFFFu, mx1, 2));
            if (ac == 0) {
                redM[wn * 128 + rb[mt]] = mx0;
                redM[wn * 128 + rb[mt] + 8] = mx1;
            }
        }
        __syncthreads();

        float cr[2][2];
#pragma unroll
        for (int mt = 0; mt < 2; mt++) {
            float mn0 = fmaxf(mm[mt][0], fmaxf(redM[rb[mt]], redM[128 + rb[mt]]));
            float mn1 = fmaxf(mm[mt][1], fmaxf(redM[rb[mt] + 8], redM[128 + rb[mt] + 8]));
            cr[mt][0] = __expf(mm[mt][0] - mn0);
            cr[mt][1] = __expf(mm[mt][1] - mn1);
            mm[mt][0] = mn0; mm[mt][1] = mn1;
#pragma unroll
            for (int nt = 0; nt < 4; nt++) {
                of[mt][nt][0] *= cr[mt][0]; of[mt][nt][1] *= cr[mt][0];
                of[mt][nt][2] *= cr[mt][1]; of[mt][nt][3] *= cr[mt][1];
            }
        }

        // exp + P store (half) + row sum
#pragma unroll
        for (int mt = 0; mt < 2; mt++) {
            float s0 = 0.f, s1 = 0.f;
#pragma unroll
            for (int nt = 0; nt < 4; nt++) {
                float p00 = __expf(sf[mt][nt][0] - mm[mt][0]);
                float p01 = __expf(sf[mt][nt][1] - mm[mt][0]);
                float p10 = __expf(sf[mt][nt][2] - mm[mt][1]);
                float p11 = __expf(sf[mt][nt][3] - mm[mt][1]);
                s0 += p00 + p01; s1 += p10 + p11;
                int cc = wn * 32 + nt * 8 + 2 * ac;
                *(uint32_t*)&Ps[rb[mt] * AH + cc] = f22u(p00, p01);
                *(uint32_t*)&Ps[(rb[mt] + 8) * AH + cc] = f22u(p10, p11);
            }
            s0 += __shfl_xor_sync(0xFFFFFFFFu, s0, 1);
            s0 += __shfl_xor_sync(0xFFFFFFFFu, s0, 2);
            s1 += __shfl_xor_sync(0xFFFFFFFFu, s1, 1);
            s1 += __shfl_xor_sync(0xFFFFFFFFu, s1, 2);
            if (ac == 0) {
                redS[wn * 128 + rb[mt]] = s0;
                redS[wn * 128 + rb[mt] + 8] = s1;
            }
        }
        __syncthreads();    // P + redS visible
#pragma unroll
        for (int mt = 0; mt < 2; mt++) {
            ll[mt][0] = ll[mt][0] * cr[mt][0] + redS[rb[mt]] + redS[128 + rb[mt]];
            ll[mt][1] = ll[mt][1] * cr[mt][1] + redS[rb[mt] + 8] + redS[128 + rb[mt] + 8];
        }

        // O += P V   (P via ldmatrix A-style; V via ldmatrix.trans B-style)
#pragma unroll
        for (int ks = 0; ks < 4; ks++) {
            uint32_t af[2][4], bf[4][2];
#pragma unroll
            for (int mt = 0; mt < 2; mt++)
                ldsm4(af[mt], pbase + (qoff + mt * 16 * AH + ks * 16) * 2);
#pragma unroll
            for (int i = 0; i < 2; i++) {
                uint32_t r[4];
                ldsm4t(r, vsb + (voff + ks * 16 * AH + i * 16) * 2);
                bf[2 * i][0] = r[0]; bf[2 * i][1] = r[1];
                bf[2 * i + 1][0] = r[2]; bf[2 * i + 1][1] = r[3];
            }
#pragma unroll
            for (int mt = 0; mt < 2; mt++)
#pragma unroll
                for (int nt = 0; nt < 4; nt++) mma16(of[mt][nt], af[mt], bf[nt]);
        }
    }

#pragma unroll
    for (int mt = 0; mt < 2; mt++) {
        float i0 = 1.0f / ll[mt][0], i1 = 1.0f / ll[mt][1];
#pragma unroll
        for (int nt = 0; nt < 4; nt++) {
            int col = h * NHD + wn * 32 + nt * 8 + 2 * ac;
            size_t o0 = (size_t)(b * NS + qbase + rb[mt]) * ND + col;
            size_t o1 = (size_t)(b * NS + qbase + rb[mt] + 8) * ND + col;
            *(uint32_t*)(O + o0) = f22u(of[mt][nt][0] * i0, of[mt][nt][1] * i0);
            *(uint32_t*)(O + o1) = f22u(of[mt][nt][2] * i1, of[mt][nt][3] * i1);
        }
    }
}

// ---------------- layernorm --------------------------------------------------
__global__ __launch_bounds__(128)
void layernorm_kernel(const float* __restrict__ X, const float* __restrict__ g,
                      const float* __restrict__ beta, float* __restrict__ Y,
                      __half* __restrict__ Yh) {
    __shared__ float ssum[4], ssq[4];
    int row = blockIdx.x;
    int t = threadIdx.x;
    float4 v = ((const float4*)(X + (size_t)row * ND))[t];
    float s = v.x + v.y + v.z + v.w;
    float q = v.x * v.x + v.y * v.y + v.z * v.z + v.w * v.w;
#pragma unroll
    for (int off = 16; off > 0; off >>= 1) {
        s += __shfl_xor_sync(0xFFFFFFFFu, s, off);
        q += __shfl_xor_sync(0xFFFFFFFFu, q, off);
    }
    int w = t >> 5;
    if ((t & 31) == 0) { ssum[w] = s; ssq[w] = q; }
    __syncthreads();
    s = ssum[0] + ssum[1] + ssum[2] + ssum[3];
    q = ssq[0] + ssq[1] + ssq[2] + ssq[3];
    float mu = s * (1.0f / 512.0f);
    float var = q * (1.0f / 512.0f) - mu * mu;
    float rstd = rsqrtf(var + 1e-12f);
    float4 gv = ((const float4*)g)[t];
    float4 bv = ((const float4*)beta)[t];
    float4 y;
    y.x = (v.x - mu) * rstd * gv.x + bv.x;
    y.y = (v.y - mu) * rstd * gv.y + bv.y;
    y.z = (v.z - mu) * rstd * gv.z + bv.z;
    y.w = (v.w - mu) * rstd * gv.w + bv.w;
    ((float4*)(Y + (size_t)row * ND))[t] = y;
    if (Yh) {
        uint2 u;
        u.x = f22u(y.x, y.y);
        u.y = f22u(y.z, y.w);
        ((uint2*)(Yh + (size_t)row * ND))[t] = u;
    }
}

// ---------------- launch -----------------------------------------------------
extern "C" void kernel_launch(void* const* d_in, const int* in_sizes, int n_in,
                              void* d_out, int out_size) {
    const float* x    = (const float*)d_in[0];
    const float* Wq   = (const float*)d_in[1];
    const float* bq   = (const float*)d_in[2];
    const float* Wk   = (const float*)d_in[3];
    const float* bk   = (const float*)d_in[4];
    const float* Wv   = (const float*)d_in[5];
    const float* bv   = (const float*)d_in[6];
    const float* Wo   = (const float*)d_in[7];
    const float* bo   = (const float*)d_in[8];
    const float* W1   = (const float*)d_in[9];
    const float* b1   = (const float*)d_in[10];
    const float* W2   = (const float*)d_in[11];
    const float* b2   = (const float*)d_in[12];
    const float* ln1g = (const float*)d_in[13];
    const float* ln1b = (const float*)d_in[14];
    const float* ln2g = (const float*)d_in[15];
    const float* ln2b = (const float*)d_in[16];

    __half *wqkvth, *woth, *w1th, *w2th, *xh, *qkvh, *attnh, *x1h, *hh;
    float *bqkv, *res1, *x1, *res2;
    cudaGetSymbolAddress((void**)&wqkvth, g_wqkvth);
    cudaGetSymbolAddress((void**)&bqkv,   g_bqkv);
    cudaGetSymbolAddress((void**)&woth,   g_woth);
    cudaGetSymbolAddress((void**)&w1th,   g_w1th);
    cudaGetSymbolAddress((void**)&w2th,   g_w2th);
    cudaGetSymbolAddress((void**)&xh,     g_xh);
    cudaGetSymbolAddress((void**)&qkvh,   g_qkvh);
    cudaGetSymbolAddress((void**)&attnh,  g_attnh);
    cudaGetSymbolAddress((void**)&res1,   g_res1);
    cudaGetSymbolAddress((void**)&x1,     g_x1);
    cudaGetSymbolAddress((void**)&x1h,    g_x1h);
    cudaGetSymbolAddress((void**)&hh,     g_hh);
    cudaGetSymbolAddress((void**)&res2,   g_res2);

    cudaFuncSetAttribute(gemm_tc, cudaFuncAttributeMaxDynamicSharedMemorySize, GEMM_SMEM);
    cudaFuncSetAttribute(attn_tc, cudaFuncAttributeMaxDynamicSharedMemorySize, ATTN_SMEM);

    // prep: coalesced tiled transposes
    pack_qkvw_t<<<dim3(16, 2, 24), 256>>>(Wq, Wk, Wv, wqkvth);
    pack_qkvb_kernel<<<6, 256>>>(bq, bk, bv, bqkv);
    transpose_half_t<<<dim3(16, 16), 256>>>(Wo, woth, 512, 512);
    transpose_half_t<<<dim3(64, 16), 256>>>(W1, w1th, 512, 2048);
    transpose_half_t<<<dim3(16, 64), 256>>>(W2, w2th, 2048, 512);
    cvt_half_kernel<<<(NROW * ND / 4) / 256, 256>>>(x, xh);

    // QKV fused projection (half out)
    gemm_tc<<<dim3(12, 64), 256, GEMM_SMEM>>>(xh, wqkvth, bqkv, nullptr, nullptr, qkvh, 1536, 512, EPI_BIAS_H);

    // flash attention (fp16 tensor cores, 128-query tiles, double-buffered)
    attn_tc<<<dim3(NS / 128, NB * NH), 256, ATTN_SMEM>>>(qkvh, attnh);

    // Wo + residual(x) -> f32; LN1 -> x1 (f32) + x1h (half)
    gemm_tc<<<dim3(4, 64), 256, GEMM_SMEM>>>(attnh, woth, bo, x, res1, nullptr, 512, 512, EPI_RES);
    layernorm_kernel<<<NROW, 128>>>(res1, ln1g, ln1b, x1, x1h);

    // FFN
    gemm_tc<<<dim3(16, 64), 256, GEMM_SMEM>>>(x1h, w1th, b1, nullptr, nullptr, hh, 2048, 512, EPI_GELU);
    gemm_tc<<<dim3(4, 64), 256, GEMM_SMEM>>>(hh, w2th, b2, x1, res2, nullptr, 512, 2048, EPI_RES);

    // LN2 -> out
    layernorm_kernel<<<NROW, 128>>>(res2, ln2g, ln2b, (float*)d_out, nullptr);
}

// round 11
// speedup vs baseline: 7.0364x; 1.0727x over previous
#include <cuda_runtime.h>
#include <cuda_fp16.h>
#include <math.h>
#include <cstdint>

// Problem dims
#define NB 4
#define NS 2048
#define ND 512
#define NH 8
#define NHD 64
#define NF 2048
#define NROW (NB * NS)   // 8192
#define QLD 1536         // fused qkv row stride (halves)

// ---------------- scratch ----------------------------------------------------
__device__ __half g_wqkvth[1536 * 512];
__device__ float  g_bqkv[1536];
__device__ __half g_woth[512 * 512];
__device__ __half g_w1th[2048 * 512];
__device__ __half g_w2th[512 * 2048];
__device__ __half g_xh[NROW * ND];
__device__ __half g_qkvh[NROW * 1536];
__device__ __half g_attnh[NROW * ND];
__device__ float  g_res1[NROW * ND];
__device__ float  g_x1[NROW * ND];
__device__ __half g_x1h[NROW * ND];
__device__ __half g_hh[NROW * NF];
__device__ float  g_res2[NROW * ND];

// ---------------- helpers ----------------------------------------------------
__device__ __forceinline__ uint32_t smem_u32(const void* p) {
    uint32_t a;
    asm("{ .reg .u64 t; cvta.to.shared.u64 t, %1; cvt.u32.u64 %0, t; }" : "=r"(a) : "l"(p));
    return a;
}
__device__ __forceinline__ void cp_async16(uint32_t sa, const void* ga) {
    asm volatile("cp.async.cg.shared.global [%0], [%1], 16;" :: "r"(sa), "l"(ga) : "memory");
}
__device__ __forceinline__ void cp_commit() { asm volatile("cp.async.commit_group;" ::: "memory"); }
template <int N> __device__ __forceinline__ void cp_wait() {
    asm volatile("cp.async.wait_group %0;" :: "n"(N) : "memory");
}
// D += A*B  (m16n8k16 fp16 in, fp32 accum)
__device__ __forceinline__ void mma16(float* c, const uint32_t* a, const uint32_t* b) {
    asm volatile("mma.sync.aligned.m16n8k16.row.col.f32.f16.f16.f32 "
                 "{%0,%1,%2,%3}, {%4,%5,%6,%7}, {%8,%9}, {%0,%1,%2,%3};"
                 : "+f"(c[0]), "+f"(c[1]), "+f"(c[2]), "+f"(c[3])
                 : "r"(a[0]), "r"(a[1]), "r"(a[2]), "r"(a[3]), "r"(b[0]), "r"(b[1]));
}
__device__ __forceinline__ void ldsm4(uint32_t* r, uint32_t addr) {
    asm volatile("ldmatrix.sync.aligned.m8n8.x4.shared.b16 {%0,%1,%2,%3}, [%4];"
                 : "=r"(r[0]), "=r"(r[1]), "=r"(r[2]), "=r"(r[3]) : "r"(addr));
}
__device__ __forceinline__ void ldsm4t(uint32_t* r, uint32_t addr) {
    asm volatile("ldmatrix.sync.aligned.m8n8.x4.trans.shared.b16 {%0,%1,%2,%3}, [%4];"
                 : "=r"(r[0]), "=r"(r[1]), "=r"(r[2]), "=r"(r[3]) : "r"(addr));
}
__device__ __forceinline__ uint32_t f22u(float a, float b) {
    __half2 t = __floats2half2_rn(a, b);
    return *(uint32_t*)&t;
}

// ---------------- prep kernels (coalesced smem-tiled transposes) -------------
__global__ void pack_qkvw_t(const float* __restrict__ Wq, const float* __restrict__ Wk,
                            const float* __restrict__ Wv, __half* __restrict__ out) {
    __shared__ float tile[32][33];
    int slice = blockIdx.z;          // sel*8 + h
    int sel = slice >> 3, h = slice & 7;
    const float* W = sel == 0 ? Wq : (sel == 1 ? Wk : Wv);
    const float* in = W + (size_t)h * (512 * 64);   // [512][64]
    int k0 = blockIdx.x * 32, e0 = blockIdx.y * 32;
    int tx = threadIdx.x & 31, ty = threadIdx.x >> 5;
#pragma unroll
    for (int i = 0; i < 4; i++)
        tile[ty + i * 8][tx] = in[(size_t)(k0 + ty + i * 8) * 64 + e0 + tx];
    __syncthreads();
    size_t nb = (size_t)sel * 512 + h * 64 + e0;
#pragma unroll
    for (int i = 0; i < 4; i++)
        out[(nb + ty + i * 8) * 512 + k0 + tx] = __float2half_rn(tile[tx][ty + i * 8]);
}
__global__ void pack_qkvb_kernel(const float* __restrict__ bq, const float* __restrict__ bk,
                                 const float* __restrict__ bv, float* __restrict__ out) {
    int n = blockIdx.x * 256 + threadIdx.x;
    if (n >= 1536) return;
    int sel = n >> 9, r = n & 511;
    const float* b = sel == 0 ? bq : (sel == 1 ? bk : bv);
    out[n] = b[r];
}
__global__ void transpose_half_t(const float* __restrict__ in, __half* __restrict__ out, int K, int N) {
    __shared__ float tile[32][33];
    int n0 = blockIdx.x * 32, k0 = blockIdx.y * 32;
    int tx = threadIdx.x & 31, ty = threadIdx.x >> 5;
#pragma unroll
    for (int i = 0; i < 4; i++)
        tile[ty + i * 8][tx] = in[(size_t)(k0 + ty + i * 8) * N + n0 + tx];
    __syncthreads();
#pragma unroll
    for (int i = 0; i < 4; i++)
        out[(size_t)(n0 + ty + i * 8) * K + k0 + tx] = __float2half_rn(tile[tx][ty + i * 8]);
}
__global__ void cvt_half_kernel(const float* __restrict__ in, __half* __restrict__ out) {
    int i = blockIdx.x * 256 + threadIdx.x;   // per 4 floats
    float4 v = ((const float4*)in)[i];
    uint2 u;
    u.x = f22u(v.x, v.y);
    u.y = f22u(v.z, v.w);
    ((uint2*)out)[i] = u;
}

// ---------------- fp16 mma.sync GEMM (4-stage, occ 2, ldmatrix) ---------------
#define SH 40                          // smem row stride (halves)
#define HSTAGE (128 * SH)              // halves per tile = 5120
#define GEMM_SMEM (4 * 2 * HSTAGE * 2) // 81920 B -> 2 CTAs/SM

#define EPI_BIAS_H 0   // bias, half out
#define EPI_RES    1   // bias + residual(f32), f32 out
#define EPI_GELU   2   // bias + gelu, half out

__global__ __launch_bounds__(256, 2)
void gemm_tc(const __half* __restrict__ A, const __half* __restrict__ Bt,
             const float* __restrict__ bias, const float* __restrict__ resid,
             float* __restrict__ Cf, __half* __restrict__ Ch, int N, int K, int epi) {
    extern __shared__ __half smh[];
    int tid = threadIdx.x;
    int lane = tid & 31, w = tid >> 5;
    int wm = w & 3, wn = w >> 2;        // 4 m-warps x 2 n-warps
    int ar = lane >> 2, ac = lane & 3;
    int quad = lane >> 3, wi = lane & 7;
    int brow = blockIdx.y * 128, bcol = blockIdx.x * 128;

    int lrow = tid >> 1, lh = (tid & 1) * 16;   // 16-half segment
    const __half* Ap = A + (size_t)(brow + lrow) * K + lh;
    const __half* Bp = Bt + (size_t)(bcol + lrow) * K + lh;
    uint32_t sbase = smem_u32(smh);
    uint32_t dstoff = (uint32_t)(lrow * SH + lh) * 2;
    int KT = K / 32;

    uint32_t aoff = (uint32_t)((wm * 32 + wi + (quad & 1) * 8) * SH + (quad >> 1) * 8);
    uint32_t boff = (uint32_t)((wn * 64 + wi + (quad >> 1) * 8) * SH + (quad & 1) * 8);

#define GFETCH(kt_) do { \
        uint32_t ab_ = sbase + ((kt_) & 3) * (2 * HSTAGE * 2); \
        uint32_t bb_ = ab_ + HSTAGE * 2; \
        const __half* ap_ = Ap + (kt_) * 32; \
        const __half* bp_ = Bp + (kt_) * 32; \
        cp_async16(ab_ + dstoff,      ap_); \
        cp_async16(ab_ + dstoff + 16, ap_ + 8); \
        cp_async16(bb_ + dstoff,      bp_); \
        cp_async16(bb_ + dstoff + 16, bp_ + 8); \
        cp_commit(); \
    } while (0)

    GFETCH(0); GFETCH(1); GFETCH(2);

    float cf[2][8][4];
#pragma unroll
    for (int mt = 0; mt < 2; mt++)
#pragma unroll
        for (int nt = 0; nt < 8; nt++)
#pragma unroll
            for (int u = 0; u < 4; u++) cf[mt][nt][u] = 0.f;

    for (int kt = 0; kt < KT; kt++) {
        int pend = KT - kt;
        if (pend >= 3) cp_wait<2>();
        else if (pend == 2) cp_wait<1>();
        else cp_wait<0>();
        __syncthreads();

        uint32_t abase = sbase + (kt & 3) * (2 * HSTAGE * 2);
        uint32_t bbase = abase + HSTAGE * 2;
#pragma unroll
        for (int ks = 0; ks < 2; ks++) {
            uint32_t af[2][4], bf[8][2];
#pragma unroll
            for (int mt = 0; mt < 2; mt++)
                ldsm4(af[mt], abase + (aoff + mt * 16 * SH + ks * 16) * 2);
#pragma unroll
            for (int i = 0; i < 4; i++) {
                uint32_t r[4];
                ldsm4(r, bbase + (boff + i * 16 * SH + ks * 16) * 2);
                bf[2 * i][0] = r[0]; bf[2 * i][1] = r[1];
                bf[2 * i + 1][0] = r[2]; bf[2 * i + 1][1] = r[3];
            }
#pragma unroll
            for (int mt = 0; mt < 2; mt++)
#pragma unroll
                for (int nt = 0; nt < 8; nt++)
                    mma16(cf[mt][nt], af[mt], bf[nt]);
        }
        if (kt + 3 < KT) GFETCH(kt + 3);
    }

    // epilogue
#pragma unroll
    for (int nt = 0; nt < 8; nt++) {
        int col = bcol + wn * 64 + nt * 8 + 2 * ac;
        float b0 = bias[col], b1 = bias[col + 1];
#pragma unroll
        for (int mt = 0; mt < 2; mt++) {
            int r0 = brow + wm * 32 + mt * 16 + ar;
            float v00 = cf[mt][nt][0] + b0, v01 = cf[mt][nt][1] + b1;
            float v10 = cf[mt][nt][2] + b0, v11 = cf[mt][nt][3] + b1;
            size_t o0 = (size_t)r0 * N + col;
            size_t o1 = (size_t)(r0 + 8) * N + col;
            if (epi == EPI_RES) {
                float2 q0 = *(const float2*)(resid + o0);
                float2 q1 = *(const float2*)(resid + o1);
                v00 += q0.x; v01 += q0.y; v10 += q1.x; v11 += q1.y;
                *(float2*)(Cf + o0) = make_float2(v00, v01);
                *(float2*)(Cf + o1) = make_float2(v10, v11);
            } else {
                if (epi == EPI_GELU) {
                    v00 = 0.5f * v00 * (1.0f + erff(v00 * 0.70710678118654752f));
                    v01 = 0.5f * v01 * (1.0f + erff(v01 * 0.70710678118654752f));
                    v10 = 0.5f * v10 * (1.0f + erff(v10 * 0.70710678118654752f));
                    v11 = 0.5f * v11 * (1.0f + erff(v11 * 0.70710678118654752f));
                }
                *(uint32_t*)(Ch + o0) = f22u(v00, v01);
                *(uint32_t*)(Ch + o1) = f22u(v10, v11);
            }
        }
    }
}

// ---------------- flash attention fp16, FA2 warp layout ----------------------
// 128 q-rows/CTA; each warp owns 16 rows x all 64 keys. In-warp softmax,
// P kept in registers (C-frag == A-frag layout). 1 sync per K-tile.
#define AH 72                                 // row stride (halves)
#define OFF_Q  0                              // 128*72
#define OFF_K  (128 * AH)                     // 2 buf x 64*72
#define OFF_V  (OFF_K + 2 * 64 * AH)          // 2 buf x 64*72
#define HTOT   (OFF_V + 2 * 64 * AH)          // 27648 halves
#define ATTN_SMEM (HTOT * 2)                  // 55296 B

__global__ __launch_bounds__(256, 2)
void attn_tc(const __half* __restrict__ QKV, __half* __restrict__ O) {
    extern __shared__ __half smh[];
    int tid = threadIdx.x;
    int lane = tid & 31, w = tid >> 5;
    int ar = lane >> 2, ac = lane & 3;
    int quad = lane >> 3, wi = lane & 7;

    int bh = blockIdx.y;
    int b = bh >> 3, h = bh & 7;
    int qbase = blockIdx.x * 128;
    const __half* Qg = QKV + (size_t)(b * NS + qbase) * QLD + h * NHD;
    const __half* Kg = QKV + (size_t)b * NS * QLD + 512 + h * NHD;
    const __half* Vg = QKV + (size_t)b * NS * QLD + 1024 + h * NHD;

    uint32_t sbase = smem_u32(smh);
    int trow = tid >> 2;            // 0..63
    int tseg = (tid & 3) * 16;      // 16-half segment

    // ldmatrix per-lane half-offsets
    uint32_t qoff = (uint32_t)((w * 16 + wi + (quad & 1) * 8) * AH + (quad >> 1) * 8);  // A (Q)
    uint32_t koff = (uint32_t)((wi + (quad >> 1) * 8) * AH + (quad & 1) * 8);           // B (K)
    uint32_t voff = (uint32_t)((wi + (quad & 1) * 8) * AH + (quad >> 1) * 8);           // B.trans (V)

    // Q (128 rows) + K0 + V0
    {
#pragma unroll
        for (int rr = 0; rr < 2; rr++) {
            int r = trow + rr * 64;
            const __half* qp = Qg + (size_t)r * QLD + tseg;
            uint32_t qd = sbase + (uint32_t)(OFF_Q + r * AH + tseg) * 2;
            cp_async16(qd, qp);
            cp_async16(qd + 16, qp + 8);
        }
        const __half* kp = Kg + (size_t)trow * QLD + tseg;
        const __half* vp = Vg + (size_t)trow * QLD + tseg;
        uint32_t kd = sbase + (uint32_t)(OFF_K + trow * AH + tseg) * 2;
        uint32_t vd = sbase + (uint32_t)(OFF_V + trow * AH + tseg) * 2;
        cp_async16(kd, kp); cp_async16(kd + 16, kp + 8);
        cp_async16(vd, vp); cp_async16(vd + 16, vp + 8);
    }
    cp_commit();
    cp_wait<0>();
    __syncthreads();

    // preload Q fragments (loop-invariant)
    uint32_t qf[4][4];
    uint32_t qsb = sbase + OFF_Q * 2;
#pragma unroll
    for (int ks = 0; ks < 4; ks++)
        ldsm4(qf[ks], qsb + (qoff + ks * 16) * 2);

    float of[8][4];
#pragma unroll
    for (int nt = 0; nt < 8; nt++)
#pragma unroll
        for (int u = 0; u < 4; u++) of[nt][u] = 0.f;
    float m0 = -1e30f, m1 = -1e30f, l0 = 0.f, l1 = 0.f;

    for (int ct = 0; ct < NS / 64; ct++) {
        if (ct > 0) {
            cp_wait<0>();
            __syncthreads();
        }
        if (ct + 1 < NS / 64) {
            int nb = (ct + 1) & 1;
            const __half* kn = Kg + (size_t)((ct + 1) * 64 + trow) * QLD + tseg;
            const __half* vn = Vg + (size_t)((ct + 1) * 64 + trow) * QLD + tseg;
            uint32_t kd = sbase + (uint32_t)(OFF_K + nb * 64 * AH + trow * AH + tseg) * 2;
            uint32_t vd = sbase + (uint32_t)(OFF_V + nb * 64 * AH + trow * AH + tseg) * 2;
            cp_async16(kd, kn); cp_async16(kd + 16, kn + 8);
            cp_async16(vd, vn); cp_async16(vd + 16, vn + 8);
            cp_commit();
        }

        uint32_t ksb = sbase + (OFF_K + (ct & 1) * 64 * AH) * 2;
        uint32_t vsb = sbase + (OFF_V + (ct & 1) * 64 * AH) * 2;

        // S = Q K^T  (16 rows x 64 keys per warp)
        float sf[8][4];
#pragma unroll
        for (int nt = 0; nt < 8; nt++)
#pragma unroll
            for (int u = 0; u < 4; u++) sf[nt][u] = 0.f;
#pragma unroll
        for (int ks = 0; ks < 4; ks++) {
            uint32_t bf[8][2];
#pragma unroll
            for (int i = 0; i < 4; i++) {
                uint32_t r[4];
                ldsm4(r, ksb + (koff + i * 16 * AH + ks * 16) * 2);
                bf[2 * i][0] = r[0]; bf[2 * i][1] = r[1];
                bf[2 * i + 1][0] = r[2]; bf[2 * i + 1][1] = r[3];
            }
#pragma unroll
            for (int nt = 0; nt < 8; nt++) mma16(sf[nt], qf[ks], bf[nt]);
        }

        // in-warp softmax (rows r0 = w*16+ar, r1 = r0+8)
        float mx0 = -1e30f, mx1 = -1e30f;
#pragma unroll
        for (int nt = 0; nt < 8; nt++) {
#pragma unroll
            for (int u = 0; u < 4; u++) sf[nt][u] *= 0.125f;
            mx0 = fmaxf(mx0, fmaxf(sf[nt][0], sf[nt][1]));
            mx1 = fmaxf(mx1, fmaxf(sf[nt][2], sf[nt][3]));
        }
        mx0 = fmaxf(mx0, __shfl_xor_sync(0xFFFFFFFFu, mx0, 1));
        mx0 = fmaxf(mx0, __shfl_xor_sync(0xFFFFFFFFu, mx0, 2));
        mx1 = fmaxf(mx1, __shfl_xor_sync(0xFFFFFFFFu, mx1, 1));
        mx1 = fmaxf(mx1, __shfl_xor_sync(0xFFFFFFFFu, mx1, 2));
        float mn0 = fmaxf(m0, mx0), mn1 = fmaxf(m1, mx1);
        float cr0 = __expf(m0 - mn0), cr1 = __expf(m1 - mn1);
        m0 = mn0; m1 = mn1;
#pragma unroll
        for (int nt = 0; nt < 8; nt++) {
            of[nt][0] *= cr0; of[nt][1] *= cr0;
            of[nt][2] *= cr1; of[nt][3] *= cr1;
        }

        // exp; pack P straight into A-fragments (C layout == A layout)
        uint32_t pf[4][4];
        float s0 = 0.f, s1 = 0.f;
#pragma unroll
        for (int ks = 0; ks < 4; ks++) {
            float p00 = __expf(sf[2 * ks][0] - mn0),     p01 = __expf(sf[2 * ks][1] - mn0);
            float p10 = __expf(sf[2 * ks][2] - mn1),     p11 = __expf(sf[2 * ks][3] - mn1);
            float p20 = __expf(sf[2 * ks + 1][0] - mn0), p21 = __expf(sf[2 * ks + 1][1] - mn0);
            float p30 = __expf(sf[2 * ks + 1][2] - mn1), p31 = __expf(sf[2 * ks + 1][3] - mn1);
            s0 += p00 + p01 + p20 + p21;
            s1 += p10 + p11 + p30 + p31;
            pf[ks][0] = f22u(p00, p01);   // row ar,   keys [16ks+2ac, +1]
            pf[ks][1] = f22u(p10, p11);   // row ar+8
            pf[ks][2] = f22u(p20, p21);   // row ar,   keys [16ks+8+2ac, +1]
            pf[ks][3] = f22u(p30, p31);   // row ar+8
        }
        s0 += __shfl_xor_sync(0xFFFFFFFFu, s0, 1);
        s0 += __shfl_xor_sync(0xFFFFFFFFu, s0, 2);
        s1 += __shfl_xor_sync(0xFFFFFFFFu, s1, 1);
        s1 += __shfl_xor_sync(0xFFFFFFFFu, s1, 2);
        l0 = l0 * cr0 + s0;
        l1 = l1 * cr1 + s1;

        // O += P V   (V via ldmatrix.trans: k = keys, n = feats)
#pragma unroll
        for (int ks = 0; ks < 4; ks++) {
            uint32_t bf[8][2];
#pragma unroll
            for (int i = 0; i < 4; i++) {
                uint32_t r[4];
                ldsm4t(r, vsb + (voff + ks * 16 * AH + i * 16) * 2);
                bf[2 * i][0] = r[0]; bf[2 * i][1] = r[1];
                bf[2 * i + 1][0] = r[2]; bf[2 * i + 1][1] = r[3];
            }
#pragma unroll
            for (int nt = 0; nt < 8; nt++) mma16(of[nt], pf[ks], bf[nt]);
        }
    }

    float i0 = 1.0f / l0, i1 = 1.0f / l1;
    int r0 = w * 16 + ar;
#pragma unroll
    for (int nt = 0; nt < 8; nt++) {
        int col = h * NHD + nt * 8 + 2 * ac;
        size_t o0 = (size_t)(b * NS + qbase + r0) * ND + col;
        size_t o1 = (size_t)(b * NS + qbase + r0 + 8) * ND + col;
        *(uint32_t*)(O + o0) = f22u(of[nt][0] * i0, of[nt][1] * i0);
        *(uint32_t*)(O + o1) = f22u(of[nt][2] * i1, of[nt][3] * i1);
    }
}

// ---------------- layernorm --------------------------------------------------
__global__ __launch_bounds__(128)
void layernorm_kernel(const float* __restrict__ X, const float* __restrict__ g,
                      const float* __restrict__ beta, float* __restrict__ Y,
                      __half* __restrict__ Yh) {
    __shared__ float ssum[4], ssq[4];
    int row = blockIdx.x;
    int t = threadIdx.x;
    float4 v = ((const float4*)(X + (size_t)row * ND))[t];
    float s = v.x + v.y + v.z + v.w;
    float q = v.x * v.x + v.y * v.y + v.z * v.z + v.w * v.w;
#pragma unroll
    for (int off = 16; off > 0; off >>= 1) {
        s += __shfl_xor_sync(0xFFFFFFFFu, s, off);
        q += __shfl_xor_sync(0xFFFFFFFFu, q, off);
    }
    int w = t >> 5;
    if ((t & 31) == 0) { ssum[w] = s; ssq[w] = q; }
    __syncthreads();
    s = ssum[0] + ssum[1] + ssum[2] + ssum[3];
    q = ssq[0] + ssq[1] + ssq[2] + ssq[3];
    float mu = s * (1.0f / 512.0f);
    float var = q * (1.0f / 512.0f) - mu * mu;
    float rstd = rsqrtf(var + 1e-12f);
    float4 gv = ((const float4*)g)[t];
    float4 bv = ((const float4*)beta)[t];
    float4 y;
    y.x = (v.x - mu) * rstd * gv.x + bv.x;
    y.y = (v.y - mu) * rstd * gv.y + bv.y;
    y.z = (v.z - mu) * rstd * gv.z + bv.z;
    y.w = (v.w - mu) * rstd * gv.w + bv.w;
    ((float4*)(Y + (size_t)row * ND))[t] = y;
    if (Yh) {
        uint2 u;
        u.x = f22u(y.x, y.y);
        u.y = f22u(y.z, y.w);
        ((uint2*)(Yh + (size_t)row * ND))[t] = u;
    }
}

// ---------------- launch -----------------------------------------------------
extern "C" void kernel_launch(void* const* d_in, const int* in_sizes, int n_in,
                              void* d_out, int out_size) {
    const float* x    = (const float*)d_in[0];
    const float* Wq   = (const float*)d_in[1];
    const float* bq   = (const float*)d_in[2];
    const float* Wk   = (const float*)d_in[3];
    const float* bk   = (const float*)d_in[4];
    const float* Wv   = (const float*)d_in[5];
    const float* bv   = (const float*)d_in[6];
    const float* Wo   = (const float*)d_in[7];
    const float* bo   = (const float*)d_in[8];
    const float* W1   = (const float*)d_in[9];
    const float* b1   = (const float*)d_in[10];
    const float* W2   = (const float*)d_in[11];
    const float* b2   = (const float*)d_in[12];
    const float* ln1g = (const float*)d_in[13];
    const float* ln1b = (const float*)d_in[14];
    const float* ln2g = (const float*)d_in[15];
    const float* ln2b = (const float*)d_in[16];

    __half *wqkvth, *woth, *w1th, *w2th, *xh, *qkvh, *attnh, *x1h, *hh;
    float *bqkv, *res1, *x1, *res2;
    cudaGetSymbolAddress((void**)&wqkvth, g_wqkvth);
    cudaGetSymbolAddress((void**)&bqkv,   g_bqkv);
    cudaGetSymbolAddress((void**)&woth,   g_woth);
    cudaGetSymbolAddress((void**)&w1th,   g_w1th);
    cudaGetSymbolAddress((void**)&w2th,   g_w2th);
    cudaGetSymbolAddress((void**)&xh,     g_xh);
    cudaGetSymbolAddress((void**)&qkvh,   g_qkvh);
    cudaGetSymbolAddress((void**)&attnh,  g_attnh);
    cudaGetSymbolAddress((void**)&res1,   g_res1);
    cudaGetSymbolAddress((void**)&x1,     g_x1);
    cudaGetSymbolAddress((void**)&x1h,    g_x1h);
    cudaGetSymbolAddress((void**)&hh,     g_hh);
    cudaGetSymbolAddress((void**)&res2,   g_res2);

    cudaFuncSetAttribute(gemm_tc, cudaFuncAttributeMaxDynamicSharedMemorySize, GEMM_SMEM);
    cudaFuncSetAttribute(attn_tc, cudaFuncAttributeMaxDynamicSharedMemorySize, ATTN_SMEM);

    // prep
    pack_qkvw_t<<<dim3(16, 2, 24), 256>>>(Wq, Wk, Wv, wqkvth);
    pack_qkvb_kernel<<<6, 256>>>(bq, bk, bv, bqkv);
    transpose_half_t<<<dim3(16, 16), 256>>>(Wo, woth, 512, 512);
    transpose_half_t<<<dim3(64, 16), 256>>>(W1, w1th, 512, 2048);
    transpose_half_t<<<dim3(16, 64), 256>>>(W2, w2th, 2048, 512);
    cvt_half_kernel<<<(NROW * ND / 4) / 256, 256>>>(x, xh);

    // QKV fused projection (half out)
    gemm_tc<<<dim3(12, 64), 256, GEMM_SMEM>>>(xh, wqkvth, bqkv, nullptr, nullptr, qkvh, 1536, 512, EPI_BIAS_H);

    // flash attention (FA2 layout)
    attn_tc<<<dim3(NS / 128, NB * NH), 256, ATTN_SMEM>>>(qkvh, attnh);

    // Wo + residual(x) -> f32; LN1 -> x1 (f32) + x1h (half)
    gemm_tc<<<dim3(4, 64), 256, GEMM_SMEM>>>(attnh, woth, bo, x, res1, nullptr, 512, 512, EPI_RES);
    layernorm_kernel<<<NROW, 128>>>(res1, ln1g, ln1b, x1, x1h);

    // FFN
    gemm_tc<<<dim3(16, 64), 256, GEMM_SMEM>>>(x1h, w1th, b1, nullptr, nullptr, hh, 2048, 512, EPI_GELU);
    gemm_tc<<<dim3(4, 64), 256, GEMM_SMEM>>>(hh, w2th, b2, x1, res2, nullptr, 512, 2048, EPI_RES);

    // LN2 -> out
    layernorm_kernel<<<NROW, 128>>>(res2, ln2g, ln2b, (float*)d_out, nullptr);
}